// round 1
// baseline (speedup 1.0000x reference)
#include <cuda_runtime.h>
#include <cuda_bf16.h>
#include <math.h>

#define BB 64
#define NPG 1000
#define INF_DIM 64
#define HD 128
#define CC 10
#define NMAX (BB*NPG)           // 64000
#define EMAX (BB*NPG*16)        // 1024000

// ---------------- scratch (device globals; no allocation) ----------------
__device__ float g_h[NMAX*HD];
__device__ float g_xw[NMAX*HD];
__device__ float g_hc[NMAX*HD];
__device__ float g_deg[NMAX];        // becomes dinv in place
__device__ float g_score[NMAX];
__device__ int   g_src[EMAX];
__device__ int   g_dst[EMAX];
__device__ float g_we[EMAX];
__device__ int   g_indeg[NMAX];
__device__ int   g_cursor[NMAX];
__device__ int   g_inv[NMAX];
__device__ int   g_rowptr[NMAX+1];
__device__ int   g_esrc[EMAX];
__device__ float g_ecoef[EMAX];
__device__ int   g_perm[NMAX];
__device__ float g_vals[NMAX];
__device__ float g_flats[BB*2*HD];
__device__ int   g_partials[64];

// ---------------- kernels ----------------

__global__ void init_kernel(const int* __restrict__ ei, const float* __restrict__ ew,
                            int* __restrict__ src, int* __restrict__ dst, float* __restrict__ we,
                            float* __restrict__ flats, int E)
{
    int i = blockIdx.x * blockDim.x + threadIdx.x;
    if (i < E) { src[i] = ei[i]; dst[i] = ei[E + i]; we[i] = ew[i]; }
    if (i < BB * 2 * HD) flats[i] = 0.f;
}

__global__ void node_init(float* __restrict__ deg, int* __restrict__ indeg,
                          int* __restrict__ cursor, int* __restrict__ inv, int N)
{
    int i = blockIdx.x * blockDim.x + threadIdx.x;
    if (i < N) { deg[i] = 1.0f; indeg[i] = 0; cursor[i] = 0; inv[i] = -1; }
}

__global__ void edge_count(const int* __restrict__ dst, const float* __restrict__ we,
                           float* __restrict__ deg, int* __restrict__ indeg, int E)
{
    int e = blockIdx.x * blockDim.x + threadIdx.x;
    if (e >= E) return;
    float w = we[e];
    if (w > 0.f) {
        int d = dst[e];
        atomicAdd(&deg[d], w);
        atomicAdd(&indeg[d], 1);
    }
}

__global__ void dinv_kernel(float* __restrict__ deg, int N)
{
    int i = blockIdx.x * blockDim.x + threadIdx.x;
    if (i < N) deg[i] = 1.0f / sqrtf(deg[i]);
}

__global__ void scan_local(const int* __restrict__ indeg, int* __restrict__ rowptr,
                           int* __restrict__ partials, int N)
{
    __shared__ int sd[1024];
    int i = blockIdx.x * 1024 + threadIdx.x;
    int v = (i < N) ? indeg[i] : 0;
    sd[threadIdx.x] = v;
    for (int off = 1; off < 1024; off <<= 1) {
        __syncthreads();
        int t = (threadIdx.x >= off) ? sd[threadIdx.x - off] : 0;
        __syncthreads();
        sd[threadIdx.x] += t;
    }
    __syncthreads();
    if (i < N) rowptr[i] = sd[threadIdx.x] - v;            // local exclusive
    if (threadIdx.x == 1023) partials[blockIdx.x] = sd[1023];
}

__global__ void scan_partials(int* __restrict__ partials, int* __restrict__ rowptr, int nch, int N)
{
    __shared__ int sp[64];
    int t = threadIdx.x;
    int v = (t < nch) ? partials[t] : 0;
    sp[t] = v;
    for (int off = 1; off < 64; off <<= 1) {
        __syncthreads();
        int x = (t >= off) ? sp[t - off] : 0;
        __syncthreads();
        sp[t] += x;
    }
    __syncthreads();
    if (t < nch) partials[t] = sp[t] - v;                  // exclusive chunk offsets
    if (t == 63) rowptr[N] = sp[63];                       // total alive edges
}

__global__ void scan_add(int* __restrict__ rowptr, const int* __restrict__ partials, int N)
{
    int i = blockIdx.x * blockDim.x + threadIdx.x;
    if (i < N) rowptr[i] += partials[i >> 10];
}

__global__ void edge_scatter(const int* __restrict__ src, const int* __restrict__ dst,
                             const float* __restrict__ we, const float* __restrict__ dinv,
                             const int* __restrict__ rowptr, int* __restrict__ cursor,
                             int* __restrict__ esrc, float* __restrict__ ecoef, int E)
{
    int e = blockIdx.x * blockDim.x + threadIdx.x;
    if (e >= E) return;
    float w = we[e];
    if (w <= 0.f) return;
    int s = src[e], d = dst[e];
    int pos = rowptr[d] + atomicAdd(&cursor[d], 1);
    esrc[pos] = s;
    ecoef[pos] = dinv[s] * dinv[d] * w;
}

template<int HIN>
__global__ __launch_bounds__(256)
void matmul_kernel(const float* __restrict__ A, const float* __restrict__ W, float* __restrict__ out)
{
    __shared__ float Hs[64][64];
    __shared__ float Ws[64][128];
    int tx = threadIdx.x & 31, ty = threadIdx.x >> 5;
    int rowBase = blockIdx.x * 64;
    float acc[8][4];
#pragma unroll
    for (int r = 0; r < 8; r++) { acc[r][0]=0.f; acc[r][1]=0.f; acc[r][2]=0.f; acc[r][3]=0.f; }

#pragma unroll
    for (int kc = 0; kc < HIN; kc += 64) {
#pragma unroll
        for (int it = 0; it < 4; it++) {                    // 64x64 H tile
            int e = threadIdx.x + it * 256;
            int r = e >> 4, c4 = e & 15;
            float4 v = *(const float4*)(A + (size_t)(rowBase + r) * HIN + kc + c4 * 4);
            *(float4*)&Hs[r][c4 * 4] = v;
        }
#pragma unroll
        for (int it = 0; it < 8; it++) {                    // 64x128 W tile
            int e = threadIdx.x + it * 256;
            int r = e >> 5, c4 = e & 31;
            *(float4*)&Ws[r][c4 * 4] = *(const float4*)(W + (size_t)(kc + r) * 128 + c4 * 4);
        }
        __syncthreads();
#pragma unroll 16
        for (int kk = 0; kk < 64; kk++) {
            float4 wv = *(const float4*)&Ws[kk][tx * 4];
#pragma unroll
            for (int r = 0; r < 8; r++) {
                float hv = Hs[ty + r * 8][kk];
                acc[r][0] = fmaf(hv, wv.x, acc[r][0]);
                acc[r][1] = fmaf(hv, wv.y, acc[r][1]);
                acc[r][2] = fmaf(hv, wv.z, acc[r][2]);
                acc[r][3] = fmaf(hv, wv.w, acc[r][3]);
            }
        }
        __syncthreads();
    }
#pragma unroll
    for (int r = 0; r < 8; r++) {
        int row = rowBase + ty + r * 8;
        *(float4*)(out + (size_t)row * 128 + tx * 4) =
            make_float4(acc[r][0], acc[r][1], acc[r][2], acc[r][3]);
    }
}

__global__ void gcn_gather(const float* __restrict__ xw, const int* __restrict__ rowptr,
                           const int* __restrict__ esrc, const float* __restrict__ ecoef,
                           const float* __restrict__ dinv,
                           const float* __restrict__ bias, const float* __restrict__ bng,
                           const float* __restrict__ bnb, const float* __restrict__ bnm,
                           const float* __restrict__ bnv, const float* __restrict__ pw,
                           float* __restrict__ hc, float* __restrict__ score, int N)
{
    int n = (blockIdx.x * blockDim.x + threadIdx.x) >> 5;
    int l = threadIdx.x & 31;
    if (n >= N) return;
    float di = dinv[n];
    float sc = di * di;
    float4 a = ((const float4*)(xw + (size_t)n * 128))[l];
    float4 acc = make_float4(a.x * sc, a.y * sc, a.z * sc, a.w * sc);
    int e0 = rowptr[n], e1 = rowptr[n + 1];
    for (int e = e0; e < e1; ++e) {
        int s = esrc[e];
        float c = ecoef[e];
        float4 v = ((const float4*)(xw + (size_t)s * 128))[l];
        acc.x = fmaf(c, v.x, acc.x);
        acc.y = fmaf(c, v.y, acc.y);
        acc.z = fmaf(c, v.z, acc.z);
        acc.w = fmaf(c, v.w, acc.w);
    }
    float4 bb = ((const float4*)bias)[l];
    float4 g  = ((const float4*)bng)[l];
    float4 be = ((const float4*)bnb)[l];
    float4 m  = ((const float4*)bnm)[l];
    float4 vv = ((const float4*)bnv)[l];
    float4 o;
    o.x = fmaxf((acc.x + bb.x - m.x) * (g.x / sqrtf(vv.x + 1e-5f)) + be.x, 0.f);
    o.y = fmaxf((acc.y + bb.y - m.y) * (g.y / sqrtf(vv.y + 1e-5f)) + be.y, 0.f);
    o.z = fmaxf((acc.z + bb.z - m.z) * (g.z / sqrtf(vv.z + 1e-5f)) + be.z, 0.f);
    o.w = fmaxf((acc.w + bb.w - m.w) * (g.w / sqrtf(vv.w + 1e-5f)) + be.w, 0.f);
    ((float4*)(hc + (size_t)n * 128))[l] = o;
    float4 p = ((const float4*)pw)[l];
    float dot = o.x * p.x + o.y * p.y + o.z * p.z + o.w * p.w;
    float p2  = p.x * p.x + p.y * p.y + p.z * p.z + p.w * p.w;
#pragma unroll
    for (int off = 16; off; off >>= 1) {
        dot += __shfl_xor_sync(0xffffffffu, dot, off);
        p2  += __shfl_xor_sync(0xffffffffu, p2, off);
    }
    if (l == 0) score[n] = tanhf(dot / sqrtf(p2));
}

// full bitonic sort of (score, idx) per graph: descending score, ascending idx on ties
__global__ void topk_kernel(const float* __restrict__ score, float* __restrict__ vals,
                            int* __restrict__ perm, int* __restrict__ inv, int n, int k)
{
    __shared__ float skey[1024];
    __shared__ int   sidx[1024];
    int b = blockIdx.x;
    for (int i = threadIdx.x; i < 1024; i += blockDim.x) {
        skey[i] = (i < n) ? score[b * n + i] : -3.402823466e38f;
        sidx[i] = i;
    }
    __syncthreads();
    for (int kk = 2; kk <= 1024; kk <<= 1) {
        for (int j = kk >> 1; j > 0; j >>= 1) {
            for (int i = threadIdx.x; i < 1024; i += blockDim.x) {
                int ixj = i ^ j;
                if (ixj > i) {
                    float ka = skey[i], kb = skey[ixj];
                    int ia = sidx[i], ib = sidx[ixj];
                    bool up = ((i & kk) == 0);
                    bool sw = up ? ((ka < kb) || (ka == kb && ia > ib))
                                 : ((ka > kb) || (ka == kb && ia < ib));
                    if (sw) { skey[i] = kb; skey[ixj] = ka; sidx[i] = ib; sidx[ixj] = ia; }
                }
            }
            __syncthreads();
        }
    }
    for (int j = threadIdx.x; j < k; j += blockDim.x) {
        int oid = b * n + sidx[j];
        vals[b * k + j] = skey[j];
        perm[b * k + j] = oid;
        inv[oid] = b * k + j;
    }
}

__global__ void pool_gather(const float* __restrict__ hc, const int* __restrict__ perm,
                            const float* __restrict__ vals, float* __restrict__ h,
                            float* __restrict__ flats, int k)
{
    int b = blockIdx.x;
    int w = threadIdx.x >> 5, l = threadIdx.x & 31;
    float4 sum = make_float4(0.f, 0.f, 0.f, 0.f);
    float4 mx  = make_float4(-3.402823466e38f, -3.402823466e38f, -3.402823466e38f, -3.402823466e38f);
    for (int j = w; j < k; j += 8) {
        int r = b * k + j;
        int p = perm[r];
        float v = vals[r];
        float4 hv = ((const float4*)(hc + (size_t)p * 128))[l];
        hv.x *= v; hv.y *= v; hv.z *= v; hv.w *= v;
        ((float4*)(h + (size_t)r * 128))[l] = hv;
        sum.x += hv.x; sum.y += hv.y; sum.z += hv.z; sum.w += hv.w;
        mx.x = fmaxf(mx.x, hv.x); mx.y = fmaxf(mx.y, hv.y);
        mx.z = fmaxf(mx.z, hv.z); mx.w = fmaxf(mx.w, hv.w);
    }
    __shared__ float4 ssum[8][32];
    __shared__ float4 smax[8][32];
    ssum[w][l] = sum; smax[w][l] = mx;
    __syncthreads();
    if (w == 0) {
#pragma unroll
        for (int q = 1; q < 8; q++) {
            float4 s2 = ssum[q][l], m2 = smax[q][l];
            sum.x += s2.x; sum.y += s2.y; sum.z += s2.z; sum.w += s2.w;
            mx.x = fmaxf(mx.x, m2.x); mx.y = fmaxf(mx.y, m2.y);
            mx.z = fmaxf(mx.z, m2.z); mx.w = fmaxf(mx.w, m2.w);
        }
        float kin = (float)k;
        float* f1 = flats + b * 256 + l * 4;
        f1[0] += sum.x / kin; f1[1] += sum.y / kin; f1[2] += sum.z / kin; f1[3] += sum.w / kin;
        float* f2 = flats + b * 256 + 128 + l * 4;
        f2[0] += mx.x; f2[1] += mx.y; f2[2] += mx.z; f2[3] += mx.w;
    }
}

__global__ void edge_remap(int* __restrict__ src, int* __restrict__ dst, float* __restrict__ we,
                           const int* __restrict__ inv, int E)
{
    int e = blockIdx.x * blockDim.x + threadIdx.x;
    if (e >= E) return;
    int s = src[e], d = dst[e];
    int is = inv[s], id = inv[d];
    bool ok = (is >= 0) && (id >= 0);
    src[e] = ok ? is : 0;
    dst[e] = ok ? id : 0;
    if (!ok) we[e] = 0.f;
}

__global__ __launch_bounds__(512)
void mlp_kernel(const float* __restrict__ flats, const float* __restrict__ d1w,
                const float* __restrict__ d1b, const float* __restrict__ d2w,
                const float* __restrict__ d2b, float* __restrict__ out)
{
    __shared__ float f[256];
    __shared__ float hd[512];
    int b = blockIdx.x, t = threadIdx.x;
    if (t < 256) f[t] = flats[b * 256 + t];
    __syncthreads();
    float acc = d1b[t];
#pragma unroll 8
    for (int i = 0; i < 256; i++) acc = fmaf(f[i], d1w[i * 512 + t], acc);
    hd[t] = fmaxf(acc, 0.f);
    __syncthreads();
    if (t < CC) {
        float o = d2b[t];
#pragma unroll 8
        for (int i = 0; i < 512; i++) o = fmaf(hd[i], d2w[i * CC + t], o);
        out[b * CC + t] = o;
    }
}

// ---------------- host launcher ----------------
extern "C" void kernel_launch(void* const* d_in, const int* in_sizes, int n_in,
                              void* d_out, int out_size)
{
    const float* x       = (const float*)d_in[0];
    const int*   ei      = (const int*)d_in[1];
    const float* ew      = (const float*)d_in[3];
    const float* conv1_w = (const float*)d_in[4];
    const float* conv_w  = (const float*)d_in[5];
    const float* conv_b  = (const float*)d_in[6];
    const float* bn_g    = (const float*)d_in[7];
    const float* bn_be   = (const float*)d_in[8];
    const float* bn_m    = (const float*)d_in[9];
    const float* bn_v    = (const float*)d_in[10];
    const float* pool_w  = (const float*)d_in[11];
    const float* d1w     = (const float*)d_in[12];
    const float* d1b     = (const float*)d_in[13];
    const float* d2w     = (const float*)d_in[14];
    const float* d2b     = (const float*)d_in[15];
    int E = in_sizes[3];

    float *h, *xw, *hc, *deg, *score, *we, *ecoef, *vals, *flats;
    int *src, *dst, *indeg, *cursor, *inv, *rowptr, *esrc, *perm, *partials;
    cudaGetSymbolAddress((void**)&h,        g_h);
    cudaGetSymbolAddress((void**)&xw,       g_xw);
    cudaGetSymbolAddress((void**)&hc,       g_hc);
    cudaGetSymbolAddress((void**)&deg,      g_deg);
    cudaGetSymbolAddress((void**)&score,    g_score);
    cudaGetSymbolAddress((void**)&src,      g_src);
    cudaGetSymbolAddress((void**)&dst,      g_dst);
    cudaGetSymbolAddress((void**)&we,       g_we);
    cudaGetSymbolAddress((void**)&indeg,    g_indeg);
    cudaGetSymbolAddress((void**)&cursor,   g_cursor);
    cudaGetSymbolAddress((void**)&inv,      g_inv);
    cudaGetSymbolAddress((void**)&rowptr,   g_rowptr);
    cudaGetSymbolAddress((void**)&esrc,     g_esrc);
    cudaGetSymbolAddress((void**)&ecoef,    g_ecoef);
    cudaGetSymbolAddress((void**)&perm,     g_perm);
    cudaGetSymbolAddress((void**)&vals,     g_vals);
    cudaGetSymbolAddress((void**)&flats,    g_flats);
    cudaGetSymbolAddress((void**)&partials, g_partials);

    const int ns[6] = {1000, 800, 640, 512, 410, 328};
    const int ks[6] = {800, 640, 512, 410, 328, 263};
    int eb = (E + 255) / 256;

    init_kernel<<<eb, 256>>>(ei, ew, src, dst, we, flats, E);

    for (int i = 0; i < 6; i++) {
        int n = ns[i], k = ks[i], N = BB * n;
        int nb = (N + 255) / 256;
        int nch = (N + 1023) >> 10;

        node_init<<<nb, 256>>>(deg, indeg, cursor, inv, N);
        edge_count<<<eb, 256>>>(dst, we, deg, indeg, E);
        dinv_kernel<<<nb, 256>>>(deg, N);
        scan_local<<<nch, 1024>>>(indeg, rowptr, partials, N);
        scan_partials<<<1, 64>>>(partials, rowptr, nch, N);
        scan_add<<<nb, 256>>>(rowptr, partials, N);
        edge_scatter<<<eb, 256>>>(src, dst, we, deg, rowptr, cursor, esrc, ecoef, E);

        if (i == 0) matmul_kernel<64><<<N / 64, 256>>>(x, conv1_w, xw);
        else        matmul_kernel<128><<<N / 64, 256>>>(h, conv_w + (size_t)(i - 1) * 128 * 128, xw);

        gcn_gather<<<N / 8, 256>>>(xw, rowptr, esrc, ecoef, deg,
                                   conv_b + i * 128, bn_g + i * 128, bn_be + i * 128,
                                   bn_m + i * 128, bn_v + i * 128, pool_w + i * 128,
                                   hc, score, N);
        topk_kernel<<<BB, 256>>>(score, vals, perm, inv, n, k);
        pool_gather<<<BB, 256>>>(hc, perm, vals, h, flats, k);
        edge_remap<<<eb, 256>>>(src, dst, we, inv, E);
    }

    mlp_kernel<<<BB, 512>>>(flats, d1w, d1b, d2w, d2b, (float*)d_out);
}

// round 2
// speedup vs baseline: 1.0064x; 1.0064x over previous
#include <cuda_runtime.h>
#include <cuda_bf16.h>
#include <math.h>

#define BB 64
#define NPG 1000
#define HD 128
#define CC 10
#define NMAX (BB*NPG)           // 64000
#define EMAX (BB*NPG*16)        // 1024000

typedef unsigned long long ull;

// ---------------- scratch (device globals; no allocation) ----------------
__device__ float g_h[NMAX*HD];
__device__ float g_xw[NMAX*HD];
__device__ float g_hc[NMAX*HD];
__device__ float g_deg[2][NMAX];        // becomes dinv in place per layer
__device__ int   g_indeg[2][NMAX];
__device__ int   g_cursor[2][NMAX];
__device__ int   g_inv[2][NMAX];
__device__ float g_score[NMAX];
__device__ int   g_src[EMAX];
__device__ int   g_dst[EMAX];
__device__ float g_we[EMAX];
__device__ int   g_rowptr[NMAX+1];
__device__ int   g_esrc[EMAX];
__device__ float g_ecoef[EMAX];
__device__ int   g_perm[NMAX];
__device__ float g_vals[NMAX];
__device__ float g_flats[BB*2*HD];
__device__ int   g_flags[6*64];

// ---------------- helpers ----------------
__device__ __forceinline__ void ffma2(ull& c, ull a, ull b) {
    asm("fma.rn.f32x2 %0, %1, %2, %0;" : "+l"(c) : "l"(a), "l"(b));
}
__device__ __forceinline__ float2 unpack2(ull v) {
    float2 f; asm("mov.b64 {%0, %1}, %2;" : "=f"(f.x), "=f"(f.y) : "l"(v)); return f;
}

// ---------------- kernels ----------------

__global__ void init_kernel(const int* __restrict__ ei, const float* __restrict__ ew,
                            int* __restrict__ src, int* __restrict__ dst, float* __restrict__ we,
                            float* __restrict__ flats, int* __restrict__ flags,
                            float* __restrict__ deg0, int* __restrict__ indeg0,
                            int* __restrict__ cursor0, int* __restrict__ inv0,
                            int E, int N0)
{
    int i = blockIdx.x * blockDim.x + threadIdx.x;
    if (i < E) { src[i] = ei[i]; dst[i] = ei[E + i]; we[i] = ew[i]; }
    if (i < BB * 2 * HD) flats[i] = 0.f;
    if (i < 6 * 64) flags[i] = 0;
    if (i < N0) { deg0[i] = 1.0f; indeg0[i] = 0; cursor0[i] = 0; inv0[i] = -1; }
}

__global__ void count0_kernel(const int* __restrict__ dst, const float* __restrict__ we,
                              float* __restrict__ deg, int* __restrict__ indeg, int E)
{
    int e = blockIdx.x * blockDim.x + threadIdx.x;
    if (e >= E) return;
    float w = we[e];
    if (w > 0.f) {
        int d = dst[e];
        atomicAdd(&deg[d], w);
        atomicAdd(&indeg[d], 1);
    }
}

// one-kernel decoupled scan + dinv + init of next-layer node buffers
__global__ __launch_bounds__(1024)
void scan_fused(const int* __restrict__ indeg, float* __restrict__ dinv,
                int* __restrict__ rowptr, int* __restrict__ flags,
                float* __restrict__ degN, int* __restrict__ indegN,
                int* __restrict__ cursorN, int* __restrict__ invN,
                int N, int Nnext)
{
    __shared__ int sd[1024];
    __shared__ int wred[32];
    __shared__ int s_prefix, s_tot;
    int tid = threadIdx.x, bid = blockIdx.x;
    int i = bid * 1024 + tid;
    int v = (i < N) ? indeg[i] : 0;

    // fast block total
    int ws = v;
#pragma unroll
    for (int o = 16; o; o >>= 1) ws += __shfl_xor_sync(0xffffffffu, ws, o);
    if ((tid & 31) == 0) wred[tid >> 5] = ws;
    if (tid == 0) s_prefix = 0;
    __syncthreads();
    if (tid == 0) {
        int tot = 0;
#pragma unroll
        for (int q = 0; q < 32; q++) tot += wred[q];
        s_tot = tot;
        atomicExch(&flags[bid], tot + 1);   // publish early
    }
    // every predecessor polled in parallel by a different thread
    if (tid < bid) {
        volatile int* fp = flags + tid;
        int f;
        while ((f = *fp) == 0) {}
        atomicAdd(&s_prefix, f - 1);
    }
    // local inclusive scan (Hillis-Steele)
    sd[tid] = v;
    for (int off = 1; off < 1024; off <<= 1) {
        __syncthreads();
        int t = (tid >= off) ? sd[tid - off] : 0;
        __syncthreads();
        sd[tid] += t;
    }
    __syncthreads();
    int prefix = s_prefix;
    if (i < N) {
        rowptr[i] = prefix + sd[tid] - v;
        dinv[i] = rsqrtf(dinv[i]);          // deg -> dinv in place
    }
    if (tid == 0 && bid == gridDim.x - 1) rowptr[N] = prefix + s_tot;
    if (i < Nnext) { degN[i] = 1.0f; indegN[i] = 0; cursorN[i] = 0; invN[i] = -1; }
}

__global__ void edge_scatter(const int* __restrict__ src, const int* __restrict__ dst,
                             const float* __restrict__ we, const float* __restrict__ dinv,
                             const int* __restrict__ rowptr, int* __restrict__ cursor,
                             int* __restrict__ esrc, float* __restrict__ ecoef, int E)
{
    int e = blockIdx.x * blockDim.x + threadIdx.x;
    if (e >= E) return;
    float w = we[e];
    if (w <= 0.f) return;
    int s = src[e], d = dst[e];
    int pos = rowptr[d] + atomicAdd(&cursor[d], 1);
    esrc[pos] = s;
    ecoef[pos] = dinv[s] * dinv[d] * w;
}

// packed-f32x2 matmul: Hs[row][k] (LDS.64 broadcast pairs), Wt[col][k] transposed
template<int HIN>
__global__ __launch_bounds__(256, 2)
void matmul_kernel(const float* __restrict__ A, const float* __restrict__ W, float* __restrict__ out)
{
    extern __shared__ float sm[];
    float (*Hs)[64] = (float(*)[64])sm;              // 64 x 64
    float (*Wt)[66] = (float(*)[66])(sm + 64 * 64);  // 128 x 66 (8B-aligned rows)
    int tid = threadIdx.x;
    int tx = tid & 31, ty = tid >> 5;
    int rowBase = blockIdx.x * 64;
    ull acc[8][4];
#pragma unroll
    for (int r = 0; r < 8; r++)
#pragma unroll
        for (int j = 0; j < 4; j++) acc[r][j] = 0ull;

#pragma unroll
    for (int kc = 0; kc < HIN; kc += 64) {
#pragma unroll
        for (int it = 0; it < 4; it++) {             // A tile 64x64
            int e = tid + it * 256;
            int r = e >> 4, c4 = e & 15;
            *(float4*)&Hs[r][c4 * 4] =
                *(const float4*)(A + (size_t)(rowBase + r) * HIN + kc + c4 * 4);
        }
#pragma unroll
        for (int it = 0; it < 8; it++) {             // W tile 64x128 transposed
            int e = tid + it * 256;
            int k = e >> 5, c4 = e & 31;
            float4 w = *(const float4*)(W + (size_t)(kc + k) * 128 + c4 * 4);
            Wt[c4 * 4 + 0][k] = w.x;
            Wt[c4 * 4 + 1][k] = w.y;
            Wt[c4 * 4 + 2][k] = w.z;
            Wt[c4 * 4 + 3][k] = w.w;
        }
        __syncthreads();
#pragma unroll 4
        for (int k2 = 0; k2 < 32; k2++) {
            ull w2[4];
#pragma unroll
            for (int j = 0; j < 4; j++)
                w2[j] = *(const ull*)&Wt[tx + 32 * j][2 * k2];
#pragma unroll
            for (int r = 0; r < 8; r++) {
                ull h2 = *(const ull*)&Hs[ty + 8 * r][2 * k2];
#pragma unroll
                for (int j = 0; j < 4; j++) ffma2(acc[r][j], h2, w2[j]);
            }
        }
        __syncthreads();
    }
#pragma unroll
    for (int r = 0; r < 8; r++) {
        int row = rowBase + ty + 8 * r;
#pragma unroll
        for (int j = 0; j < 4; j++) {
            float2 v = unpack2(acc[r][j]);
            out[(size_t)row * 128 + tx + 32 * j] = v.x + v.y;
        }
    }
}

__global__ void gcn_gather(const float* __restrict__ xw, const int* __restrict__ rowptr,
                           const int* __restrict__ esrc, const float* __restrict__ ecoef,
                           const float* __restrict__ dinv,
                           const float* __restrict__ bias, const float* __restrict__ bng,
                           const float* __restrict__ bnb, const float* __restrict__ bnm,
                           const float* __restrict__ bnv, const float* __restrict__ pw,
                           float* __restrict__ hc, float* __restrict__ score, int N)
{
    int n = (blockIdx.x * blockDim.x + threadIdx.x) >> 5;
    int l = threadIdx.x & 31;
    if (n >= N) return;
    float di = dinv[n];
    float sc = di * di;
    float4 a = ((const float4*)(xw + (size_t)n * 128))[l];
    float4 acc = make_float4(a.x * sc, a.y * sc, a.z * sc, a.w * sc);
    int e0 = rowptr[n], e1 = rowptr[n + 1];
    for (int e = e0; e < e1; ++e) {
        int s = esrc[e];
        float c = ecoef[e];
        float4 v = ((const float4*)(xw + (size_t)s * 128))[l];
        acc.x = fmaf(c, v.x, acc.x);
        acc.y = fmaf(c, v.y, acc.y);
        acc.z = fmaf(c, v.z, acc.z);
        acc.w = fmaf(c, v.w, acc.w);
    }
    float4 bb = ((const float4*)bias)[l];
    float4 g  = ((const float4*)bng)[l];
    float4 be = ((const float4*)bnb)[l];
    float4 m  = ((const float4*)bnm)[l];
    float4 vv = ((const float4*)bnv)[l];
    float4 o;
    o.x = fmaxf((acc.x + bb.x - m.x) * (g.x * rsqrtf(vv.x + 1e-5f)) + be.x, 0.f);
    o.y = fmaxf((acc.y + bb.y - m.y) * (g.y * rsqrtf(vv.y + 1e-5f)) + be.y, 0.f);
    o.z = fmaxf((acc.z + bb.z - m.z) * (g.z * rsqrtf(vv.z + 1e-5f)) + be.z, 0.f);
    o.w = fmaxf((acc.w + bb.w - m.w) * (g.w * rsqrtf(vv.w + 1e-5f)) + be.w, 0.f);
    ((float4*)(hc + (size_t)n * 128))[l] = o;
    float4 p = ((const float4*)pw)[l];
    float dot = o.x * p.x + o.y * p.y + o.z * p.z + o.w * p.w;
    float p2  = p.x * p.x + p.y * p.y + p.z * p.z + p.w * p.w;
#pragma unroll
    for (int off = 16; off; off >>= 1) {
        dot += __shfl_xor_sync(0xffffffffu, dot, off);
        p2  += __shfl_xor_sync(0xffffffffu, p2, off);
    }
    if (l == 0) score[n] = tanhf(dot * rsqrtf(p2));
}

// full bitonic sort of (score, idx) per graph: descending score, ascending idx on ties
__global__ void topk_kernel(const float* __restrict__ score, float* __restrict__ vals,
                            int* __restrict__ perm, int* __restrict__ inv, int n, int k)
{
    __shared__ float skey[1024];
    __shared__ int   sidx[1024];
    int b = blockIdx.x;
    for (int i = threadIdx.x; i < 1024; i += blockDim.x) {
        skey[i] = (i < n) ? score[b * n + i] : -3.402823466e38f;
        sidx[i] = i;
    }
    __syncthreads();
    for (int kk = 2; kk <= 1024; kk <<= 1) {
        for (int j = kk >> 1; j > 0; j >>= 1) {
            for (int i = threadIdx.x; i < 1024; i += blockDim.x) {
                int ixj = i ^ j;
                if (ixj > i) {
                    float ka = skey[i], kb = skey[ixj];
                    int ia = sidx[i], ib = sidx[ixj];
                    bool up = ((i & kk) == 0);
                    bool sw = up ? ((ka < kb) || (ka == kb && ia > ib))
                                 : ((ka > kb) || (ka == kb && ia < ib));
                    if (sw) { skey[i] = kb; skey[ixj] = ka; sidx[i] = ib; sidx[ixj] = ia; }
                }
            }
            __syncthreads();
        }
    }
    for (int j = threadIdx.x; j < k; j += blockDim.x) {
        int oid = b * n + sidx[j];
        vals[b * k + j] = skey[j];
        perm[b * k + j] = oid;
        inv[oid] = b * k + j;
    }
}

__global__ void pool_gather(const float* __restrict__ hc, const int* __restrict__ perm,
                            const float* __restrict__ vals, float* __restrict__ h,
                            float* __restrict__ flats, int k)
{
    int b = blockIdx.x;
    int w = threadIdx.x >> 5, l = threadIdx.x & 31;
    float4 sum = make_float4(0.f, 0.f, 0.f, 0.f);
    float4 mx  = make_float4(-3.402823466e38f, -3.402823466e38f, -3.402823466e38f, -3.402823466e38f);
    for (int j = w; j < k; j += 8) {
        int r = b * k + j;
        int p = perm[r];
        float v = vals[r];
        float4 hv = ((const float4*)(hc + (size_t)p * 128))[l];
        hv.x *= v; hv.y *= v; hv.z *= v; hv.w *= v;
        ((float4*)(h + (size_t)r * 128))[l] = hv;
        sum.x += hv.x; sum.y += hv.y; sum.z += hv.z; sum.w += hv.w;
        mx.x = fmaxf(mx.x, hv.x); mx.y = fmaxf(mx.y, hv.y);
        mx.z = fmaxf(mx.z, hv.z); mx.w = fmaxf(mx.w, hv.w);
    }
    __shared__ float4 ssum[8][32];
    __shared__ float4 smax[8][32];
    ssum[w][l] = sum; smax[w][l] = mx;
    __syncthreads();
    if (w == 0) {
#pragma unroll
        for (int q = 1; q < 8; q++) {
            float4 s2 = ssum[q][l], m2 = smax[q][l];
            sum.x += s2.x; sum.y += s2.y; sum.z += s2.z; sum.w += s2.w;
            mx.x = fmaxf(mx.x, m2.x); mx.y = fmaxf(mx.y, m2.y);
            mx.z = fmaxf(mx.z, m2.z); mx.w = fmaxf(mx.w, m2.w);
        }
        float kin = (float)k;
        float* f1 = flats + b * 256 + l * 4;
        f1[0] += sum.x / kin; f1[1] += sum.y / kin; f1[2] += sum.z / kin; f1[3] += sum.w / kin;
        float* f2 = flats + b * 256 + 128 + l * 4;
        f2[0] += mx.x; f2[1] += mx.y; f2[2] += mx.z; f2[3] += mx.w;
    }
}

// remap edges to pooled ids AND accumulate next layer's deg/indeg (buffers pre-inited in scan_fused)
__global__ void remap_count(int* __restrict__ src, int* __restrict__ dst, float* __restrict__ we,
                            const int* __restrict__ inv,
                            float* __restrict__ degN, int* __restrict__ indegN, int E)
{
    int e = blockIdx.x * blockDim.x + threadIdx.x;
    if (e >= E) return;
    int s = src[e], d = dst[e];
    int is = inv[s], id = inv[d];
    bool ok = (is >= 0) && (id >= 0);
    float w = we[e];
    if (!ok) { is = 0; id = 0; if (w != 0.f) we[e] = 0.f; w = 0.f; }
    src[e] = is; dst[e] = id;
    if (w > 0.f) {
        atomicAdd(&degN[id], w);
        atomicAdd(&indegN[id], 1);
    }
}

__global__ __launch_bounds__(512)
void mlp_kernel(const float* __restrict__ flats, const float* __restrict__ d1w,
                const float* __restrict__ d1b, const float* __restrict__ d2w,
                const float* __restrict__ d2b, float* __restrict__ out)
{
    __shared__ float f[256];
    __shared__ float hd[512];
    int b = blockIdx.x, t = threadIdx.x;
    if (t < 256) f[t] = flats[b * 256 + t];
    __syncthreads();
    float acc = d1b[t];
#pragma unroll 8
    for (int i = 0; i < 256; i++) acc = fmaf(f[i], d1w[i * 512 + t], acc);
    hd[t] = fmaxf(acc, 0.f);
    __syncthreads();
    if (t < CC) {
        float o = d2b[t];
#pragma unroll 8
        for (int i = 0; i < 512; i++) o = fmaf(hd[i], d2w[i * CC + t], o);
        out[b * CC + t] = o;
    }
}

// ---------------- host launcher ----------------
extern "C" void kernel_launch(void* const* d_in, const int* in_sizes, int n_in,
                              void* d_out, int out_size)
{
    const float* x       = (const float*)d_in[0];
    const int*   ei      = (const int*)d_in[1];
    const float* ew      = (const float*)d_in[3];
    const float* conv1_w = (const float*)d_in[4];
    const float* conv_w  = (const float*)d_in[5];
    const float* conv_b  = (const float*)d_in[6];
    const float* bn_g    = (const float*)d_in[7];
    const float* bn_be   = (const float*)d_in[8];
    const float* bn_m    = (const float*)d_in[9];
    const float* bn_v    = (const float*)d_in[10];
    const float* pool_w  = (const float*)d_in[11];
    const float* d1w     = (const float*)d_in[12];
    const float* d1b     = (const float*)d_in[13];
    const float* d2w     = (const float*)d_in[14];
    const float* d2b     = (const float*)d_in[15];
    int E = in_sizes[3];

    float *h, *xw, *hc, *score, *we, *ecoef, *vals, *flats;
    float *deg[2];
    int *src, *dst, *rowptr, *esrc, *perm, *flags;
    int *indeg[2], *cursor[2], *inv[2];
    cudaGetSymbolAddress((void**)&h,      g_h);
    cudaGetSymbolAddress((void**)&xw,     g_xw);
    cudaGetSymbolAddress((void**)&hc,     g_hc);
    cudaGetSymbolAddress((void**)&score,  g_score);
    cudaGetSymbolAddress((void**)&src,    g_src);
    cudaGetSymbolAddress((void**)&dst,    g_dst);
    cudaGetSymbolAddress((void**)&we,     g_we);
    cudaGetSymbolAddress((void**)&rowptr, g_rowptr);
    cudaGetSymbolAddress((void**)&esrc,   g_esrc);
    cudaGetSymbolAddress((void**)&ecoef,  g_ecoef);
    cudaGetSymbolAddress((void**)&perm,   g_perm);
    cudaGetSymbolAddress((void**)&vals,   g_vals);
    cudaGetSymbolAddress((void**)&flats,  g_flats);
    cudaGetSymbolAddress((void**)&flags,  g_flags);
    {
        float* p; cudaGetSymbolAddress((void**)&p, g_deg);
        deg[0] = p; deg[1] = p + NMAX;
        int* q;
        cudaGetSymbolAddress((void**)&q, g_indeg);  indeg[0]  = q; indeg[1]  = q + NMAX;
        cudaGetSymbolAddress((void**)&q, g_cursor); cursor[0] = q; cursor[1] = q + NMAX;
        cudaGetSymbolAddress((void**)&q, g_inv);    inv[0]    = q; inv[1]    = q + NMAX;
    }

    const int ns[6] = {1000, 800, 640, 512, 410, 328};
    const int ks[6] = {800, 640, 512, 410, 328, 263};
    int eb = (E + 255) / 256;
    const int SMEM_MM = (64 * 64 + 128 * 66) * 4;   // 50176

    cudaFuncSetAttribute(matmul_kernel<64>,  cudaFuncAttributeMaxDynamicSharedMemorySize, SMEM_MM);
    cudaFuncSetAttribute(matmul_kernel<128>, cudaFuncAttributeMaxDynamicSharedMemorySize, SMEM_MM);

    init_kernel<<<eb, 256>>>(ei, ew, src, dst, we, flats, flags,
                             deg[0], indeg[0], cursor[0], inv[0], E, BB * ns[0]);
    count0_kernel<<<eb, 256>>>(dst, we, deg[0], indeg[0], E);

    for (int i = 0; i < 6; i++) {
        int n = ns[i], k = ks[i], N = BB * n;
        int cur = i & 1, nxt = cur ^ 1;
        int Nnext = (i < 5) ? BB * k : 0;
        int nch = (N + 1023) >> 10;

        scan_fused<<<nch, 1024>>>(indeg[cur], deg[cur], rowptr, flags + i * 64,
                                  deg[nxt], indeg[nxt], cursor[nxt], inv[nxt], N, Nnext);
        edge_scatter<<<eb, 256>>>(src, dst, we, deg[cur], rowptr, cursor[cur], esrc, ecoef, E);

        if (i == 0) matmul_kernel<64><<<N / 64, 256, SMEM_MM>>>(x, conv1_w, xw);
        else        matmul_kernel<128><<<N / 64, 256, SMEM_MM>>>(h, conv_w + (size_t)(i - 1) * 128 * 128, xw);

        gcn_gather<<<N / 8, 256>>>(xw, rowptr, esrc, ecoef, deg[cur],
                                   conv_b + i * 128, bn_g + i * 128, bn_be + i * 128,
                                   bn_m + i * 128, bn_v + i * 128, pool_w + i * 128,
                                   hc, score, N);
        topk_kernel<<<BB, 256>>>(score, vals, perm, inv[cur], n, k);
        pool_gather<<<BB, 256>>>(hc, perm, vals, h, flats, k);
        if (i < 5)
            remap_count<<<eb, 256>>>(src, dst, we, inv[cur], deg[nxt], indeg[nxt], E);
    }

    mlp_kernel<<<BB, 512>>>(flats, d1w, d1b, d2w, d2b, (float*)d_out);
}

// round 3
// speedup vs baseline: 1.1978x; 1.1901x over previous
#include <cuda_runtime.h>
#include <cuda_bf16.h>
#include <math.h>

#define BB 64
#define NPG 1000
#define HD 128
#define CC 10
#define NMAX (BB*NPG)           // 64000
#define EMAX (BB*NPG*16)        // 1024000

typedef unsigned long long ull;

// ---------------- scratch (device globals; no allocation) ----------------
__device__ float g_h[NMAX*HD];
__device__ float g_xw[NMAX*HD];
__device__ float g_hc[NMAX*HD];
__device__ float g_deg[2][NMAX];        // becomes dinv in place per layer
__device__ int   g_indeg[2][NMAX];
__device__ int   g_cursor[2][NMAX];
__device__ int   g_inv[2][NMAX];
__device__ float g_score[NMAX];
__device__ int   g_srcE[2][EMAX];
__device__ int   g_dstE[2][EMAX];
__device__ float g_weE[2][EMAX];
__device__ int   g_rowptr[NMAX+1];
__device__ int   g_esrc[EMAX];
__device__ float g_ecoef[EMAX];
__device__ float g_flats[BB*2*HD];
__device__ int   g_flags[6*64];
__device__ int   g_nE[8];

// ---------------- helpers ----------------
__device__ __forceinline__ void ffma2(ull& c, ull a, ull b) {
    asm("fma.rn.f32x2 %0, %1, %2, %0;" : "+l"(c) : "l"(a), "l"(b));
}
__device__ __forceinline__ float2 unpack2(ull v) {
    float2 f; asm("mov.b64 {%0, %1}, %2;" : "=f"(f.x), "=f"(f.y) : "l"(v)); return f;
}

// ---------------- kernels ----------------

__global__ void init_kernel(const int* __restrict__ ei, const float* __restrict__ ew,
                            int* __restrict__ src, int* __restrict__ dst, float* __restrict__ we,
                            float* __restrict__ flats, int* __restrict__ flags,
                            float* __restrict__ deg0, int* __restrict__ indeg0,
                            int* __restrict__ cursor0, int* __restrict__ inv0,
                            int* __restrict__ nE, int E, int N0)
{
    int i = blockIdx.x * blockDim.x + threadIdx.x;
    if (i < E) { src[i] = ei[i]; dst[i] = ei[E + i]; we[i] = ew[i]; }
    if (i < BB * 2 * HD) flats[i] = 0.f;
    if (i < 6 * 64) flags[i] = 0;
    if (i < 8) nE[i] = (i == 0) ? E : 0;
    if (i < N0) { deg0[i] = 1.0f; indeg0[i] = 0; cursor0[i] = 0; inv0[i] = -1; }
}

__global__ void count0_kernel(const int* __restrict__ dst, const float* __restrict__ we,
                              float* __restrict__ deg, int* __restrict__ indeg, int E)
{
    int e = blockIdx.x * blockDim.x + threadIdx.x;
    if (e >= E) return;
    float w = we[e];
    if (w > 0.f) {
        int d = dst[e];
        atomicAdd(&deg[d], w);
        atomicAdd(&indeg[d], 1);
    }
}

// one-kernel decoupled scan + dinv + init of next-layer node buffers
__global__ __launch_bounds__(1024)
void scan_fused(const int* __restrict__ indeg, float* __restrict__ dinv,
                int* __restrict__ rowptr, int* __restrict__ flags,
                float* __restrict__ degN, int* __restrict__ indegN,
                int* __restrict__ cursorN, int* __restrict__ invN,
                int N, int Nnext)
{
    __shared__ int sd[1024];
    __shared__ int wred[32];
    __shared__ int s_prefix, s_tot;
    int tid = threadIdx.x, bid = blockIdx.x;
    int i = bid * 1024 + tid;
    int v = (i < N) ? indeg[i] : 0;

    int ws = v;
#pragma unroll
    for (int o = 16; o; o >>= 1) ws += __shfl_xor_sync(0xffffffffu, ws, o);
    if ((tid & 31) == 0) wred[tid >> 5] = ws;
    if (tid == 0) s_prefix = 0;
    __syncthreads();
    if (tid == 0) {
        int tot = 0;
#pragma unroll
        for (int q = 0; q < 32; q++) tot += wred[q];
        s_tot = tot;
        atomicExch(&flags[bid], tot + 1);   // publish early
    }
    if (tid < bid) {
        volatile int* fp = flags + tid;
        int f;
        while ((f = *fp) == 0) {}
        atomicAdd(&s_prefix, f - 1);
    }
    sd[tid] = v;
    for (int off = 1; off < 1024; off <<= 1) {
        __syncthreads();
        int t = (tid >= off) ? sd[tid - off] : 0;
        __syncthreads();
        sd[tid] += t;
    }
    __syncthreads();
    int prefix = s_prefix;
    if (i < N) {
        rowptr[i] = prefix + sd[tid] - v;
        dinv[i] = rsqrtf(dinv[i]);          // deg -> dinv in place
    }
    if (tid == 0 && bid == gridDim.x - 1) rowptr[N] = prefix + s_tot;
    if (i < Nnext) { degN[i] = 1.0f; indegN[i] = 0; cursorN[i] = 0; invN[i] = -1; }
}

// merged: blocks [0, mmB) do the GEMM (packed f32x2, KC=32 tiles);
// blocks [mmB, mmB+EB) do the CSR edge scatter — independent work, overlapped.
template<int HIN>
__global__ __launch_bounds__(256, 2)
void mm_scatter(const float* __restrict__ A, const float* __restrict__ W,
                float* __restrict__ out, int mmB,
                const int* __restrict__ srcC, const int* __restrict__ dstC,
                const float* __restrict__ weC, const float* __restrict__ dinv,
                const int* __restrict__ rowptr, int* __restrict__ cursor,
                int* __restrict__ esrc, float* __restrict__ ecoef,
                const int* __restrict__ pcnt)
{
    __shared__ float Hs[64][32];
    __shared__ float Wt[128][34];

    if (blockIdx.x >= mmB) {
        int e = (blockIdx.x - mmB) * 256 + threadIdx.x;
        int cnt = *pcnt;
        if (e >= cnt) return;
        float w = weC[e];
        if (w <= 0.f) return;
        int s = srcC[e], d = dstC[e];
        int pos = rowptr[d] + atomicAdd(&cursor[d], 1);
        esrc[pos] = s;
        ecoef[pos] = dinv[s] * dinv[d] * w;
        return;
    }

    int tid = threadIdx.x;
    int tx = tid & 31, ty = tid >> 5;
    int rowBase = blockIdx.x * 64;
    ull acc[8][4];
#pragma unroll
    for (int r = 0; r < 8; r++)
#pragma unroll
        for (int j = 0; j < 4; j++) acc[r][j] = 0ull;

#pragma unroll
    for (int kc = 0; kc < HIN; kc += 32) {
#pragma unroll
        for (int it = 0; it < 2; it++) {             // A tile 64x32
            int idx = tid + it * 256;
            int r = idx >> 3, c4 = idx & 7;
            *(float4*)&Hs[r][c4 * 4] =
                *(const float4*)(A + (size_t)(rowBase + r) * HIN + kc + c4 * 4);
        }
#pragma unroll
        for (int it = 0; it < 4; it++) {             // W tile 32x128 transposed
            int idx = tid + it * 256;
            int kr = idx >> 5, c4 = idx & 31;
            float4 w = *(const float4*)(W + (size_t)(kc + kr) * 128 + c4 * 4);
            Wt[c4 * 4 + 0][kr] = w.x;
            Wt[c4 * 4 + 1][kr] = w.y;
            Wt[c4 * 4 + 2][kr] = w.z;
            Wt[c4 * 4 + 3][kr] = w.w;
        }
        __syncthreads();
#pragma unroll 4
        for (int k2 = 0; k2 < 16; k2++) {
            ull w2[4];
#pragma unroll
            for (int j = 0; j < 4; j++)
                w2[j] = *(const ull*)&Wt[tx + 32 * j][2 * k2];
#pragma unroll
            for (int r = 0; r < 8; r++) {
                ull h2 = *(const ull*)&Hs[ty + 8 * r][2 * k2];
#pragma unroll
                for (int j = 0; j < 4; j++) ffma2(acc[r][j], h2, w2[j]);
            }
        }
        __syncthreads();
    }
#pragma unroll
    for (int r = 0; r < 8; r++) {
        int row = rowBase + ty + 8 * r;
#pragma unroll
        for (int j = 0; j < 4; j++) {
            float2 v = unpack2(acc[r][j]);
            out[(size_t)row * 128 + tx + 32 * j] = v.x + v.y;
        }
    }
}

__global__ void gcn_gather(const float* __restrict__ xw, const int* __restrict__ rowptr,
                           const int* __restrict__ esrc, const float* __restrict__ ecoef,
                           const float* __restrict__ dinv,
                           const float* __restrict__ bias, const float* __restrict__ bng,
                           const float* __restrict__ bnb, const float* __restrict__ bnm,
                           const float* __restrict__ bnv, const float* __restrict__ pw,
                           float* __restrict__ hc, float* __restrict__ score, int N)
{
    int n = (blockIdx.x * blockDim.x + threadIdx.x) >> 5;
    int l = threadIdx.x & 31;
    if (n >= N) return;
    float di = dinv[n];
    float sc = di * di;
    float4 a = ((const float4*)(xw + (size_t)n * 128))[l];
    float4 acc = make_float4(a.x * sc, a.y * sc, a.z * sc, a.w * sc);
    float4 acc2 = make_float4(0.f, 0.f, 0.f, 0.f);
    int e0 = rowptr[n], e1 = rowptr[n + 1];
    int e = e0;
    for (; e + 2 <= e1; e += 2) {
        int s0 = esrc[e],     s1 = esrc[e + 1];
        float c0 = ecoef[e],  c1 = ecoef[e + 1];
        float4 v0 = ((const float4*)(xw + (size_t)s0 * 128))[l];
        float4 v1 = ((const float4*)(xw + (size_t)s1 * 128))[l];
        acc.x  = fmaf(c0, v0.x, acc.x);   acc.y  = fmaf(c0, v0.y, acc.y);
        acc.z  = fmaf(c0, v0.z, acc.z);   acc.w  = fmaf(c0, v0.w, acc.w);
        acc2.x = fmaf(c1, v1.x, acc2.x);  acc2.y = fmaf(c1, v1.y, acc2.y);
        acc2.z = fmaf(c1, v1.z, acc2.z);  acc2.w = fmaf(c1, v1.w, acc2.w);
    }
    if (e < e1) {
        int s = esrc[e];
        float c = ecoef[e];
        float4 v = ((const float4*)(xw + (size_t)s * 128))[l];
        acc.x = fmaf(c, v.x, acc.x);
        acc.y = fmaf(c, v.y, acc.y);
        acc.z = fmaf(c, v.z, acc.z);
        acc.w = fmaf(c, v.w, acc.w);
    }
    acc.x += acc2.x; acc.y += acc2.y; acc.z += acc2.z; acc.w += acc2.w;
    float4 bb = ((const float4*)bias)[l];
    float4 g  = ((const float4*)bng)[l];
    float4 be = ((const float4*)bnb)[l];
    float4 m  = ((const float4*)bnm)[l];
    float4 vv = ((const float4*)bnv)[l];
    float4 o;
    o.x = fmaxf((acc.x + bb.x - m.x) * (g.x * rsqrtf(vv.x + 1e-5f)) + be.x, 0.f);
    o.y = fmaxf((acc.y + bb.y - m.y) * (g.y * rsqrtf(vv.y + 1e-5f)) + be.y, 0.f);
    o.z = fmaxf((acc.z + bb.z - m.z) * (g.z * rsqrtf(vv.z + 1e-5f)) + be.z, 0.f);
    o.w = fmaxf((acc.w + bb.w - m.w) * (g.w * rsqrtf(vv.w + 1e-5f)) + be.w, 0.f);
    ((float4*)(hc + (size_t)n * 128))[l] = o;
    float4 p = ((const float4*)pw)[l];
    float dot = o.x * p.x + o.y * p.y + o.z * p.z + o.w * p.w;
    float p2  = p.x * p.x + p.y * p.y + p.z * p.z + p.w * p.w;
#pragma unroll
    for (int off = 16; off; off >>= 1) {
        dot += __shfl_xor_sync(0xffffffffu, dot, off);
        p2  += __shfl_xor_sync(0xffffffffu, p2, off);
    }
    if (l == 0) score[n] = tanhf(dot * rsqrtf(p2));
}

// fused: bitonic full sort (1024 threads, 1 cmp-exch/thread/step) + pooled h + flats
__global__ __launch_bounds__(1024)
void topk_pool(const float* __restrict__ score, const float* __restrict__ hc,
               float* __restrict__ h, float* __restrict__ flats,
               int* __restrict__ inv, int n, int k)
{
    __shared__ float skey[1024];
    __shared__ int   sidx[1024];
    __shared__ float4 ssum[32][32];
    __shared__ float4 smax[32][32];
    int b = blockIdx.x;
    int tid = threadIdx.x;

    skey[tid] = (tid < n) ? score[b * n + tid] : -3.402823466e38f;
    sidx[tid] = tid;
    __syncthreads();

    for (int kk = 2; kk <= 1024; kk <<= 1) {
        for (int j = kk >> 1; j > 0; j >>= 1) {
            if (tid < 512) {
                int i = ((tid & ~(j - 1)) << 1) | (tid & (j - 1));
                int ixj = i | j;
                float ka = skey[i], kb = skey[ixj];
                int ia = sidx[i], ib = sidx[ixj];
                bool up = ((i & kk) == 0);
                bool sw = up ? ((ka < kb) || (ka == kb && ia > ib))
                             : ((ka > kb) || (ka == kb && ia < ib));
                if (sw) { skey[i] = kb; skey[ixj] = ka; sidx[i] = ib; sidx[ixj] = ia; }
            }
            __syncthreads();
        }
    }

    if (tid < k) inv[b * n + sidx[tid]] = b * k + tid;

    // pooled features + mean/max readout from sorted smem
    int w = tid >> 5, l = tid & 31;
    float4 sum = make_float4(0.f, 0.f, 0.f, 0.f);
    float4 mx  = make_float4(-3.402823466e38f, -3.402823466e38f, -3.402823466e38f, -3.402823466e38f);
    for (int j = w; j < k; j += 32) {
        int p = b * n + sidx[j];
        float v = skey[j];
        float4 hv = ((const float4*)(hc + (size_t)p * 128))[l];
        hv.x *= v; hv.y *= v; hv.z *= v; hv.w *= v;
        ((float4*)(h + (size_t)(b * k + j) * 128))[l] = hv;
        sum.x += hv.x; sum.y += hv.y; sum.z += hv.z; sum.w += hv.w;
        mx.x = fmaxf(mx.x, hv.x); mx.y = fmaxf(mx.y, hv.y);
        mx.z = fmaxf(mx.z, hv.z); mx.w = fmaxf(mx.w, hv.w);
    }
    ssum[w][l] = sum; smax[w][l] = mx;
    __syncthreads();
    if (w == 0) {
#pragma unroll
        for (int q = 1; q < 32; q++) {
            float4 s2 = ssum[q][l], m2 = smax[q][l];
            sum.x += s2.x; sum.y += s2.y; sum.z += s2.z; sum.w += s2.w;
            mx.x = fmaxf(mx.x, m2.x); mx.y = fmaxf(mx.y, m2.y);
            mx.z = fmaxf(mx.z, m2.z); mx.w = fmaxf(mx.w, m2.w);
        }
        float kin = (float)k;
        float* f1 = flats + b * 256 + l * 4;
        f1[0] += sum.x / kin; f1[1] += sum.y / kin; f1[2] += sum.z / kin; f1[3] += sum.w / kin;
        float* f2 = flats + b * 256 + 128 + l * 4;
        f2[0] += mx.x; f2[1] += mx.y; f2[2] += mx.z; f2[3] += mx.w;
    }
}

// remap + warp-aggregated compaction of surviving edges + next-layer degree counts
__global__ void remap_compact(const int* __restrict__ srcC, const int* __restrict__ dstC,
                              const float* __restrict__ weC, const int* __restrict__ inv,
                              const int* __restrict__ pcnt,
                              int* __restrict__ srcN, int* __restrict__ dstN,
                              float* __restrict__ weN, int* __restrict__ pcntN,
                              float* __restrict__ degN, int* __restrict__ indegN)
{
    int e = blockIdx.x * blockDim.x + threadIdx.x;
    int cnt = *pcnt;
    bool alive = false;
    int is = 0, id = 0; float w = 0.f;
    if (e < cnt) {
        w = weC[e];
        if (w > 0.f) {
            is = inv[srcC[e]];
            id = inv[dstC[e]];
            alive = (is >= 0) && (id >= 0);
        }
    }
    unsigned m = __ballot_sync(0xffffffffu, alive);
    if (m == 0) return;
    int lane = threadIdx.x & 31;
    int leader = __ffs(m) - 1;
    int base = 0;
    if (lane == leader) base = atomicAdd(pcntN, __popc(m));
    base = __shfl_sync(0xffffffffu, base, leader);
    if (alive) {
        int pos = base + __popc(m & ((1u << lane) - 1));
        srcN[pos] = is;
        dstN[pos] = id;
        weN[pos] = w;
        atomicAdd(&degN[id], w);
        atomicAdd(&indegN[id], 1);
    }
}

__global__ __launch_bounds__(512)
void mlp_kernel(const float* __restrict__ flats, const float* __restrict__ d1w,
                const float* __restrict__ d1b, const float* __restrict__ d2w,
                const float* __restrict__ d2b, float* __restrict__ out)
{
    __shared__ float f[256];
    __shared__ float hd[512];
    int b = blockIdx.x, t = threadIdx.x;
    if (t < 256) f[t] = flats[b * 256 + t];
    __syncthreads();
    float acc = d1b[t];
#pragma unroll 8
    for (int i = 0; i < 256; i++) acc = fmaf(f[i], d1w[i * 512 + t], acc);
    hd[t] = fmaxf(acc, 0.f);
    __syncthreads();
    if (t < CC) {
        float o = d2b[t];
#pragma unroll 8
        for (int i = 0; i < 512; i++) o = fmaf(hd[i], d2w[i * CC + t], o);
        out[b * CC + t] = o;
    }
}

// ---------------- host launcher ----------------
extern "C" void kernel_launch(void* const* d_in, const int* in_sizes, int n_in,
                              void* d_out, int out_size)
{
    const float* x       = (const float*)d_in[0];
    const int*   ei      = (const int*)d_in[1];
    const float* ew      = (const float*)d_in[3];
    const float* conv1_w = (const float*)d_in[4];
    const float* conv_w  = (const float*)d_in[5];
    const float* conv_b  = (const float*)d_in[6];
    const float* bn_g    = (const float*)d_in[7];
    const float* bn_be   = (const float*)d_in[8];
    const float* bn_m    = (const float*)d_in[9];
    const float* bn_v    = (const float*)d_in[10];
    const float* pool_w  = (const float*)d_in[11];
    const float* d1w     = (const float*)d_in[12];
    const float* d1b     = (const float*)d_in[13];
    const float* d2w     = (const float*)d_in[14];
    const float* d2b     = (const float*)d_in[15];
    int E = in_sizes[3];

    float *h, *xw, *hc, *score, *ecoef, *flats;
    float *deg[2], *weE[2];
    int *rowptr, *esrc, *flags, *nE;
    int *indeg[2], *cursor[2], *inv[2], *srcE[2], *dstE[2];
    cudaGetSymbolAddress((void**)&h,      g_h);
    cudaGetSymbolAddress((void**)&xw,     g_xw);
    cudaGetSymbolAddress((void**)&hc,     g_hc);
    cudaGetSymbolAddress((void**)&score,  g_score);
    cudaGetSymbolAddress((void**)&rowptr, g_rowptr);
    cudaGetSymbolAddress((void**)&esrc,   g_esrc);
    cudaGetSymbolAddress((void**)&ecoef,  g_ecoef);
    cudaGetSymbolAddress((void**)&flats,  g_flats);
    cudaGetSymbolAddress((void**)&flags,  g_flags);
    cudaGetSymbolAddress((void**)&nE,     g_nE);
    {
        float* p; int* q;
        cudaGetSymbolAddress((void**)&p, g_deg);    deg[0] = p;  deg[1] = p + NMAX;
        cudaGetSymbolAddress((void**)&q, g_indeg);  indeg[0]  = q; indeg[1]  = q + NMAX;
        cudaGetSymbolAddress((void**)&q, g_cursor); cursor[0] = q; cursor[1] = q + NMAX;
        cudaGetSymbolAddress((void**)&q, g_inv);    inv[0]    = q; inv[1]    = q + NMAX;
        cudaGetSymbolAddress((void**)&q, g_srcE);   srcE[0]   = q; srcE[1]   = q + EMAX;
        cudaGetSymbolAddress((void**)&q, g_dstE);   dstE[0]   = q; dstE[1]   = q + EMAX;
        cudaGetSymbolAddress((void**)&p, g_weE);    weE[0]    = p; weE[1]    = p + EMAX;
    }

    const int ns[6] = {1000, 800, 640, 512, 410, 328};
    const int ks[6] = {800, 640, 512, 410, 328, 263};
    int eb = (E + 255) / 256;

    init_kernel<<<eb, 256>>>(ei, ew, srcE[0], dstE[0], weE[0], flats, flags,
                             deg[0], indeg[0], cursor[0], inv[0], nE, E, BB * ns[0]);
    count0_kernel<<<eb, 256>>>(dstE[0], weE[0], deg[0], indeg[0], E);

    for (int i = 0; i < 6; i++) {
        int n = ns[i], k = ks[i], N = BB * n;
        int cur = i & 1, nxt = cur ^ 1;
        int Nnext = (i < 5) ? BB * k : 0;
        int nch = (N + 1023) >> 10;
        int mmB = N / 64;

        scan_fused<<<nch, 1024>>>(indeg[cur], deg[cur], rowptr, flags + i * 64,
                                  deg[nxt], indeg[nxt], cursor[nxt], inv[nxt], N, Nnext);

        if (i == 0)
            mm_scatter<64><<<mmB + eb, 256>>>(x, conv1_w, xw, mmB,
                srcE[cur], dstE[cur], weE[cur], deg[cur], rowptr, cursor[cur],
                esrc, ecoef, nE + i);
        else
            mm_scatter<128><<<mmB + eb, 256>>>(h, conv_w + (size_t)(i - 1) * 128 * 128, xw, mmB,
                srcE[cur], dstE[cur], weE[cur], deg[cur], rowptr, cursor[cur],
                esrc, ecoef, nE + i);

        gcn_gather<<<N / 8, 256>>>(xw, rowptr, esrc, ecoef, deg[cur],
                                   conv_b + i * 128, bn_g + i * 128, bn_be + i * 128,
                                   bn_m + i * 128, bn_v + i * 128, pool_w + i * 128,
                                   hc, score, N);

        topk_pool<<<BB, 1024>>>(score, hc, h, flats, inv[cur], n, k);

        if (i < 5)
            remap_compact<<<eb, 256>>>(srcE[cur], dstE[cur], weE[cur], inv[cur], nE + i,
                                       srcE[nxt], dstE[nxt], weE[nxt], nE + i + 1,
                                       deg[nxt], indeg[nxt]);
    }

    mlp_kernel<<<BB, 512>>>(flats, d1w, d1b, d2w, d2b, (float*)d_out);
}

// round 4
// speedup vs baseline: 1.2799x; 1.0686x over previous
#include <cuda_runtime.h>
#include <cuda_bf16.h>
#include <math.h>

#define BB 64
#define HD 128
#define CC 10
#define NMAX (BB*1000)          // 64000
#define EMAX (BB*1000*16)       // 1024000

typedef unsigned long long ull;

// ---------------- scratch (device globals; no allocation) ----------------
__device__ float g_h[NMAX*HD];
__device__ float g_xw[NMAX*HD];
__device__ float g_hc[NMAX*HD];
__device__ float g_wk[6*64*256];        // [layer][k2][col] -> (W[2k2][c], W[2k2+1][c])
__device__ float g_deg[2][NMAX];        // becomes dinv in place per layer
__device__ int   g_indeg[2][NMAX];
__device__ int   g_cursor[2][NMAX];
__device__ int   g_inv[2][NMAX];
__device__ float g_score[NMAX];
__device__ int   g_srcE[2][EMAX];
__device__ int   g_dstE[2][EMAX];
__device__ float g_weE[2][EMAX];
__device__ int   g_rowptr[NMAX+1];
__device__ int   g_esrc[EMAX];
__device__ float g_ecoef[EMAX];
__device__ float g_flats[BB*2*HD];
__device__ int   g_flags[6*64];
__device__ int   g_nE[8];

// ---------------- helpers ----------------
__device__ __forceinline__ void ffma2(ull& c, ull a, ull b) {
    asm("fma.rn.f32x2 %0, %1, %2, %0;" : "+l"(c) : "l"(a), "l"(b));
}
__device__ __forceinline__ float2 unpack2(ull v) {
    float2 f; asm("mov.b64 {%0, %1}, %2;" : "=f"(f.x), "=f"(f.y) : "l"(v)); return f;
}
__device__ __forceinline__ unsigned smem_u32(const void* p) {
    return (unsigned)__cvta_generic_to_shared(p);
}
#define CPA16(dst, src) asm volatile("cp.async.ca.shared.global [%0], [%1], 16;" :: "r"(dst), "l"(src))

// ---------------- kernels ----------------

// pre-pair W into [k2][col] (even-k, odd-k) layout, per layer
__global__ void wk_transpose(const float* __restrict__ w1, const float* __restrict__ w5)
{
    int idx = blockIdx.x * 256 + threadIdx.x;
    if (idx >= 6 * 64 * 128) return;
    int l  = idx >> 13;
    int k2 = (idx >> 7) & 63;
    int c  = idx & 127;
    float a = 0.f, b = 0.f;
    if (l == 0) {
        if (k2 < 32) { a = w1[(2 * k2) * 128 + c]; b = w1[(2 * k2 + 1) * 128 + c]; }
    } else {
        const float* W = w5 + (size_t)(l - 1) * 16384;
        a = W[(2 * k2) * 128 + c]; b = W[(2 * k2 + 1) * 128 + c];
    }
    g_wk[l * 16384 + k2 * 256 + c * 2]     = a;
    g_wk[l * 16384 + k2 * 256 + c * 2 + 1] = b;
}

__global__ void init_kernel(const int* __restrict__ ei, const float* __restrict__ ew,
                            int* __restrict__ src, int* __restrict__ dst, float* __restrict__ we,
                            float* __restrict__ flats, int* __restrict__ flags,
                            float* __restrict__ deg0, int* __restrict__ indeg0,
                            int* __restrict__ cursor0, int* __restrict__ inv0,
                            int* __restrict__ nE, int E, int N0)
{
    int i = blockIdx.x * blockDim.x + threadIdx.x;
    if (i < E) { src[i] = ei[i]; dst[i] = ei[E + i]; we[i] = ew[i]; }
    if (i < BB * 2 * HD) flats[i] = 0.f;
    if (i < 6 * 64) flags[i] = 0;
    if (i < 8) nE[i] = (i == 0) ? E : 0;
    if (i < N0) { deg0[i] = 1.0f; indeg0[i] = 0; cursor0[i] = 0; inv0[i] = -1; }
}

__global__ void count0_kernel(const int* __restrict__ dst, const float* __restrict__ we,
                              float* __restrict__ deg, int* __restrict__ indeg, int E)
{
    int e = blockIdx.x * blockDim.x + threadIdx.x;
    if (e >= E) return;
    float w = we[e];
    if (w > 0.f) {
        int d = dst[e];
        atomicAdd(&deg[d], w);
        atomicAdd(&indeg[d], 1);
    }
}

// one-kernel decoupled scan + dinv + init of next-layer node buffers
__global__ __launch_bounds__(1024)
void scan_fused(const int* __restrict__ indeg, float* __restrict__ dinv,
                int* __restrict__ rowptr, int* __restrict__ flags,
                float* __restrict__ degN, int* __restrict__ indegN,
                int* __restrict__ cursorN, int* __restrict__ invN,
                int N, int Nnext)
{
    __shared__ int sd[1024];
    __shared__ int wred[32];
    __shared__ int s_prefix, s_tot;
    int tid = threadIdx.x, bid = blockIdx.x;
    int i = bid * 1024 + tid;
    int v = (i < N) ? indeg[i] : 0;

    int ws = v;
#pragma unroll
    for (int o = 16; o; o >>= 1) ws += __shfl_xor_sync(0xffffffffu, ws, o);
    if ((tid & 31) == 0) wred[tid >> 5] = ws;
    if (tid == 0) s_prefix = 0;
    __syncthreads();
    if (tid == 0) {
        int tot = 0;
#pragma unroll
        for (int q = 0; q < 32; q++) tot += wred[q];
        s_tot = tot;
        atomicExch(&flags[bid], tot + 1);   // publish early
    }
    if (tid < bid) {
        volatile int* fp = flags + tid;
        int f;
        while ((f = *fp) == 0) {}
        atomicAdd(&s_prefix, f - 1);
    }
    sd[tid] = v;
    for (int off = 1; off < 1024; off <<= 1) {
        __syncthreads();
        int t = (tid >= off) ? sd[tid - off] : 0;
        __syncthreads();
        sd[tid] += t;
    }
    __syncthreads();
    int prefix = s_prefix;
    if (i < N) {
        rowptr[i] = prefix + sd[tid] - v;
        dinv[i] = rsqrtf(dinv[i]);          // deg -> dinv in place
    }
    if (tid == 0 && bid == gridDim.x - 1) rowptr[N] = prefix + s_tot;
    if (i < Nnext) { degN[i] = 1.0f; indegN[i] = 0; cursorN[i] = 0; invN[i] = -1; }
}

// merged: blocks [0, mmB) do the GEMM (cp.async double-buffered, packed f32x2);
// blocks [mmB, ...) do the CSR edge scatter — independent work, overlapped.
template<int HIN>
__global__ __launch_bounds__(256, 2)
void mm_scatter(const float* __restrict__ A, const float* __restrict__ wk,
                float* __restrict__ out, int mmB,
                const int* __restrict__ srcC, const int* __restrict__ dstC,
                const float* __restrict__ weC, const float* __restrict__ dinv,
                const int* __restrict__ rowptr, int* __restrict__ cursor,
                int* __restrict__ esrc, float* __restrict__ ecoef,
                const int* __restrict__ pcnt)
{
    extern __shared__ float sm[];
    float* As  = sm;            // [2][64*32]
    float* Wks = sm + 4096;     // [2][16*128*2]

    if (blockIdx.x >= mmB) {
        int e = (blockIdx.x - mmB) * 256 + threadIdx.x;
        int cnt = *pcnt;
        if (e >= cnt) return;
        float w = weC[e];
        if (w <= 0.f) return;
        int s = srcC[e], d = dstC[e];
        int pos = rowptr[d] + atomicAdd(&cursor[d], 1);
        esrc[pos] = s;
        ecoef[pos] = dinv[s] * dinv[d] * w;
        return;
    }

    const int NCH = HIN / 32;
    int tid = threadIdx.x;
    int tx = tid & 31, ty = tid >> 5;
    int rowBase = blockIdx.x * 64;

    ull acc[8][4];
#pragma unroll
    for (int r = 0; r < 8; r++)
#pragma unroll
        for (int j = 0; j < 4; j++) acc[r][j] = 0ull;

    // async load of chunk kc into buffer buf
    auto load_chunk = [&](int kc, int buf) {
#pragma unroll
        for (int q = 0; q < 2; q++) {           // A tile 64x32 (8 KB)
            int idx = tid + q * 256;
            int r = idx >> 3, c4 = idx & 7;
            unsigned d = smem_u32(&As[buf * 2048 + r * 32 + c4 * 4]);
            CPA16(d, A + (size_t)(rowBase + r) * HIN + kc * 32 + c4 * 4);
        }
#pragma unroll
        for (int q = 0; q < 4; q++) {           // W tile 16 k2-rows x 128 ull (16 KB, contiguous)
            int idx = tid + q * 256;
            unsigned d = smem_u32(&Wks[buf * 4096 + idx * 4]);
            CPA16(d, wk + kc * 4096 + idx * 4);
        }
    };

    load_chunk(0, 0);
    asm volatile("cp.async.commit_group;");

#pragma unroll
    for (int kc = 0; kc < NCH; kc++) {
        if (kc + 1 < NCH) {
            load_chunk(kc + 1, (kc + 1) & 1);
            asm volatile("cp.async.commit_group;");
            asm volatile("cp.async.wait_group 1;");
        } else {
            asm volatile("cp.async.wait_group 0;");
        }
        __syncthreads();
        const float* Ab = As  + (kc & 1) * 2048;
        const float* Wb = Wks + (kc & 1) * 4096;
#pragma unroll
        for (int k2 = 0; k2 < 16; k2++) {
            ull w2[4];
#pragma unroll
            for (int j = 0; j < 4; j++)
                w2[j] = *(const ull*)&Wb[(k2 * 128 + tx + 32 * j) * 2];
#pragma unroll
            for (int r = 0; r < 8; r++) {
                ull h2 = *(const ull*)&Ab[(ty + 8 * r) * 32 + 2 * k2];
#pragma unroll
                for (int j = 0; j < 4; j++) ffma2(acc[r][j], h2, w2[j]);
            }
        }
        __syncthreads();
    }
#pragma unroll
    for (int r = 0; r < 8; r++) {
        int row = rowBase + ty + 8 * r;
#pragma unroll
        for (int j = 0; j < 4; j++) {
            float2 v = unpack2(acc[r][j]);
            out[(size_t)row * 128 + tx + 32 * j] = v.x + v.y;
        }
    }
}

__global__ void gcn_gather(const float* __restrict__ xw, const int* __restrict__ rowptr,
                           const int* __restrict__ esrc, const float* __restrict__ ecoef,
                           const float* __restrict__ dinv,
                           const float* __restrict__ bias, const float* __restrict__ bng,
                           const float* __restrict__ bnb, const float* __restrict__ bnm,
                           const float* __restrict__ bnv, const float* __restrict__ pw,
                           float* __restrict__ hc, float* __restrict__ score, int N)
{
    int n = (blockIdx.x * blockDim.x + threadIdx.x) >> 5;
    int l = threadIdx.x & 31;
    if (n >= N) return;
    float di = dinv[n];
    float sc = di * di;
    float4 a = ((const float4*)(xw + (size_t)n * 128))[l];
    float4 acc = make_float4(a.x * sc, a.y * sc, a.z * sc, a.w * sc);
    float4 acc2 = make_float4(0.f, 0.f, 0.f, 0.f);
    int e0 = rowptr[n], e1 = rowptr[n + 1];
    int e = e0;
    for (; e + 2 <= e1; e += 2) {
        int s0 = esrc[e],     s1 = esrc[e + 1];
        float c0 = ecoef[e],  c1 = ecoef[e + 1];
        float4 v0 = ((const float4*)(xw + (size_t)s0 * 128))[l];
        float4 v1 = ((const float4*)(xw + (size_t)s1 * 128))[l];
        acc.x  = fmaf(c0, v0.x, acc.x);   acc.y  = fmaf(c0, v0.y, acc.y);
        acc.z  = fmaf(c0, v0.z, acc.z);   acc.w  = fmaf(c0, v0.w, acc.w);
        acc2.x = fmaf(c1, v1.x, acc2.x);  acc2.y = fmaf(c1, v1.y, acc2.y);
        acc2.z = fmaf(c1, v1.z, acc2.z);  acc2.w = fmaf(c1, v1.w, acc2.w);
    }
    if (e < e1) {
        int s = esrc[e];
        float c = ecoef[e];
        float4 v = ((const float4*)(xw + (size_t)s * 128))[l];
        acc.x = fmaf(c, v.x, acc.x);
        acc.y = fmaf(c, v.y, acc.y);
        acc.z = fmaf(c, v.z, acc.z);
        acc.w = fmaf(c, v.w, acc.w);
    }
    acc.x += acc2.x; acc.y += acc2.y; acc.z += acc2.z; acc.w += acc2.w;
    float4 bb = ((const float4*)bias)[l];
    float4 g  = ((const float4*)bng)[l];
    float4 be = ((const float4*)bnb)[l];
    float4 m  = ((const float4*)bnm)[l];
    float4 vv = ((const float4*)bnv)[l];
    float4 o;
    o.x = fmaxf((acc.x + bb.x - m.x) * (g.x * rsqrtf(vv.x + 1e-5f)) + be.x, 0.f);
    o.y = fmaxf((acc.y + bb.y - m.y) * (g.y * rsqrtf(vv.y + 1e-5f)) + be.y, 0.f);
    o.z = fmaxf((acc.z + bb.z - m.z) * (g.z * rsqrtf(vv.z + 1e-5f)) + be.z, 0.f);
    o.w = fmaxf((acc.w + bb.w - m.w) * (g.w * rsqrtf(vv.w + 1e-5f)) + be.w, 0.f);
    ((float4*)(hc + (size_t)n * 128))[l] = o;
    float4 p = ((const float4*)pw)[l];
    float dot = o.x * p.x + o.y * p.y + o.z * p.z + o.w * p.w;
    float p2  = p.x * p.x + p.y * p.y + p.z * p.z + p.w * p.w;
#pragma unroll
    for (int off = 16; off; off >>= 1) {
        dot += __shfl_xor_sync(0xffffffffu, dot, off);
        p2  += __shfl_xor_sync(0xffffffffu, p2, off);
    }
    if (l == 0) score[n] = tanhf(dot * rsqrtf(p2));
}

// fused: bitonic full sort (1024 threads) + pooled h + flats
__global__ __launch_bounds__(1024)
void topk_pool(const float* __restrict__ score, const float* __restrict__ hc,
               float* __restrict__ h, float* __restrict__ flats,
               int* __restrict__ inv, int n, int k)
{
    __shared__ float skey[1024];
    __shared__ int   sidx[1024];
    __shared__ float4 ssum[32][32];
    __shared__ float4 smax[32][32];
    int b = blockIdx.x;
    int tid = threadIdx.x;

    skey[tid] = (tid < n) ? score[b * n + tid] : -3.402823466e38f;
    sidx[tid] = tid;
    __syncthreads();

    for (int kk = 2; kk <= 1024; kk <<= 1) {
        for (int j = kk >> 1; j > 0; j >>= 1) {
            if (tid < 512) {
                int i = ((tid & ~(j - 1)) << 1) | (tid & (j - 1));
                int ixj = i | j;
                float ka = skey[i], kb = skey[ixj];
                int ia = sidx[i], ib = sidx[ixj];
                bool up = ((i & kk) == 0);
                bool sw = up ? ((ka < kb) || (ka == kb && ia > ib))
                             : ((ka > kb) || (ka == kb && ia < ib));
                if (sw) { skey[i] = kb; skey[ixj] = ka; sidx[i] = ib; sidx[ixj] = ia; }
            }
            __syncthreads();
        }
    }

    if (tid < k) inv[b * n + sidx[tid]] = b * k + tid;

    int w = tid >> 5, l = tid & 31;
    float4 sum = make_float4(0.f, 0.f, 0.f, 0.f);
    float4 mx  = make_float4(-3.402823466e38f, -3.402823466e38f, -3.402823466e38f, -3.402823466e38f);
    for (int j = w; j < k; j += 32) {
        int p = b * n + sidx[j];
        float v = skey[j];
        float4 hv = ((const float4*)(hc + (size_t)p * 128))[l];
        hv.x *= v; hv.y *= v; hv.z *= v; hv.w *= v;
        ((float4*)(h + (size_t)(b * k + j) * 128))[l] = hv;
        sum.x += hv.x; sum.y += hv.y; sum.z += hv.z; sum.w += hv.w;
        mx.x = fmaxf(mx.x, hv.x); mx.y = fmaxf(mx.y, hv.y);
        mx.z = fmaxf(mx.z, hv.z); mx.w = fmaxf(mx.w, hv.w);
    }
    ssum[w][l] = sum; smax[w][l] = mx;
    __syncthreads();
    if (w == 0) {
#pragma unroll
        for (int q = 1; q < 32; q++) {
            float4 s2 = ssum[q][l], m2 = smax[q][l];
            sum.x += s2.x; sum.y += s2.y; sum.z += s2.z; sum.w += s2.w;
            mx.x = fmaxf(mx.x, m2.x); mx.y = fmaxf(mx.y, m2.y);
            mx.z = fmaxf(mx.z, m2.z); mx.w = fmaxf(mx.w, m2.w);
        }
        float kin = (float)k;
        float* f1 = flats + b * 256 + l * 4;
        f1[0] += sum.x / kin; f1[1] += sum.y / kin; f1[2] += sum.z / kin; f1[3] += sum.w / kin;
        float* f2 = flats + b * 256 + 128 + l * 4;
        f2[0] += mx.x; f2[1] += mx.y; f2[2] += mx.z; f2[3] += mx.w;
    }
}

// remap + warp-aggregated compaction of surviving edges + next-layer degree counts
__global__ void remap_compact(const int* __restrict__ srcC, const int* __restrict__ dstC,
                              const float* __restrict__ weC, const int* __restrict__ inv,
                              const int* __restrict__ pcnt,
                              int* __restrict__ srcN, int* __restrict__ dstN,
                              float* __restrict__ weN, int* __restrict__ pcntN,
                              float* __restrict__ degN, int* __restrict__ indegN)
{
    int e = blockIdx.x * blockDim.x + threadIdx.x;
    int cnt = *pcnt;
    bool alive = false;
    int is = 0, id = 0; float w = 0.f;
    if (e < cnt) {
        w = weC[e];
        if (w > 0.f) {
            is = inv[srcC[e]];
            id = inv[dstC[e]];
            alive = (is >= 0) && (id >= 0);
        }
    }
    unsigned m = __ballot_sync(0xffffffffu, alive);
    if (m == 0) return;
    int lane = threadIdx.x & 31;
    int leader = __ffs(m) - 1;
    int base = 0;
    if (lane == leader) base = atomicAdd(pcntN, __popc(m));
    base = __shfl_sync(0xffffffffu, base, leader);
    if (alive) {
        int pos = base + __popc(m & ((1u << lane) - 1));
        srcN[pos] = is;
        dstN[pos] = id;
        weN[pos] = w;
        atomicAdd(&degN[id], w);
        atomicAdd(&indegN[id], 1);
    }
}

__global__ __launch_bounds__(512)
void mlp_kernel(const float* __restrict__ flats, const float* __restrict__ d1w,
                const float* __restrict__ d1b, const float* __restrict__ d2w,
                const float* __restrict__ d2b, float* __restrict__ out)
{
    __shared__ float f[256];
    __shared__ float hd[512];
    int b = blockIdx.x, t = threadIdx.x;
    if (t < 256) f[t] = flats[b * 256 + t];
    __syncthreads();
    float acc = d1b[t];
#pragma unroll 8
    for (int i = 0; i < 256; i++) acc = fmaf(f[i], d1w[i * 512 + t], acc);
    hd[t] = fmaxf(acc, 0.f);
    __syncthreads();
    if (t < CC) {
        float o = d2b[t];
#pragma unroll 8
        for (int i = 0; i < 512; i++) o = fmaf(hd[i], d2w[i * CC + t], o);
        out[b * CC + t] = o;
    }
}

// ---------------- host launcher ----------------
extern "C" void kernel_launch(void* const* d_in, const int* in_sizes, int n_in,
                              void* d_out, int out_size)
{
    const float* x       = (const float*)d_in[0];
    const int*   ei      = (const int*)d_in[1];
    const float* ew      = (const float*)d_in[3];
    const float* conv1_w = (const float*)d_in[4];
    const float* conv_w  = (const float*)d_in[5];
    const float* conv_b  = (const float*)d_in[6];
    const float* bn_g    = (const float*)d_in[7];
    const float* bn_be   = (const float*)d_in[8];
    const float* bn_m    = (const float*)d_in[9];
    const float* bn_v    = (const float*)d_in[10];
    const float* pool_w  = (const float*)d_in[11];
    const float* d1w     = (const float*)d_in[12];
    const float* d1b     = (const float*)d_in[13];
    const float* d2w     = (const float*)d_in[14];
    const float* d2b     = (const float*)d_in[15];
    int E = in_sizes[3];

    float *h, *xw, *hc, *score, *ecoef, *flats, *wk;
    float *deg[2], *weE[2];
    int *rowptr, *esrc, *flags, *nE;
    int *indeg[2], *cursor[2], *inv[2], *srcE[2], *dstE[2];
    cudaGetSymbolAddress((void**)&h,      g_h);
    cudaGetSymbolAddress((void**)&xw,     g_xw);
    cudaGetSymbolAddress((void**)&hc,     g_hc);
    cudaGetSymbolAddress((void**)&score,  g_score);
    cudaGetSymbolAddress((void**)&rowptr, g_rowptr);
    cudaGetSymbolAddress((void**)&esrc,   g_esrc);
    cudaGetSymbolAddress((void**)&ecoef,  g_ecoef);
    cudaGetSymbolAddress((void**)&flats,  g_flats);
    cudaGetSymbolAddress((void**)&flags,  g_flags);
    cudaGetSymbolAddress((void**)&nE,     g_nE);
    cudaGetSymbolAddress((void**)&wk,     g_wk);
    {
        float* p; int* q;
        cudaGetSymbolAddress((void**)&p, g_deg);    deg[0] = p;  deg[1] = p + NMAX;
        cudaGetSymbolAddress((void**)&q, g_indeg);  indeg[0]  = q; indeg[1]  = q + NMAX;
        cudaGetSymbolAddress((void**)&q, g_cursor); cursor[0] = q; cursor[1] = q + NMAX;
        cudaGetSymbolAddress((void**)&q, g_inv);    inv[0]    = q; inv[1]    = q + NMAX;
        cudaGetSymbolAddress((void**)&q, g_srcE);   srcE[0]   = q; srcE[1]   = q + EMAX;
        cudaGetSymbolAddress((void**)&q, g_dstE);   dstE[0]   = q; dstE[1]   = q + EMAX;
        cudaGetSymbolAddress((void**)&p, g_weE);    weE[0]    = p; weE[1]    = p + EMAX;
    }

    const int ns[6] = {1000, 800, 640, 512, 410, 328};
    const int ks[6] = {800, 640, 512, 410, 328, 263};
    // generous upper bounds on surviving edge counts (expected 0.64^i, sigma ~500)
    const double ubf[6] = {1.0, 0.75, 0.56, 0.42, 0.31, 0.24};
    int eb = (E + 255) / 256;
    const int SMEM_MM = (2 * 2048 + 2 * 4096) * 4;   // 49152

    cudaFuncSetAttribute(mm_scatter<64>,  cudaFuncAttributeMaxDynamicSharedMemorySize, SMEM_MM);
    cudaFuncSetAttribute(mm_scatter<128>, cudaFuncAttributeMaxDynamicSharedMemorySize, SMEM_MM);

    wk_transpose<<<(6 * 64 * 128 + 255) / 256, 256>>>(conv1_w, conv_w);
    init_kernel<<<eb, 256>>>(ei, ew, srcE[0], dstE[0], weE[0], flats, flags,
                             deg[0], indeg[0], cursor[0], inv[0], nE, E, BB * ns[0]);
    count0_kernel<<<eb, 256>>>(dstE[0], weE[0], deg[0], indeg[0], E);

    for (int i = 0; i < 6; i++) {
        int n = ns[i], k = ks[i], N = BB * n;
        int cur = i & 1, nxt = cur ^ 1;
        int Nnext = (i < 5) ? BB * k : 0;
        int nch = (N + 1023) >> 10;
        int mmB = N / 64;
        int ubi = (int)((double)E * ubf[i]) + 256;
        int scB = (ubi + 255) / 256;

        scan_fused<<<nch, 1024>>>(indeg[cur], deg[cur], rowptr, flags + i * 64,
                                  deg[nxt], indeg[nxt], cursor[nxt], inv[nxt], N, Nnext);

        if (i == 0)
            mm_scatter<64><<<mmB + scB, 256, SMEM_MM>>>(x, wk, xw, mmB,
                srcE[cur], dstE[cur], weE[cur], deg[cur], rowptr, cursor[cur],
                esrc, ecoef, nE + i);
        else
            mm_scatter<128><<<mmB + scB, 256, SMEM_MM>>>(h, wk + (size_t)i * 16384, xw, mmB,
                srcE[cur], dstE[cur], weE[cur], deg[cur], rowptr, cursor[cur],
                esrc, ecoef, nE + i);

        gcn_gather<<<N / 8, 256>>>(xw, rowptr, esrc, ecoef, deg[cur],
                                   conv_b + i * 128, bn_g + i * 128, bn_be + i * 128,
                                   bn_m + i * 128, bn_v + i * 128, pool_w + i * 128,
                                   hc, score, N);

        topk_pool<<<BB, 1024>>>(score, hc, h, flats, inv[cur], n, k);

        if (i < 5)
            remap_compact<<<scB, 256>>>(srcE[cur], dstE[cur], weE[cur], inv[cur], nE + i,
                                        srcE[nxt], dstE[nxt], weE[nxt], nE + i + 1,
                                        deg[nxt], indeg[nxt]);
    }

    mlp_kernel<<<BB, 512>>>(flats, d1w, d1b, d2w, d2b, (float*)d_out);
}

// round 6
// speedup vs baseline: 1.3980x; 1.0923x over previous
#include <cuda_runtime.h>
#include <cuda_bf16.h>
#include <math.h>

#define BB 64
#define HD 128
#define CC 10
#define NMAX (BB*1000)          // 64000
#define EMAX (BB*1000*16)       // 1024000

typedef unsigned long long ull;
typedef __nv_bfloat16 bf16;

// ---------------- scratch (device globals; no allocation) ----------------
__device__ float g_xw[NMAX*HD];
__device__ float g_hc[NMAX*HD];
__device__ __align__(16) bf16 g_hhi[NMAX*HD];
__device__ __align__(16) bf16 g_hlo[NMAX*HD];
__device__ __align__(16) bf16 g_xhi[NMAX*64];
__device__ __align__(16) bf16 g_xlo[NMAX*64];
__device__ __align__(16) bf16 g_whi[6*128*128];   // per layer: [n][k] K-major
__device__ __align__(16) bf16 g_wlo[6*128*128];
__device__ float g_deg[2][NMAX];        // becomes dinv in place per layer
__device__ int   g_indeg[2][NMAX];
__device__ int   g_cursor[2][NMAX];
__device__ int   g_inv[2][NMAX];
__device__ float g_score[NMAX];
__device__ int   g_srcE[2][EMAX];
__device__ int   g_dstE[2][EMAX];
__device__ float g_weE[2][EMAX];
__device__ int   g_rowptr[NMAX+1];
__device__ int   g_esrc[EMAX];
__device__ float g_ecoef[EMAX];
__device__ float g_flats[BB*2*HD];
__device__ int   g_flags[6*64];
__device__ int   g_nE[8];

// ---------------- helpers ----------------
__device__ __forceinline__ unsigned smem_u32(const void* p) {
    return (unsigned)__cvta_generic_to_shared(p);
}
#define CPA16(dst, src) asm volatile("cp.async.ca.shared.global [%0], [%1], 16;" :: "r"(dst), "l"(src))

#define LDSM4(r, addr) \
    asm volatile("ldmatrix.sync.aligned.m8n8.x4.shared.b16 {%0,%1,%2,%3}, [%4];" \
        : "=r"((r)[0]), "=r"((r)[1]), "=r"((r)[2]), "=r"((r)[3]) : "r"(addr))

#define MMA16816(c, a, b0, b1) \
    asm volatile("mma.sync.aligned.m16n8k16.row.col.f32.bf16.bf16.f32 " \
        "{%0,%1,%2,%3},{%4,%5,%6,%7},{%8,%9},{%0,%1,%2,%3};" \
        : "+f"((c)[0]), "+f"((c)[1]), "+f"((c)[2]), "+f"((c)[3]) \
        : "r"((a)[0]), "r"((a)[1]), "r"((a)[2]), "r"((a)[3]), "r"(b0), "r"(b1))

__device__ __forceinline__ ull pack4bf(bf16 a0, bf16 a1, bf16 a2, bf16 a3) {
    return (ull)__bfloat16_as_ushort(a0) | ((ull)__bfloat16_as_ushort(a1) << 16)
         | ((ull)__bfloat16_as_ushort(a2) << 32) | ((ull)__bfloat16_as_ushort(a3) << 48);
}

// ---------------- kernels ----------------

// split W into bf16 hi/lo, transposed to [n][k] K-major per layer
__global__ void w_prep(const float* __restrict__ w1, const float* __restrict__ w5,
                       bf16* __restrict__ whi, bf16* __restrict__ wlo)
{
    int idx = blockIdx.x * 256 + threadIdx.x;
    if (idx >= 6 * 16384) return;
    int l = idx >> 14, r = idx & 16383;
    float v; int dst;
    if (l == 0) {
        if (r >= 128 * 64) return;
        int n = r >> 6, kk = r & 63;
        v = w1[kk * 128 + n];
        dst = n * 64 + kk;
    } else {
        int n = r >> 7, kk = r & 127;
        v = w5[(size_t)(l - 1) * 16384 + kk * 128 + n];
        dst = l * 16384 + n * 128 + kk;
    }
    bf16 hi = __float2bfloat16(v);
    whi[dst] = hi;
    wlo[dst] = __float2bfloat16(v - __bfloat162float(hi));
}

__global__ void x_prep(const float* __restrict__ x,
                       bf16* __restrict__ xhi, bf16* __restrict__ xlo, int n)
{
    int i = blockIdx.x * 256 + threadIdx.x;
    if (i >= n) return;
    float v = x[i];
    bf16 hi = __float2bfloat16(v);
    xhi[i] = hi;
    xlo[i] = __float2bfloat16(v - __bfloat162float(hi));
}

__global__ void init_kernel(const int* __restrict__ ei, const float* __restrict__ ew,
                            int* __restrict__ src, int* __restrict__ dst, float* __restrict__ we,
                            float* __restrict__ flats, int* __restrict__ flags,
                            float* __restrict__ deg0, int* __restrict__ indeg0,
                            int* __restrict__ cursor0, int* __restrict__ inv0,
                            int* __restrict__ nE, int E, int N0)
{
    int i = blockIdx.x * blockDim.x + threadIdx.x;
    if (i < E) { src[i] = ei[i]; dst[i] = ei[E + i]; we[i] = ew[i]; }
    if (i < BB * 2 * HD) flats[i] = 0.f;
    if (i < 6 * 64) flags[i] = 0;
    if (i < 8) nE[i] = (i == 0) ? E : 0;
    if (i < N0) { deg0[i] = 1.0f; indeg0[i] = 0; cursor0[i] = 0; inv0[i] = -1; }
}

__global__ void count0_kernel(const int* __restrict__ dst, const float* __restrict__ we,
                              float* __restrict__ deg, int* __restrict__ indeg, int E)
{
    int e = blockIdx.x * blockDim.x + threadIdx.x;
    if (e >= E) return;
    float w = we[e];
    if (w > 0.f) {
        int d = dst[e];
        atomicAdd(&deg[d], w);
        atomicAdd(&indeg[d], 1);
    }
}

// one-kernel decoupled scan + dinv + init of next-layer node buffers
__global__ __launch_bounds__(1024)
void scan_fused(const int* __restrict__ indeg, float* __restrict__ dinv,
                int* __restrict__ rowptr, int* __restrict__ flags,
                float* __restrict__ degN, int* __restrict__ indegN,
                int* __restrict__ cursorN, int* __restrict__ invN,
                int N, int Nnext)
{
    __shared__ int sd[1024];
    __shared__ int wred[32];
    __shared__ int s_prefix, s_tot;
    int tid = threadIdx.x, bid = blockIdx.x;
    int i = bid * 1024 + tid;
    int v = (i < N) ? indeg[i] : 0;

    int ws = v;
#pragma unroll
    for (int o = 16; o; o >>= 1) ws += __shfl_xor_sync(0xffffffffu, ws, o);
    if ((tid & 31) == 0) wred[tid >> 5] = ws;
    if (tid == 0) s_prefix = 0;
    __syncthreads();
    if (tid == 0) {
        int tot = 0;
#pragma unroll
        for (int q = 0; q < 32; q++) tot += wred[q];
        s_tot = tot;
        atomicExch(&flags[bid], tot + 1);   // publish early
    }
    if (tid < bid) {
        volatile int* fp = flags + tid;
        int f;
        while ((f = *fp) == 0) {}
        atomicAdd(&s_prefix, f - 1);
    }
    sd[tid] = v;
    for (int off = 1; off < 1024; off <<= 1) {
        __syncthreads();
        int t = (tid >= off) ? sd[tid - off] : 0;
        __syncthreads();
        sd[tid] += t;
    }
    __syncthreads();
    int prefix = s_prefix;
    if (i < N) {
        rowptr[i] = prefix + sd[tid] - v;
        dinv[i] = rsqrtf(dinv[i]);          // deg -> dinv in place
    }
    if (tid == 0 && bid == gridDim.x - 1) rowptr[N] = prefix + s_tot;
    if (i < Nnext) { degN[i] = 1.0f; indegN[i] = 0; cursorN[i] = 0; invN[i] = -1; }
}

__global__ void edge_scatter(const int* __restrict__ srcC, const int* __restrict__ dstC,
                             const float* __restrict__ weC, const float* __restrict__ dinv,
                             const int* __restrict__ rowptr, int* __restrict__ cursor,
                             int* __restrict__ esrc, float* __restrict__ ecoef,
                             const int* __restrict__ pcnt)
{
    int e = blockIdx.x * blockDim.x + threadIdx.x;
    int cnt = *pcnt;
    if (e >= cnt) return;
    float w = weC[e];
    if (w <= 0.f) return;
    int s = srcC[e], d = dstC[e];
    int pos = rowptr[d] + atomicAdd(&cursor[d], 1);
    esrc[pos] = s;
    ecoef[pos] = dinv[s] * dinv[d] * w;
}

// bf16 split-GEMM via mma.sync (HMMA): D = Ahi*Whi + Ahi*Wlo + Alo*Whi (fp32 accum)
// A: [M, K] bf16 row-major. W: [128, K] bf16 row-major ([n][k] — B operand col-major).
// Tile: 128x128 per block, 8 warps each 32 rows x 64 cols.
template<int K>
__global__ __launch_bounds__(256)
void gemm_bf16(const bf16* __restrict__ Ahi, const bf16* __restrict__ Alo,
               const bf16* __restrict__ Whi, const bf16* __restrict__ Wlo,
               float* __restrict__ out)
{
    extern __shared__ __align__(128) char sm[];
    const unsigned smb = smem_u32(sm);
    constexpr int CH = K / 8;                   // 16B chunks per row
    constexpr int TILEB = 128 * K * 2;          // bytes per matrix tile
    constexpr unsigned OFF_A = 0;               // Ahi, then Alo at +TILEB
    constexpr unsigned OFF_W = 2 * TILEB;       // Whi, then Wlo at +TILEB

    int tid = threadIdx.x;
    int wid = tid >> 5, lane = tid & 31;
    int rowBase = blockIdx.x * 128;

    // cp.async fill: 4 matrices, XOR-swizzled 16B chunks (chunk c of row r at c^(r&7))
    const bf16* gsrc[4] = { Ahi + (size_t)rowBase * K, Alo + (size_t)rowBase * K, Whi, Wlo };
    const unsigned soff[4] = { OFF_A, OFF_A + TILEB, OFF_W, OFF_W + TILEB };
#pragma unroll
    for (int m = 0; m < 4; m++) {
#pragma unroll
        for (int c = tid; c < 128 * CH; c += 256) {
            int r = c / CH, cc = c % CH;
            CPA16(smb + soff[m] + (unsigned)((r * CH + (cc ^ (r & 7))) * 16),
                  gsrc[m] + (size_t)r * K + cc * 8);
        }
    }
    asm volatile("cp.async.commit_group;");
    asm volatile("cp.async.wait_group 0;");
    __syncthreads();

    int mi = wid & 3, ni = wid >> 2;
    int mbase = mi * 32, nbase = ni * 64;

    float acc[2][8][4];
#pragma unroll
    for (int t = 0; t < 2; t++)
#pragma unroll
        for (int f = 0; f < 8; f++)
#pragma unroll
            for (int j = 0; j < 4; j++) acc[t][f][j] = 0.f;

    // precomputed ldmatrix lane-address components
    int rowA0 = mbase + (lane & 15);                       // + t*16
    int rowW0 = nbase + (lane & 7) + ((lane >> 4) << 3);   // + u*16
    int kselA = (lane >> 4) & 1;
    int kselW = (lane >> 3) & 1;

#pragma unroll
    for (int s = 0; s < K / 16; s++) {
        unsigned aHi[2][4], aLo[2][4];
#pragma unroll
        for (int t = 0; t < 2; t++) {
            int row = rowA0 + t * 16;
            unsigned addr = smb + OFF_A + (unsigned)((row * CH + ((2 * s + kselA) ^ (row & 7))) * 16);
            LDSM4(aHi[t], addr);
            LDSM4(aLo[t], addr + TILEB);
        }
#pragma unroll
        for (int u = 0; u < 4; u++) {
            int row = rowW0 + u * 16;
            unsigned addr = smb + OFF_W + (unsigned)((row * CH + ((2 * s + kselW) ^ (row & 7))) * 16);
            unsigned bHi[4], bLo[4];
            LDSM4(bHi, addr);
            LDSM4(bLo, addr + TILEB);
#pragma unroll
            for (int t = 0; t < 2; t++) {
                MMA16816(acc[t][2 * u],     aHi[t], bHi[0], bHi[1]);
                MMA16816(acc[t][2 * u + 1], aHi[t], bHi[2], bHi[3]);
                MMA16816(acc[t][2 * u],     aHi[t], bLo[0], bLo[1]);
                MMA16816(acc[t][2 * u + 1], aHi[t], bLo[2], bLo[3]);
                MMA16816(acc[t][2 * u],     aLo[t], bHi[0], bHi[1]);
                MMA16816(acc[t][2 * u + 1], aLo[t], bHi[2], bHi[3]);
            }
        }
    }

    // epilogue: C fragment (g = lane>>2, tg = lane&3): rows g, g+8; cols tg*2, tg*2+1
    int g = lane >> 2, tg = lane & 3;
#pragma unroll
    for (int t = 0; t < 2; t++) {
        int row0 = rowBase + mbase + t * 16 + g;
#pragma unroll
        for (int f = 0; f < 8; f++) {
            int col = nbase + f * 8 + tg * 2;
            *(float2*)(out + (size_t)row0 * 128 + col) = make_float2(acc[t][f][0], acc[t][f][1]);
            *(float2*)(out + (size_t)(row0 + 8) * 128 + col) = make_float2(acc[t][f][2], acc[t][f][3]);
        }
    }
}

__global__ void gcn_gather(const float* __restrict__ xw, const int* __restrict__ rowptr,
                           const int* __restrict__ esrc, const float* __restrict__ ecoef,
                           const float* __restrict__ dinv,
                           const float* __restrict__ bias, const float* __restrict__ bng,
                           const float* __restrict__ bnb, const float* __restrict__ bnm,
                           const float* __restrict__ bnv, const float* __restrict__ pw,
                           float* __restrict__ hc, float* __restrict__ score, int N)
{
    int n = (blockIdx.x * blockDim.x + threadIdx.x) >> 5;
    int l = threadIdx.x & 31;
    if (n >= N) return;
    float di = dinv[n];
    float sc = di * di;
    float4 a = ((const float4*)(xw + (size_t)n * 128))[l];
    float4 acc = make_float4(a.x * sc, a.y * sc, a.z * sc, a.w * sc);
    float4 acc2 = make_float4(0.f, 0.f, 0.f, 0.f);
    int e0 = rowptr[n], e1 = rowptr[n + 1];
    int e = e0;
    for (; e + 2 <= e1; e += 2) {
        int s0 = esrc[e],     s1 = esrc[e + 1];
        float c0 = ecoef[e],  c1 = ecoef[e + 1];
        float4 v0 = ((const float4*)(xw + (size_t)s0 * 128))[l];
        float4 v1 = ((const float4*)(xw + (size_t)s1 * 128))[l];
        acc.x  = fmaf(c0, v0.x, acc.x);   acc.y  = fmaf(c0, v0.y, acc.y);
        acc.z  = fmaf(c0, v0.z, acc.z);   acc.w  = fmaf(c0, v0.w, acc.w);
        acc2.x = fmaf(c1, v1.x, acc2.x);  acc2.y = fmaf(c1, v1.y, acc2.y);
        acc2.z = fmaf(c1, v1.z, acc2.z);  acc2.w = fmaf(c1, v1.w, acc2.w);
    }
    if (e < e1) {
        int s = esrc[e];
        float c = ecoef[e];
        float4 v = ((const float4*)(xw + (size_t)s * 128))[l];
        acc.x = fmaf(c, v.x, acc.x);
        acc.y = fmaf(c, v.y, acc.y);
        acc.z = fmaf(c, v.z, acc.z);
        acc.w = fmaf(c, v.w, acc.w);
    }
    acc.x += acc2.x; acc.y += acc2.y; acc.z += acc2.z; acc.w += acc2.w;
    float4 bb = ((const float4*)bias)[l];
    float4 g  = ((const float4*)bng)[l];
    float4 be = ((const float4*)bnb)[l];
    float4 m  = ((const float4*)bnm)[l];
    float4 vv = ((const float4*)bnv)[l];
    float4 o;
    o.x = fmaxf((acc.x + bb.x - m.x) * (g.x * rsqrtf(vv.x + 1e-5f)) + be.x, 0.f);
    o.y = fmaxf((acc.y + bb.y - m.y) * (g.y * rsqrtf(vv.y + 1e-5f)) + be.y, 0.f);
    o.z = fmaxf((acc.z + bb.z - m.z) * (g.z * rsqrtf(vv.z + 1e-5f)) + be.z, 0.f);
    o.w = fmaxf((acc.w + bb.w - m.w) * (g.w * rsqrtf(vv.w + 1e-5f)) + be.w, 0.f);
    ((float4*)(hc + (size_t)n * 128))[l] = o;
    float4 p = ((const float4*)pw)[l];
    float dot = o.x * p.x + o.y * p.y + o.z * p.z + o.w * p.w;
    float p2  = p.x * p.x + p.y * p.y + p.z * p.z + p.w * p.w;
#pragma unroll
    for (int off = 16; off; off >>= 1) {
        dot += __shfl_xor_sync(0xffffffffu, dot, off);
        p2  += __shfl_xor_sync(0xffffffffu, p2, off);
    }
    if (l == 0) score[n] = tanhf(dot * rsqrtf(p2));
}

// fused: bitonic full sort (1024 threads) + pooled h (bf16 hi/lo split) + flats
__global__ __launch_bounds__(1024)
void topk_pool(const float* __restrict__ score, const float* __restrict__ hc,
               bf16* __restrict__ hhi, bf16* __restrict__ hlo,
               float* __restrict__ flats, int* __restrict__ inv, int n, int k)
{
    __shared__ float skey[1024];
    __shared__ int   sidx[1024];
    __shared__ float4 ssum[32][32];
    __shared__ float4 smax[32][32];
    int b = blockIdx.x;
    int tid = threadIdx.x;

    skey[tid] = (tid < n) ? score[b * n + tid] : -3.402823466e38f;
    sidx[tid] = tid;
    __syncthreads();

    for (int kk = 2; kk <= 1024; kk <<= 1) {
        for (int j = kk >> 1; j > 0; j >>= 1) {
            if (tid < 512) {
                int i = ((tid & ~(j - 1)) << 1) | (tid & (j - 1));
                int ixj = i | j;
                float ka = skey[i], kb = skey[ixj];
                int ia = sidx[i], ib = sidx[ixj];
                bool up = ((i & kk) == 0);
                bool sw = up ? ((ka < kb) || (ka == kb && ia > ib))
                             : ((ka > kb) || (ka == kb && ia < ib));
                if (sw) { skey[i] = kb; skey[ixj] = ka; sidx[i] = ib; sidx[ixj] = ia; }
            }
            __syncthreads();
        }
    }

    if (tid < k) inv[b * n + sidx[tid]] = b * k + tid;

    int w = tid >> 5, l = tid & 31;
    float4 sum = make_float4(0.f, 0.f, 0.f, 0.f);
    float4 mx  = make_float4(-3.402823466e38f, -3.402823466e38f, -3.402823466e38f, -3.402823466e38f);
    for (int j = w; j < k; j += 32) {
        int p = b * n + sidx[j];
        float v = skey[j];
        float4 hv = ((const float4*)(hc + (size_t)p * 128))[l];
        hv.x *= v; hv.y *= v; hv.z *= v; hv.w *= v;
        bf16 a0 = __float2bfloat16(hv.x), a1 = __float2bfloat16(hv.y);
        bf16 a2 = __float2bfloat16(hv.z), a3 = __float2bfloat16(hv.w);
        bf16 b0 = __float2bfloat16(hv.x - __bfloat162float(a0));
        bf16 b1 = __float2bfloat16(hv.y - __bfloat162float(a1));
        bf16 b2 = __float2bfloat16(hv.z - __bfloat162float(a2));
        bf16 b3 = __float2bfloat16(hv.w - __bfloat162float(a3));
        size_t rbase = (size_t)(b * k + j) * 128 + l * 4;
        *(ull*)(hhi + rbase) = pack4bf(a0, a1, a2, a3);
        *(ull*)(hlo + rbase) = pack4bf(b0, b1, b2, b3);
        sum.x += hv.x; sum.y += hv.y; sum.z += hv.z; sum.w += hv.w;
        mx.x = fmaxf(mx.x, hv.x); mx.y = fmaxf(mx.y, hv.y);
        mx.z = fmaxf(mx.z, hv.z); mx.w = fmaxf(mx.w, hv.w);
    }
    ssum[w][l] = sum; smax[w][l] = mx;
    __syncthreads();
    if (w == 0) {
#pragma unroll
        for (int q = 1; q < 32; q++) {
            float4 s2 = ssum[q][l], m2 = smax[q][l];
            sum.x += s2.x; sum.y += s2.y; sum.z += s2.z; sum.w += s2.w;
            mx.x = fmaxf(mx.x, m2.x); mx.y = fmaxf(mx.y, m2.y);
            mx.z = fmaxf(mx.z, m2.z); mx.w = fmaxf(mx.w, m2.w);
        }
        float kin = (float)k;
        float* f1 = flats + b * 256 + l * 4;
        f1[0] += sum.x / kin; f1[1] += sum.y / kin; f1[2] += sum.z / kin; f1[3] += sum.w / kin;
        float* f2 = flats + b * 256 + 128 + l * 4;
        f2[0] += mx.x; f2[1] += mx.y; f2[2] += mx.z; f2[3] += mx.w;
    }
}

// remap + warp-aggregated compaction of surviving edges + next-layer degree counts
__global__ void remap_compact(const int* __restrict__ srcC, const int* __restrict__ dstC,
                              const float* __restrict__ weC, const int* __restrict__ inv,
                              const int* __restrict__ pcnt,
                              int* __restrict__ srcN, int* __restrict__ dstN,
                              float* __restrict__ weN, int* __restrict__ pcntN,
                              float* __restrict__ degN, int* __restrict__ indegN)
{
    int e = blockIdx.x * blockDim.x + threadIdx.x;
    int cnt = *pcnt;
    bool alive = false;
    int is = 0, id = 0; float w = 0.f;
    if (e < cnt) {
        w = weC[e];
        if (w > 0.f) {
            is = inv[srcC[e]];
            id = inv[dstC[e]];
            alive = (is >= 0) && (id >= 0);
        }
    }
    unsigned m = __ballot_sync(0xffffffffu, alive);
    if (m == 0) return;
    int lane = threadIdx.x & 31;
    int leader = __ffs(m) - 1;
    int base = 0;
    if (lane == leader) base = atomicAdd(pcntN, __popc(m));
    base = __shfl_sync(0xffffffffu, base, leader);
    if (alive) {
        int pos = base + __popc(m & ((1u << lane) - 1));
        srcN[pos] = is;
        dstN[pos] = id;
        weN[pos] = w;
        atomicAdd(&degN[id], w);
        atomicAdd(&indegN[id], 1);
    }
}

__global__ __launch_bounds__(512)
void mlp_kernel(const float* __restrict__ flats, const float* __restrict__ d1w,
                const float* __restrict__ d1b, const float* __restrict__ d2w,
                const float* __restrict__ d2b, float* __restrict__ out)
{
    __shared__ float f[256];
    __shared__ float hd[512];
    int b = blockIdx.x, t = threadIdx.x;
    if (t < 256) f[t] = flats[b * 256 + t];
    __syncthreads();
    float acc = d1b[t];
#pragma unroll 8
    for (int i = 0; i < 256; i++) acc = fmaf(f[i], d1w[i * 512 + t], acc);
    hd[t] = fmaxf(acc, 0.f);
    __syncthreads();
    if (t < CC) {
        float o = d2b[t];
#pragma unroll 8
        for (int i = 0; i < 512; i++) o = fmaf(hd[i], d2w[i * CC + t], o);
        out[b * CC + t] = o;
    }
}

// ---------------- host launcher ----------------
extern "C" void kernel_launch(void* const* d_in, const int* in_sizes, int n_in,
                              void* d_out, int out_size)
{
    const float* x       = (const float*)d_in[0];
    const int*   ei      = (const int*)d_in[1];
    const float* ew      = (const float*)d_in[3];
    const float* conv1_w = (const float*)d_in[4];
    const float* conv_w  = (const float*)d_in[5];
    const float* conv_b  = (const float*)d_in[6];
    const float* bn_g    = (const float*)d_in[7];
    const float* bn_be   = (const float*)d_in[8];
    const float* bn_m    = (const float*)d_in[9];
    const float* bn_v    = (const float*)d_in[10];
    const float* pool_w  = (const float*)d_in[11];
    const float* d1w     = (const float*)d_in[12];
    const float* d1b     = (const float*)d_in[13];
    const float* d2w     = (const float*)d_in[14];
    const float* d2b     = (const float*)d_in[15];
    int E = in_sizes[3];

    float *xw, *hc, *score, *ecoef, *flats;
    float *deg[2], *weE[2];
    int *rowptr, *esrc, *flags, *nE;
    int *indeg[2], *cursor[2], *inv[2], *srcE[2], *dstE[2];
    bf16 *xhi, *xlo, *hhi, *hlo, *whi, *wlo;
    cudaGetSymbolAddress((void**)&xw,     g_xw);
    cudaGetSymbolAddress((void**)&hc,     g_hc);
    cudaGetSymbolAddress((void**)&score,  g_score);
    cudaGetSymbolAddress((void**)&rowptr, g_rowptr);
    cudaGetSymbolAddress((void**)&esrc,   g_esrc);
    cudaGetSymbolAddress((void**)&ecoef,  g_ecoef);
    cudaGetSymbolAddress((void**)&flats,  g_flats);
    cudaGetSymbolAddress((void**)&flags,  g_flags);
    cudaGetSymbolAddress((void**)&nE,     g_nE);
    cudaGetSymbolAddress((void**)&xhi,    g_xhi);
    cudaGetSymbolAddress((void**)&xlo,    g_xlo);
    cudaGetSymbolAddress((void**)&hhi,    g_hhi);
    cudaGetSymbolAddress((void**)&hlo,    g_hlo);
    cudaGetSymbolAddress((void**)&whi,    g_whi);
    cudaGetSymbolAddress((void**)&wlo,    g_wlo);
    {
        float* p; int* q;
        cudaGetSymbolAddress((void**)&p, g_deg);    deg[0] = p;  deg[1] = p + NMAX;
        cudaGetSymbolAddress((void**)&q, g_indeg);  indeg[0]  = q; indeg[1]  = q + NMAX;
        cudaGetSymbolAddress((void**)&q, g_cursor); cursor[0] = q; cursor[1] = q + NMAX;
        cudaGetSymbolAddress((void**)&q, g_inv);    inv[0]    = q; inv[1]    = q + NMAX;
        cudaGetSymbolAddress((void**)&q, g_srcE);   srcE[0]   = q; srcE[1]   = q + EMAX;
        cudaGetSymbolAddress((void**)&q, g_dstE);   dstE[0]   = q; dstE[1]   = q + EMAX;
        cudaGetSymbolAddress((void**)&p, g_weE);    weE[0]    = p; weE[1]    = p + EMAX;
    }

    const int ns[6] = {1000, 800, 640, 512, 410, 328};
    const int ks[6] = {800, 640, 512, 410, 328, 263};
    const double ubf[6] = {1.0, 0.75, 0.56, 0.42, 0.31, 0.24};
    int eb = (E + 255) / 256;
    const int SMEM_G64  = 4 * 128 * 64 * 2;    // 65536
    const int SMEM_G128 = 4 * 128 * 128 * 2;   // 131072

    cudaFuncSetAttribute(gemm_bf16<64>,  cudaFuncAttributeMaxDynamicSharedMemorySize, SMEM_G64);
    cudaFuncSetAttribute(gemm_bf16<128>, cudaFuncAttributeMaxDynamicSharedMemorySize, SMEM_G128);

    w_prep<<<(6 * 16384 + 255) / 256, 256>>>(conv1_w, conv_w, whi, wlo);
    x_prep<<<(NMAX * 64 + 255) / 256, 256>>>(x, xhi, xlo, NMAX * 64);
    init_kernel<<<eb, 256>>>(ei, ew, srcE[0], dstE[0], weE[0], flats, flags,
                             deg[0], indeg[0], cursor[0], inv[0], nE, E, BB * ns[0]);
    count0_kernel<<<eb, 256>>>(dstE[0], weE[0], deg[0], indeg[0], E);

    for (int i = 0; i < 6; i++) {
        int n = ns[i], k = ks[i], N = BB * n;
        int cur = i & 1, nxt = cur ^ 1;
        int Nnext = (i < 5) ? BB * k : 0;
        int nch = (N + 1023) >> 10;
        int ubi = (int)((double)E * ubf[i]) + 256;
        int scB = (ubi + 255) / 256;

        scan_fused<<<nch, 1024>>>(indeg[cur], deg[cur], rowptr, flags + i * 64,
                                  deg[nxt], indeg[nxt], cursor[nxt], inv[nxt], N, Nnext);

        edge_scatter<<<scB, 256>>>(srcE[cur], dstE[cur], weE[cur], deg[cur],
                                   rowptr, cursor[cur], esrc, ecoef, nE + i);

        if (i == 0)
            gemm_bf16<64><<<N / 128, 256, SMEM_G64>>>(xhi, xlo, whi, wlo, xw);
        else
            gemm_bf16<128><<<N / 128, 256, SMEM_G128>>>(hhi, hlo,
                whi + (size_t)i * 16384, wlo + (size_t)i * 16384, xw);

        gcn_gather<<<N / 8, 256>>>(xw, rowptr, esrc, ecoef, deg[cur],
                                   conv_b + i * 128, bn_g + i * 128, bn_be + i * 128,
                                   bn_m + i * 128, bn_v + i * 128, pool_w + i * 128,
                                   hc, score, N);

        topk_pool<<<BB, 1024>>>(score, hc, hhi, hlo, flats, inv[cur], n, k);

        if (i < 5)
            remap_compact<<<scB, 256>>>(srcE[cur], dstE[cur], weE[cur], inv[cur], nE + i,
                                        srcE[nxt], dstE[nxt], weE[nxt], nE + i + 1,
                                        deg[nxt], indeg[nxt]);
    }

    mlp_kernel<<<BB, 512>>>(flats, d1w, d1b, d2w, d2b, (float*)d_out);
}

// round 7
// speedup vs baseline: 1.4947x; 1.0692x over previous
#include <cuda_runtime.h>
#include <cuda_bf16.h>
#include <math.h>

#define BB 64
#define HD 128
#define CC 10
#define NMAX (BB*1000)          // 64000
#define EMAX (BB*1000*16)       // 1024000

typedef unsigned long long ull;
typedef __nv_bfloat16 bf16;

// ---------------- scratch (device globals; no allocation) ----------------
__device__ float g_xw[NMAX*HD];
__device__ float g_hc[NMAX*HD];
__device__ __align__(16) bf16 g_hhi[NMAX*HD];
__device__ __align__(16) bf16 g_hlo[NMAX*HD];
__device__ __align__(16) bf16 g_xhi[NMAX*64];
__device__ __align__(16) bf16 g_xlo[NMAX*64];
__device__ __align__(16) bf16 g_whi[6*128*128];   // per layer: [n][k] K-major
__device__ __align__(16) bf16 g_wlo[6*128*128];
__device__ float g_deg[2][NMAX];        // becomes dinv in place per layer
__device__ int   g_indeg[2][NMAX];
__device__ int   g_cursor[2][NMAX];
__device__ int   g_inv[2][NMAX];
__device__ float g_score[NMAX];
__device__ int   g_srcE[2][EMAX];
__device__ int   g_dstE[2][EMAX];
__device__ float g_weE[2][EMAX];
__device__ int   g_rowptr[NMAX+1];
__device__ int   g_esrc[EMAX];
__device__ float g_ecoef[EMAX];
__device__ float g_flats[BB*2*HD];
__device__ int   g_flags[6*64];
__device__ int   g_nE[8];

// ---------------- helpers ----------------
__device__ __forceinline__ unsigned smem_u32(const void* p) {
    return (unsigned)__cvta_generic_to_shared(p);
}
#define CPA16(dst, src) asm volatile("cp.async.ca.shared.global [%0], [%1], 16;" :: "r"(dst), "l"(src))

#define LDSM4(r, addr) \
    asm volatile("ldmatrix.sync.aligned.m8n8.x4.shared.b16 {%0,%1,%2,%3}, [%4];" \
        : "=r"((r)[0]), "=r"((r)[1]), "=r"((r)[2]), "=r"((r)[3]) : "r"(addr))

#define MMA16816(c, a, b0, b1) \
    asm volatile("mma.sync.aligned.m16n8k16.row.col.f32.bf16.bf16.f32 " \
        "{%0,%1,%2,%3},{%4,%5,%6,%7},{%8,%9},{%0,%1,%2,%3};" \
        : "+f"((c)[0]), "+f"((c)[1]), "+f"((c)[2]), "+f"((c)[3]) \
        : "r"((a)[0]), "r"((a)[1]), "r"((a)[2]), "r"((a)[3]), "r"(b0), "r"(b1))

__device__ __forceinline__ ull pack4bf(bf16 a0, bf16 a1, bf16 a2, bf16 a3) {
    return (ull)__bfloat16_as_ushort(a0) | ((ull)__bfloat16_as_ushort(a1) << 16)
         | ((ull)__bfloat16_as_ushort(a2) << 32) | ((ull)__bfloat16_as_ushort(a3) << 48);
}

// ---------------- kernels ----------------

// split W into bf16 hi/lo, transposed to [n][k] K-major per layer
__global__ void w_prep(const float* __restrict__ w1, const float* __restrict__ w5,
                       bf16* __restrict__ whi, bf16* __restrict__ wlo)
{
    int idx = blockIdx.x * 256 + threadIdx.x;
    if (idx >= 6 * 16384) return;
    int l = idx >> 14, r = idx & 16383;
    float v; int dst;
    if (l == 0) {
        if (r >= 128 * 64) return;
        int n = r >> 6, kk = r & 63;
        v = w1[kk * 128 + n];
        dst = n * 64 + kk;
    } else {
        int n = r >> 7, kk = r & 127;
        v = w5[(size_t)(l - 1) * 16384 + kk * 128 + n];
        dst = l * 16384 + n * 128 + kk;
    }
    bf16 hi = __float2bfloat16(v);
    whi[dst] = hi;
    wlo[dst] = __float2bfloat16(v - __bfloat162float(hi));
}

__global__ void x_prep(const float* __restrict__ x,
                       bf16* __restrict__ xhi, bf16* __restrict__ xlo, int n)
{
    int i = blockIdx.x * 256 + threadIdx.x;
    if (i >= n) return;
    float v = x[i];
    bf16 hi = __float2bfloat16(v);
    xhi[i] = hi;
    xlo[i] = __float2bfloat16(v - __bfloat162float(hi));
}

__global__ void init_kernel(const int* __restrict__ ei, const float* __restrict__ ew,
                            int* __restrict__ src, int* __restrict__ dst, float* __restrict__ we,
                            float* __restrict__ flats, int* __restrict__ flags,
                            float* __restrict__ deg0, int* __restrict__ indeg0,
                            int* __restrict__ cursor0, int* __restrict__ inv0,
                            int* __restrict__ nE, int E, int N0)
{
    int i = blockIdx.x * blockDim.x + threadIdx.x;
    if (i < E) { src[i] = ei[i]; dst[i] = ei[E + i]; we[i] = ew[i]; }
    if (i < BB * 2 * HD) flats[i] = 0.f;
    if (i < 6 * 64) flags[i] = 0;
    if (i < 8) nE[i] = (i == 0) ? E : 0;
    if (i < N0) { deg0[i] = 1.0f; indeg0[i] = 0; cursor0[i] = 0; inv0[i] = -1; }
}

__global__ void count0_kernel(const int* __restrict__ dst, const float* __restrict__ we,
                              float* __restrict__ deg, int* __restrict__ indeg, int E)
{
    int e = blockIdx.x * blockDim.x + threadIdx.x;
    if (e >= E) return;
    float w = we[e];
    if (w > 0.f) {
        int d = dst[e];
        atomicAdd(&deg[d], w);
        atomicAdd(&indeg[d], 1);
    }
}

// one-kernel decoupled scan + dinv + init of next-layer node buffers
// warp-shuffle scan (3 barriers) instead of Hillis-Steele (20 barriers)
__global__ __launch_bounds__(1024)
void scan_fused(const int* __restrict__ indeg, float* __restrict__ dinv,
                int* __restrict__ rowptr, int* __restrict__ flags,
                float* __restrict__ degN, int* __restrict__ indegN,
                int* __restrict__ cursorN, int* __restrict__ invN,
                int N, int Nnext)
{
    __shared__ int wsum[32];
    __shared__ int woff[32];
    __shared__ int s_prefix, s_tot;
    int tid = threadIdx.x, bid = blockIdx.x;
    int lane = tid & 31, wid = tid >> 5;
    int i = bid * 1024 + tid;
    int v = (i < N) ? indeg[i] : 0;

    int incl = v;
#pragma unroll
    for (int o = 1; o < 32; o <<= 1) {
        int t = __shfl_up_sync(0xffffffffu, incl, o);
        if (lane >= o) incl += t;
    }
    if (lane == 31) wsum[wid] = incl;
    if (tid == 0) s_prefix = 0;
    __syncthreads();
    if (wid == 0) {
        int s = wsum[lane];
        int si = s;
#pragma unroll
        for (int o = 1; o < 32; o <<= 1) {
            int t = __shfl_up_sync(0xffffffffu, si, o);
            if (lane >= o) si += t;
        }
        woff[lane] = si - s;
        if (lane == 31) { s_tot = si; atomicExch(&flags[bid], si + 1); }   // publish
    }
    __syncthreads();
    if (tid < bid) {
        volatile int* fp = flags + tid;
        int f;
        while ((f = *fp) == 0) {}
        atomicAdd(&s_prefix, f - 1);
    }
    __syncthreads();
    int prefix = s_prefix;
    if (i < N) {
        rowptr[i] = prefix + woff[wid] + incl - v;
        dinv[i] = rsqrtf(dinv[i]);          // deg -> dinv in place
    }
    if (tid == 0 && bid == gridDim.x - 1) rowptr[N] = prefix + s_tot;
    if (i < Nnext) { degN[i] = 1.0f; indegN[i] = 0; cursorN[i] = 0; invN[i] = -1; }
}

__global__ void edge_scatter(const int* __restrict__ srcC, const int* __restrict__ dstC,
                             const float* __restrict__ weC, const float* __restrict__ dinv,
                             const int* __restrict__ rowptr, int* __restrict__ cursor,
                             int* __restrict__ esrc, float* __restrict__ ecoef,
                             const int* __restrict__ pcnt)
{
    int e = blockIdx.x * blockDim.x + threadIdx.x;
    int cnt = *pcnt;
    if (e >= cnt) return;
    float w = weC[e];
    if (w <= 0.f) return;
    int s = srcC[e], d = dstC[e];
    int pos = rowptr[d] + atomicAdd(&cursor[d], 1);
    esrc[pos] = s;
    ecoef[pos] = dinv[s] * dinv[d] * w;
}

// bf16 split-GEMM via mma.sync (HMMA): D = Ahi*Whi + Ahi*Wlo + Alo*Whi (fp32 accum)
template<int K>
__global__ __launch_bounds__(256)
void gemm_bf16(const bf16* __restrict__ Ahi, const bf16* __restrict__ Alo,
               const bf16* __restrict__ Whi, const bf16* __restrict__ Wlo,
               float* __restrict__ out)
{
    extern __shared__ __align__(128) char sm[];
    const unsigned smb = smem_u32(sm);
    constexpr int CH = K / 8;
    constexpr int TILEB = 128 * K * 2;
    constexpr unsigned OFF_A = 0;
    constexpr unsigned OFF_W = 2 * TILEB;

    int tid = threadIdx.x;
    int wid = tid >> 5, lane = tid & 31;
    int rowBase = blockIdx.x * 128;

    const bf16* gsrc[4] = { Ahi + (size_t)rowBase * K, Alo + (size_t)rowBase * K, Whi, Wlo };
    const unsigned soff[4] = { OFF_A, OFF_A + TILEB, OFF_W, OFF_W + TILEB };
#pragma unroll
    for (int m = 0; m < 4; m++) {
#pragma unroll
        for (int c = tid; c < 128 * CH; c += 256) {
            int r = c / CH, cc = c % CH;
            CPA16(smb + soff[m] + (unsigned)((r * CH + (cc ^ (r & 7))) * 16),
                  gsrc[m] + (size_t)r * K + cc * 8);
        }
    }
    asm volatile("cp.async.commit_group;");
    asm volatile("cp.async.wait_group 0;");
    __syncthreads();

    int mi = wid & 3, ni = wid >> 2;
    int mbase = mi * 32, nbase = ni * 64;

    float acc[2][8][4];
#pragma unroll
    for (int t = 0; t < 2; t++)
#pragma unroll
        for (int f = 0; f < 8; f++)
#pragma unroll
            for (int j = 0; j < 4; j++) acc[t][f][j] = 0.f;

    int rowA0 = mbase + (lane & 15);
    int rowW0 = nbase + (lane & 7) + ((lane >> 4) << 3);
    int kselA = (lane >> 4) & 1;
    int kselW = (lane >> 3) & 1;

#pragma unroll
    for (int s = 0; s < K / 16; s++) {
        unsigned aHi[2][4], aLo[2][4];
#pragma unroll
        for (int t = 0; t < 2; t++) {
            int row = rowA0 + t * 16;
            unsigned addr = smb + OFF_A + (unsigned)((row * CH + ((2 * s + kselA) ^ (row & 7))) * 16);
            LDSM4(aHi[t], addr);
            LDSM4(aLo[t], addr + TILEB);
        }
#pragma unroll
        for (int u = 0; u < 4; u++) {
            int row = rowW0 + u * 16;
            unsigned addr = smb + OFF_W + (unsigned)((row * CH + ((2 * s + kselW) ^ (row & 7))) * 16);
            unsigned bHi[4], bLo[4];
            LDSM4(bHi, addr);
            LDSM4(bLo, addr + TILEB);
#pragma unroll
            for (int t = 0; t < 2; t++) {
                MMA16816(acc[t][2 * u],     aHi[t], bHi[0], bHi[1]);
                MMA16816(acc[t][2 * u + 1], aHi[t], bHi[2], bHi[3]);
                MMA16816(acc[t][2 * u],     aHi[t], bLo[0], bLo[1]);
                MMA16816(acc[t][2 * u + 1], aHi[t], bLo[2], bLo[3]);
                MMA16816(acc[t][2 * u],     aLo[t], bHi[0], bHi[1]);
                MMA16816(acc[t][2 * u + 1], aLo[t], bHi[2], bHi[3]);
            }
        }
    }

    int g = lane >> 2, tg = lane & 3;
#pragma unroll
    for (int t = 0; t < 2; t++) {
        int row0 = rowBase + mbase + t * 16 + g;
#pragma unroll
        for (int f = 0; f < 8; f++) {
            int col = nbase + f * 8 + tg * 2;
            *(float2*)(out + (size_t)row0 * 128 + col) = make_float2(acc[t][f][0], acc[t][f][1]);
            *(float2*)(out + (size_t)(row0 + 8) * 128 + col) = make_float2(acc[t][f][2], acc[t][f][3]);
        }
    }
}

__global__ void gcn_gather(const float* __restrict__ xw, const int* __restrict__ rowptr,
                           const int* __restrict__ esrc, const float* __restrict__ ecoef,
                           const float* __restrict__ dinv,
                           const float* __restrict__ bias, const float* __restrict__ bng,
                           const float* __restrict__ bnb, const float* __restrict__ bnm,
                           const float* __restrict__ bnv, const float* __restrict__ pw,
                           float* __restrict__ hc, float* __restrict__ score, int N)
{
    int n = (blockIdx.x * blockDim.x + threadIdx.x) >> 5;
    int l = threadIdx.x & 31;
    if (n >= N) return;
    float di = dinv[n];
    float sc = di * di;
    float4 a = ((const float4*)(xw + (size_t)n * 128))[l];
    float4 acc = make_float4(a.x * sc, a.y * sc, a.z * sc, a.w * sc);
    float4 acc2 = make_float4(0.f, 0.f, 0.f, 0.f);
    int e0 = rowptr[n], e1 = rowptr[n + 1];
    int e = e0;
    for (; e + 2 <= e1; e += 2) {
        int s0 = esrc[e],     s1 = esrc[e + 1];
        float c0 = ecoef[e],  c1 = ecoef[e + 1];
        float4 v0 = ((const float4*)(xw + (size_t)s0 * 128))[l];
        float4 v1 = ((const float4*)(xw + (size_t)s1 * 128))[l];
        acc.x  = fmaf(c0, v0.x, acc.x);   acc.y  = fmaf(c0, v0.y, acc.y);
        acc.z  = fmaf(c0, v0.z, acc.z);   acc.w  = fmaf(c0, v0.w, acc.w);
        acc2.x = fmaf(c1, v1.x, acc2.x);  acc2.y = fmaf(c1, v1.y, acc2.y);
        acc2.z = fmaf(c1, v1.z, acc2.z);  acc2.w = fmaf(c1, v1.w, acc2.w);
    }
    if (e < e1) {
        int s = esrc[e];
        float c = ecoef[e];
        float4 v = ((const float4*)(xw + (size_t)s * 128))[l];
        acc.x = fmaf(c, v.x, acc.x);
        acc.y = fmaf(c, v.y, acc.y);
        acc.z = fmaf(c, v.z, acc.z);
        acc.w = fmaf(c, v.w, acc.w);
    }
    acc.x += acc2.x; acc.y += acc2.y; acc.z += acc2.z; acc.w += acc2.w;
    float4 bb = ((const float4*)bias)[l];
    float4 g  = ((const float4*)bng)[l];
    float4 be = ((const float4*)bnb)[l];
    float4 m  = ((const float4*)bnm)[l];
    float4 vv = ((const float4*)bnv)[l];
    float4 o;
    o.x = fmaxf((acc.x + bb.x - m.x) * (g.x * rsqrtf(vv.x + 1e-5f)) + be.x, 0.f);
    o.y = fmaxf((acc.y + bb.y - m.y) * (g.y * rsqrtf(vv.y + 1e-5f)) + be.y, 0.f);
    o.z = fmaxf((acc.z + bb.z - m.z) * (g.z * rsqrtf(vv.z + 1e-5f)) + be.z, 0.f);
    o.w = fmaxf((acc.w + bb.w - m.w) * (g.w * rsqrtf(vv.w + 1e-5f)) + be.w, 0.f);
    ((float4*)(hc + (size_t)n * 128))[l] = o;
    float4 p = ((const float4*)pw)[l];
    float dot = o.x * p.x + o.y * p.y + o.z * p.z + o.w * p.w;
    float p2  = p.x * p.x + p.y * p.y + p.z * p.z + p.w * p.w;
#pragma unroll
    for (int off = 16; off; off >>= 1) {
        dot += __shfl_xor_sync(0xffffffffu, dot, off);
        p2  += __shfl_xor_sync(0xffffffffu, p2, off);
    }
    if (l == 0) score[n] = tanhf(dot * rsqrtf(p2));
}

// fused: bitonic full sort (1024 threads) + pooled h (bf16 hi/lo split) + flats
__global__ __launch_bounds__(1024)
void topk_pool(const float* __restrict__ score, const float* __restrict__ hc,
               bf16* __restrict__ hhi, bf16* __restrict__ hlo,
               float* __restrict__ flats, int* __restrict__ inv, int n, int k)
{
    __shared__ float skey[1024];
    __shared__ int   sidx[1024];
    __shared__ float4 ssum[32][32];
    __shared__ float4 smax[32][32];
    int b = blockIdx.x;
    int tid = threadIdx.x;

    skey[tid] = (tid < n) ? score[b * n + tid] : -3.402823466e38f;
    sidx[tid] = tid;
    __syncthreads();

    for (int kk = 2; kk <= 1024; kk <<= 1) {
        for (int j = kk >> 1; j > 0; j >>= 1) {
            if (tid < 512) {
                int i = ((tid & ~(j - 1)) << 1) | (tid & (j - 1));
                int ixj = i | j;
                float ka = skey[i], kb = skey[ixj];
                int ia = sidx[i], ib = sidx[ixj];
                bool up = ((i & kk) == 0);
                bool sw = up ? ((ka < kb) || (ka == kb && ia > ib))
                             : ((ka > kb) || (ka == kb && ia < ib));
                if (sw) { skey[i] = kb; skey[ixj] = ka; sidx[i] = ib; sidx[ixj] = ia; }
            }
            __syncthreads();
        }
    }

    if (tid < k) inv[b * n + sidx[tid]] = b * k + tid;

    int w = tid >> 5, l = tid & 31;
    float4 sum = make_float4(0.f, 0.f, 0.f, 0.f);
    float4 mx  = make_float4(-3.402823466e38f, -3.402823466e38f, -3.402823466e38f, -3.402823466e38f);
    for (int j = w; j < k; j += 32) {
        int p = b * n + sidx[j];
        float v = skey[j];
        float4 hv = ((const float4*)(hc + (size_t)p * 128))[l];
        hv.x *= v; hv.y *= v; hv.z *= v; hv.w *= v;
        bf16 a0 = __float2bfloat16(hv.x), a1 = __float2bfloat16(hv.y);
        bf16 a2 = __float2bfloat16(hv.z), a3 = __float2bfloat16(hv.w);
        bf16 b0 = __float2bfloat16(hv.x - __bfloat162float(a0));
        bf16 b1 = __float2bfloat16(hv.y - __bfloat162float(a1));
        bf16 b2 = __float2bfloat16(hv.z - __bfloat162float(a2));
        bf16 b3 = __float2bfloat16(hv.w - __bfloat162float(a3));
        size_t rbase = (size_t)(b * k + j) * 128 + l * 4;
        *(ull*)(hhi + rbase) = pack4bf(a0, a1, a2, a3);
        *(ull*)(hlo + rbase) = pack4bf(b0, b1, b2, b3);
        sum.x += hv.x; sum.y += hv.y; sum.z += hv.z; sum.w += hv.w;
        mx.x = fmaxf(mx.x, hv.x); mx.y = fmaxf(mx.y, hv.y);
        mx.z = fmaxf(mx.z, hv.z); mx.w = fmaxf(mx.w, hv.w);
    }
    ssum[w][l] = sum; smax[w][l] = mx;
    __syncthreads();
    if (w == 0) {
#pragma unroll
        for (int q = 1; q < 32; q++) {
            float4 s2 = ssum[q][l], m2 = smax[q][l];
            sum.x += s2.x; sum.y += s2.y; sum.z += s2.z; sum.w += s2.w;
            mx.x = fmaxf(mx.x, m2.x); mx.y = fmaxf(mx.y, m2.y);
            mx.z = fmaxf(mx.z, m2.z); mx.w = fmaxf(mx.w, m2.w);
        }
        float kin = (float)k;
        float* f1 = flats + b * 256 + l * 4;
        f1[0] += sum.x / kin; f1[1] += sum.y / kin; f1[2] += sum.z / kin; f1[3] += sum.w / kin;
        float* f2 = flats + b * 256 + 128 + l * 4;
        f2[0] += mx.x; f2[1] += mx.y; f2[2] += mx.z; f2[3] += mx.w;
    }
}

// remap + warp-aggregated compaction of surviving edges + next-layer degree counts
__global__ void remap_compact(const int* __restrict__ srcC, const int* __restrict__ dstC,
                              const float* __restrict__ weC, const int* __restrict__ inv,
                              const int* __restrict__ pcnt,
                              int* __restrict__ srcN, int* __restrict__ dstN,
                              float* __restrict__ weN, int* __restrict__ pcntN,
                              float* __restrict__ degN, int* __restrict__ indegN)
{
    int e = blockIdx.x * blockDim.x + threadIdx.x;
    int cnt = *pcnt;
    bool alive = false;
    int is = 0, id = 0; float w = 0.f;
    if (e < cnt) {
        w = weC[e];
        if (w > 0.f) {
            is = inv[srcC[e]];
            id = inv[dstC[e]];
            alive = (is >= 0) && (id >= 0);
        }
    }
    unsigned m = __ballot_sync(0xffffffffu, alive);
    if (m == 0) return;
    int lane = threadIdx.x & 31;
    int leader = __ffs(m) - 1;
    int base = 0;
    if (lane == leader) base = atomicAdd(pcntN, __popc(m));
    base = __shfl_sync(0xffffffffu, base, leader);
    if (alive) {
        int pos = base + __popc(m & ((1u << lane) - 1));
        srcN[pos] = is;
        dstN[pos] = id;
        weN[pos] = w;
        atomicAdd(&degN[id], w);
        atomicAdd(&indegN[id], 1);
    }
}

__global__ __launch_bounds__(512)
void mlp_kernel(const float* __restrict__ flats, const float* __restrict__ d1w,
                const float* __restrict__ d1b, const float* __restrict__ d2w,
                const float* __restrict__ d2b, float* __restrict__ out)
{
    __shared__ float f[256];
    __shared__ float hd[512];
    int b = blockIdx.x, t = threadIdx.x;
    if (t < 256) f[t] = flats[b * 256 + t];
    __syncthreads();
    float acc = d1b[t];
#pragma unroll 8
    for (int i = 0; i < 256; i++) acc = fmaf(f[i], d1w[i * 512 + t], acc);
    hd[t] = fmaxf(acc, 0.f);
    __syncthreads();
    if (t < CC) {
        float o = d2b[t];
#pragma unroll 8
        for (int i = 0; i < 512; i++) o = fmaf(hd[i], d2w[i * CC + t], o);
        out[b * CC + t] = o;
    }
}

// ---------------- host launcher ----------------
extern "C" void kernel_launch(void* const* d_in, const int* in_sizes, int n_in,
                              void* d_out, int out_size)
{
    const float* x       = (const float*)d_in[0];
    const int*   ei      = (const int*)d_in[1];
    const float* ew      = (const float*)d_in[3];
    const float* conv1_w = (const float*)d_in[4];
    const float* conv_w  = (const float*)d_in[5];
    const float* conv_b  = (const float*)d_in[6];
    const float* bn_g    = (const float*)d_in[7];
    const float* bn_be   = (const float*)d_in[8];
    const float* bn_m    = (const float*)d_in[9];
    const float* bn_v    = (const float*)d_in[10];
    const float* pool_w  = (const float*)d_in[11];
    const float* d1w     = (const float*)d_in[12];
    const float* d1b     = (const float*)d_in[13];
    const float* d2w     = (const float*)d_in[14];
    const float* d2b     = (const float*)d_in[15];
    int E = in_sizes[3];

    float *xw, *hc, *score, *ecoef, *flats;
    float *deg[2], *weE[2];
    int *rowptr, *esrc, *flags, *nE;
    int *indeg[2], *cursor[2], *inv[2], *srcE[2], *dstE[2];
    bf16 *xhi, *xlo, *hhi, *hlo, *whi, *wlo;
    cudaGetSymbolAddress((void**)&xw,     g_xw);
    cudaGetSymbolAddress((void**)&hc,     g_hc);
    cudaGetSymbolAddress((void**)&score,  g_score);
    cudaGetSymbolAddress((void**)&rowptr, g_rowptr);
    cudaGetSymbolAddress((void**)&esrc,   g_esrc);
    cudaGetSymbolAddress((void**)&ecoef,  g_ecoef);
    cudaGetSymbolAddress((void**)&flats,  g_flats);
    cudaGetSymbolAddress((void**)&flags,  g_flags);
    cudaGetSymbolAddress((void**)&nE,     g_nE);
    cudaGetSymbolAddress((void**)&xhi,    g_xhi);
    cudaGetSymbolAddress((void**)&xlo,    g_xlo);
    cudaGetSymbolAddress((void**)&hhi,    g_hhi);
    cudaGetSymbolAddress((void**)&hlo,    g_hlo);
    cudaGetSymbolAddress((void**)&whi,    g_whi);
    cudaGetSymbolAddress((void**)&wlo,    g_wlo);
    {
        float* p; int* q;
        cudaGetSymbolAddress((void**)&p, g_deg);    deg[0] = p;  deg[1] = p + NMAX;
        cudaGetSymbolAddress((void**)&q, g_indeg);  indeg[0]  = q; indeg[1]  = q + NMAX;
        cudaGetSymbolAddress((void**)&q, g_cursor); cursor[0] = q; cursor[1] = q + NMAX;
        cudaGetSymbolAddress((void**)&q, g_inv);    inv[0]    = q; inv[1]    = q + NMAX;
        cudaGetSymbolAddress((void**)&q, g_srcE);   srcE[0]   = q; srcE[1]   = q + EMAX;
        cudaGetSymbolAddress((void**)&q, g_dstE);   dstE[0]   = q; dstE[1]   = q + EMAX;
        cudaGetSymbolAddress((void**)&p, g_weE);    weE[0]    = p; weE[1]    = p + EMAX;
    }

    const int ns[6] = {1000, 800, 640, 512, 410, 328};
    const int ks[6] = {800, 640, 512, 410, 328, 263};
    const double ubf[6] = {1.0, 0.75, 0.56, 0.42, 0.31, 0.24};
    int eb = (E + 255) / 256;
    const int SMEM_G64  = 4 * 128 * 64 * 2;    // 65536
    const int SMEM_G128 = 4 * 128 * 128 * 2;   // 131072

    cudaFuncSetAttribute(gemm_bf16<64>,  cudaFuncAttributeMaxDynamicSharedMemorySize, SMEM_G64);
    cudaFuncSetAttribute(gemm_bf16<128>, cudaFuncAttributeMaxDynamicSharedMemorySize, SMEM_G128);

    // side stream for the GEMM branch (fork-join via events; leak is bounded:
    // kernel_launch runs only for correctness + capture, not per replay)
    cudaStream_t s1;
    cudaStreamCreateWithFlags(&s1, cudaStreamNonBlocking);
    cudaStream_t s0 = (cudaStream_t)0;

    #define FORK_S1() do { cudaEvent_t e_; cudaEventCreateWithFlags(&e_, cudaEventDisableTiming); \
        cudaEventRecord(e_, s0); cudaStreamWaitEvent(s1, e_, 0); } while (0)
    #define JOIN_S0() do { cudaEvent_t e_; cudaEventCreateWithFlags(&e_, cudaEventDisableTiming); \
        cudaEventRecord(e_, s1); cudaStreamWaitEvent(s0, e_, 0); } while (0)

    // ---- prologue fork: edge chain on s0, prep+gemm0 on s1 ----
    FORK_S1();
    w_prep<<<(6 * 16384 + 255) / 256, 256, 0, s1>>>(conv1_w, conv_w, whi, wlo);
    x_prep<<<(NMAX * 64 + 255) / 256, 256, 0, s1>>>(x, xhi, xlo, NMAX * 64);
    gemm_bf16<64><<<BB * ns[0] / 128, 256, SMEM_G64, s1>>>(xhi, xlo, whi, wlo, xw);

    init_kernel<<<eb, 256, 0, s0>>>(ei, ew, srcE[0], dstE[0], weE[0], flats, flags,
                                    deg[0], indeg[0], cursor[0], inv[0], nE, E, BB * ns[0]);
    count0_kernel<<<eb, 256, 0, s0>>>(dstE[0], weE[0], deg[0], indeg[0], E);

    for (int i = 0; i < 6; i++) {
        int n = ns[i], k = ks[i], N = BB * n;
        int cur = i & 1, nxt = cur ^ 1;
        int Nnext = (i < 5) ? BB * k : 0;
        int nch = (N + 1023) >> 10;
        int ubi = (int)((double)E * ubf[i]) + 256;
        int scB = (ubi + 255) / 256;

        if (i > 0) {
            // fork recorded after topk(i-1): gemm(i) on s1 || edge chain on s0
            FORK_S1();
            gemm_bf16<128><<<N / 128, 256, SMEM_G128, s1>>>(hhi, hlo,
                whi + (size_t)i * 16384, wlo + (size_t)i * 16384, xw);

            int ubiP = (int)((double)E * ubf[i - 1]) + 256;
            int scBP = (ubiP + 255) / 256;
            remap_compact<<<scBP, 256, 0, s0>>>(srcE[nxt], dstE[nxt], weE[nxt], inv[nxt], nE + i - 1,
                                                srcE[cur], dstE[cur], weE[cur], nE + i,
                                                deg[cur], indeg[cur]);
        }

        scan_fused<<<nch, 1024, 0, s0>>>(indeg[cur], deg[cur], rowptr, flags + i * 64,
                                         deg[nxt], indeg[nxt], cursor[nxt], inv[nxt], N, Nnext);

        edge_scatter<<<scB, 256, 0, s0>>>(srcE[cur], dstE[cur], weE[cur], deg[cur],
                                          rowptr, cursor[cur], esrc, ecoef, nE + i);

        JOIN_S0();   // wait for gemm(i)

        gcn_gather<<<N / 8, 256, 0, s0>>>(xw, rowptr, esrc, ecoef, deg[cur],
                                          conv_b + i * 128, bn_g + i * 128, bn_be + i * 128,
                                          bn_m + i * 128, bn_v + i * 128, pool_w + i * 128,
                                          hc, score, N);

        topk_pool<<<BB, 1024, 0, s0>>>(score, hc, hhi, hlo, flats, inv[cur], n, k);
    }

    mlp_kernel<<<BB, 512, 0, s0>>>(flats, d1w, d1b, d2w, d2b, (float*)d_out);

    #undef FORK_S1
    #undef JOIN_S0
}

// round 8
// speedup vs baseline: 1.7969x; 1.2022x over previous
#include <cuda_runtime.h>
#include <cuda_bf16.h>
#include <math.h>

#define BB 64
#define HD 128
#define CC 10
#define SEG 16000               // edge slots per graph
#define NMAX (BB*1000)          // 64000
#define EMAX (BB*SEG)           // 1024000

typedef unsigned long long ull;
typedef __nv_bfloat16 bf16;

// ---------------- scratch (device globals; no allocation) ----------------
__device__ float g_xw[NMAX*HD];
__device__ float g_hc[NMAX*HD];
__device__ __align__(16) bf16 g_hhi[NMAX*HD];
__device__ __align__(16) bf16 g_hlo[NMAX*HD];
__device__ __align__(16) bf16 g_xhi[NMAX*64];
__device__ __align__(16) bf16 g_xlo[NMAX*64];
__device__ __align__(16) bf16 g_whi[6*128*128];   // per layer: [n][k] K-major
__device__ __align__(16) bf16 g_wlo[6*128*128];
__device__ float g_dinv[NMAX];
__device__ int   g_inv[NMAX];           // per-graph local old->new map
__device__ float g_score[NMAX];
__device__ int   g_srcE[2][EMAX];       // graph-local ids, segmented by graph
__device__ int   g_dstE[2][EMAX];
__device__ float g_weE[2][EMAX];
__device__ int   g_rowptr[NMAX];        // absolute CSR start per node
__device__ int   g_rowend[NMAX];        // absolute CSR end per node
__device__ int   g_esrc[EMAX];          // global src ids
__device__ float g_ecoef[EMAX];
__device__ float g_flats[BB*2*HD];
__device__ int   g_gcnt[BB];            // per-graph live edge count

// ---------------- helpers ----------------
__device__ __forceinline__ unsigned smem_u32(const void* p) {
    return (unsigned)__cvta_generic_to_shared(p);
}
#define CPA16(dst, src) asm volatile("cp.async.ca.shared.global [%0], [%1], 16;" :: "r"(dst), "l"(src))

#define LDSM4(r, addr) \
    asm volatile("ldmatrix.sync.aligned.m8n8.x4.shared.b16 {%0,%1,%2,%3}, [%4];" \
        : "=r"((r)[0]), "=r"((r)[1]), "=r"((r)[2]), "=r"((r)[3]) : "r"(addr))

#define MMA16816(c, a, b0, b1) \
    asm volatile("mma.sync.aligned.m16n8k16.row.col.f32.bf16.bf16.f32 " \
        "{%0,%1,%2,%3},{%4,%5,%6,%7},{%8,%9},{%0,%1,%2,%3};" \
        : "+f"((c)[0]), "+f"((c)[1]), "+f"((c)[2]), "+f"((c)[3]) \
        : "r"((a)[0]), "r"((a)[1]), "r"((a)[2]), "r"((a)[3]), "r"(b0), "r"(b1))

__device__ __forceinline__ ull pack4bf(bf16 a0, bf16 a1, bf16 a2, bf16 a3) {
    return (ull)__bfloat16_as_ushort(a0) | ((ull)__bfloat16_as_ushort(a1) << 16)
         | ((ull)__bfloat16_as_ushort(a2) << 32) | ((ull)__bfloat16_as_ushort(a3) << 48);
}

// ---------------- prep kernels ----------------

__global__ void w_prep(const float* __restrict__ w1, const float* __restrict__ w5,
                       bf16* __restrict__ whi, bf16* __restrict__ wlo)
{
    int idx = blockIdx.x * 256 + threadIdx.x;
    if (idx >= 6 * 16384) return;
    int l = idx >> 14, r = idx & 16383;
    float v; int dst;
    if (l == 0) {
        if (r >= 128 * 64) return;
        int n = r >> 6, kk = r & 63;
        v = w1[kk * 128 + n];
        dst = n * 64 + kk;
    } else {
        int n = r >> 7, kk = r & 127;
        v = w5[(size_t)(l - 1) * 16384 + kk * 128 + n];
        dst = l * 16384 + n * 128 + kk;
    }
    bf16 hi = __float2bfloat16(v);
    whi[dst] = hi;
    wlo[dst] = __float2bfloat16(v - __bfloat162float(hi));
}

__global__ void x_prep(const float* __restrict__ x,
                       bf16* __restrict__ xhi, bf16* __restrict__ xlo, int n)
{
    int i = blockIdx.x * 256 + threadIdx.x;
    if (i >= n) return;
    float v = x[i];
    bf16 hi = __float2bfloat16(v);
    xhi[i] = hi;
    xlo[i] = __float2bfloat16(v - __bfloat162float(hi));
}

// ---------------- per-graph edge machinery: remap+compact+count+scan+CSR in ONE kernel ----
// one block of 1024 threads per graph
__global__ __launch_bounds__(1024)
void edge_build(const int* __restrict__ pS, const int* __restrict__ pD,
                const float* __restrict__ pW,
                int fixedCnt, int useInv, int subMul, int nPrev, int nCur,
                const int* __restrict__ invG,
                int* __restrict__ srcN, int* __restrict__ dstN, float* __restrict__ weN,
                int* __restrict__ esrc, float* __restrict__ ecoef,
                float* __restrict__ dinvG, int* __restrict__ rowptrG, int* __restrict__ rowendG,
                int* __restrict__ gcnt)
{
    __shared__ int   s_inv[1024];
    __shared__ int   s_indeg[1024];
    __shared__ int   s_cur[1024];
    __shared__ float s_degw[1024];
    __shared__ float s_dinv[1024];
    __shared__ int   s_wsum[32];
    __shared__ int   s_woff[32];
    __shared__ int   s_count;

    int b = blockIdx.x;
    int tid = threadIdx.x;
    int lane = tid & 31;
    int seg = b * SEG;
    int sub = b * subMul;           // layer0: subtract graph base from global ids

    s_indeg[tid] = 0;
    s_degw[tid] = 0.f;
    if (tid == 0) s_count = 0;
    if (useInv && tid < nPrev) s_inv[tid] = invG[b * nPrev + tid];
    __syncthreads();

    int cnt = useInv ? gcnt[b] : fixedCnt;

    // Phase A: remap + compact + histogram
    int iters = (cnt + 1023) >> 10;
    for (int it = 0; it < iters; it++) {
        int e = it * 1024 + tid;
        bool alive = false;
        int s = 0, d = 0; float w = 0.f;
        if (e < cnt) {
            s = pS[seg + e] - sub;
            d = pD[seg + e] - sub;
            w = pW[seg + e];
            if (useInv) {
                s = s_inv[s];
                d = s_inv[d];
                alive = (s >= 0) && (d >= 0) && (w > 0.f);
            } else {
                alive = (w > 0.f);
            }
        }
        unsigned m = __ballot_sync(0xffffffffu, alive);
        if (m) {
            int leader = __ffs(m) - 1;
            int base = 0;
            if (lane == leader) base = atomicAdd(&s_count, __popc(m));
            base = __shfl_sync(0xffffffffu, base, leader);
            if (alive) {
                int pos = base + __popc(m & ((1u << lane) - 1));
                srcN[seg + pos] = s;
                dstN[seg + pos] = d;
                weN[seg + pos] = w;
                atomicAdd(&s_indeg[d], 1);
                atomicAdd(&s_degw[d], w);
            }
        }
    }
    __syncthreads();

    // Phase B: block scan of indeg -> CSR bases; dinv; write per-node CSR bounds
    {
        int wid = tid >> 5;
        int v = s_indeg[tid];
        int incl = v;
#pragma unroll
        for (int o = 1; o < 32; o <<= 1) {
            int t = __shfl_up_sync(0xffffffffu, incl, o);
            if (lane >= o) incl += t;
        }
        if (lane == 31) s_wsum[wid] = incl;
        __syncthreads();
        if (wid == 0) {
            int sv = s_wsum[lane];
            int si = sv;
#pragma unroll
            for (int o = 1; o < 32; o <<= 1) {
                int t = __shfl_up_sync(0xffffffffu, si, o);
                if (lane >= o) si += t;
            }
            s_woff[lane] = si - sv;
        }
        __syncthreads();
        int base = s_woff[tid >> 5] + incl - v;
        s_cur[tid] = base;
        if (tid < nCur) {
            float dv = rsqrtf(1.0f + s_degw[tid]);
            s_dinv[tid] = dv;
            int gn = b * nCur + tid;
            dinvG[gn] = dv;
            rowptrG[gn] = seg + base;
            rowendG[gn] = seg + base + v;
        }
    }
    __syncthreads();

    // Phase C: scatter into CSR slots (smem cursors), compute coefficients
    int cntN = s_count;
    for (int e = tid; e < cntN; e += 1024) {
        int s = srcN[seg + e];
        int d = dstN[seg + e];
        float w = weN[seg + e];
        int pos = atomicAdd(&s_cur[d], 1);
        esrc[seg + pos] = b * nCur + s;
        ecoef[seg + pos] = s_dinv[s] * s_dinv[d] * w;
    }
    if (tid == 0) gcnt[b] = cntN;
}

// ---------------- bf16 split-GEMM via mma.sync (HMMA) ----------------
template<int K>
__global__ __launch_bounds__(256)
void gemm_bf16(const bf16* __restrict__ Ahi, const bf16* __restrict__ Alo,
               const bf16* __restrict__ Whi, const bf16* __restrict__ Wlo,
               float* __restrict__ out)
{
    extern __shared__ __align__(128) char sm[];
    const unsigned smb = smem_u32(sm);
    constexpr int CH = K / 8;
    constexpr int TILEB = 128 * K * 2;
    constexpr unsigned OFF_A = 0;
    constexpr unsigned OFF_W = 2 * TILEB;

    int tid = threadIdx.x;
    int wid = tid >> 5, lane = tid & 31;
    int rowBase = blockIdx.x * 128;

    const bf16* gsrc[4] = { Ahi + (size_t)rowBase * K, Alo + (size_t)rowBase * K, Whi, Wlo };
    const unsigned soff[4] = { OFF_A, OFF_A + TILEB, OFF_W, OFF_W + TILEB };
#pragma unroll
    for (int m = 0; m < 4; m++) {
#pragma unroll
        for (int c = tid; c < 128 * CH; c += 256) {
            int r = c / CH, cc = c % CH;
            CPA16(smb + soff[m] + (unsigned)((r * CH + (cc ^ (r & 7))) * 16),
                  gsrc[m] + (size_t)r * K + cc * 8);
        }
    }
    asm volatile("cp.async.commit_group;");
    asm volatile("cp.async.wait_group 0;");
    __syncthreads();

    int mi = wid & 3, ni = wid >> 2;
    int mbase = mi * 32, nbase = ni * 64;

    float acc[2][8][4];
#pragma unroll
    for (int t = 0; t < 2; t++)
#pragma unroll
        for (int f = 0; f < 8; f++)
#pragma unroll
            for (int j = 0; j < 4; j++) acc[t][f][j] = 0.f;

    int rowA0 = mbase + (lane & 15);
    int rowW0 = nbase + (lane & 7) + ((lane >> 4) << 3);
    int kselA = (lane >> 4) & 1;
    int kselW = (lane >> 3) & 1;

#pragma unroll
    for (int s = 0; s < K / 16; s++) {
        unsigned aHi[2][4], aLo[2][4];
#pragma unroll
        for (int t = 0; t < 2; t++) {
            int row = rowA0 + t * 16;
            unsigned addr = smb + OFF_A + (unsigned)((row * CH + ((2 * s + kselA) ^ (row & 7))) * 16);
            LDSM4(aHi[t], addr);
            LDSM4(aLo[t], addr + TILEB);
        }
#pragma unroll
        for (int u = 0; u < 4; u++) {
            int row = rowW0 + u * 16;
            unsigned addr = smb + OFF_W + (unsigned)((row * CH + ((2 * s + kselW) ^ (row & 7))) * 16);
            unsigned bHi[4], bLo[4];
            LDSM4(bHi, addr);
            LDSM4(bLo, addr + TILEB);
#pragma unroll
            for (int t = 0; t < 2; t++) {
                MMA16816(acc[t][2 * u],     aHi[t], bHi[0], bHi[1]);
                MMA16816(acc[t][2 * u + 1], aHi[t], bHi[2], bHi[3]);
                MMA16816(acc[t][2 * u],     aHi[t], bLo[0], bLo[1]);
                MMA16816(acc[t][2 * u + 1], aHi[t], bLo[2], bLo[3]);
                MMA16816(acc[t][2 * u],     aLo[t], bHi[0], bHi[1]);
                MMA16816(acc[t][2 * u + 1], aLo[t], bHi[2], bHi[3]);
            }
        }
    }

    int g = lane >> 2, tg = lane & 3;
#pragma unroll
    for (int t = 0; t < 2; t++) {
        int row0 = rowBase + mbase + t * 16 + g;
#pragma unroll
        for (int f = 0; f < 8; f++) {
            int col = nbase + f * 8 + tg * 2;
            *(float2*)(out + (size_t)row0 * 128 + col) = make_float2(acc[t][f][0], acc[t][f][1]);
            *(float2*)(out + (size_t)(row0 + 8) * 128 + col) = make_float2(acc[t][f][2], acc[t][f][3]);
        }
    }
}

// ---------------- CSR gather + BN + ReLU + score (unroll x4) ----------------
__global__ void gcn_gather(const float* __restrict__ xw, const int* __restrict__ rowptr,
                           const int* __restrict__ rowend,
                           const int* __restrict__ esrc, const float* __restrict__ ecoef,
                           const float* __restrict__ dinv,
                           const float* __restrict__ bias, const float* __restrict__ bng,
                           const float* __restrict__ bnb, const float* __restrict__ bnm,
                           const float* __restrict__ bnv, const float* __restrict__ pw,
                           float* __restrict__ hc, float* __restrict__ score, int N)
{
    int n = (blockIdx.x * blockDim.x + threadIdx.x) >> 5;
    int l = threadIdx.x & 31;
    if (n >= N) return;
    float di = dinv[n];
    float sc = di * di;
    float4 a = ((const float4*)(xw + (size_t)n * 128))[l];
    float4 ac0 = make_float4(a.x * sc, a.y * sc, a.z * sc, a.w * sc);
    float4 ac1 = make_float4(0.f, 0.f, 0.f, 0.f);
    float4 ac2 = make_float4(0.f, 0.f, 0.f, 0.f);
    float4 ac3 = make_float4(0.f, 0.f, 0.f, 0.f);
    int e0 = rowptr[n], e1 = rowend[n];
    int e = e0;
    for (; e + 4 <= e1; e += 4) {
        int s0 = esrc[e], s1 = esrc[e + 1], s2 = esrc[e + 2], s3 = esrc[e + 3];
        float c0 = ecoef[e], c1 = ecoef[e + 1], c2 = ecoef[e + 2], c3 = ecoef[e + 3];
        float4 v0 = ((const float4*)(xw + (size_t)s0 * 128))[l];
        float4 v1 = ((const float4*)(xw + (size_t)s1 * 128))[l];
        float4 v2 = ((const float4*)(xw + (size_t)s2 * 128))[l];
        float4 v3 = ((const float4*)(xw + (size_t)s3 * 128))[l];
        ac0.x = fmaf(c0, v0.x, ac0.x); ac0.y = fmaf(c0, v0.y, ac0.y);
        ac0.z = fmaf(c0, v0.z, ac0.z); ac0.w = fmaf(c0, v0.w, ac0.w);
        ac1.x = fmaf(c1, v1.x, ac1.x); ac1.y = fmaf(c1, v1.y, ac1.y);
        ac1.z = fmaf(c1, v1.z, ac1.z); ac1.w = fmaf(c1, v1.w, ac1.w);
        ac2.x = fmaf(c2, v2.x, ac2.x); ac2.y = fmaf(c2, v2.y, ac2.y);
        ac2.z = fmaf(c2, v2.z, ac2.z); ac2.w = fmaf(c2, v2.w, ac2.w);
        ac3.x = fmaf(c3, v3.x, ac3.x); ac3.y = fmaf(c3, v3.y, ac3.y);
        ac3.z = fmaf(c3, v3.z, ac3.z); ac3.w = fmaf(c3, v3.w, ac3.w);
    }
    for (; e < e1; e++) {
        int s = esrc[e];
        float c = ecoef[e];
        float4 v = ((const float4*)(xw + (size_t)s * 128))[l];
        ac0.x = fmaf(c, v.x, ac0.x); ac0.y = fmaf(c, v.y, ac0.y);
        ac0.z = fmaf(c, v.z, ac0.z); ac0.w = fmaf(c, v.w, ac0.w);
    }
    ac0.x += ac1.x + ac2.x + ac3.x;
    ac0.y += ac1.y + ac2.y + ac3.y;
    ac0.z += ac1.z + ac2.z + ac3.z;
    ac0.w += ac1.w + ac2.w + ac3.w;
    float4 bb = ((const float4*)bias)[l];
    float4 g  = ((const float4*)bng)[l];
    float4 be = ((const float4*)bnb)[l];
    float4 m  = ((const float4*)bnm)[l];
    float4 vv = ((const float4*)bnv)[l];
    float4 o;
    o.x = fmaxf((ac0.x + bb.x - m.x) * (g.x * rsqrtf(vv.x + 1e-5f)) + be.x, 0.f);
    o.y = fmaxf((ac0.y + bb.y - m.y) * (g.y * rsqrtf(vv.y + 1e-5f)) + be.y, 0.f);
    o.z = fmaxf((ac0.z + bb.z - m.z) * (g.z * rsqrtf(vv.z + 1e-5f)) + be.z, 0.f);
    o.w = fmaxf((ac0.w + bb.w - m.w) * (g.w * rsqrtf(vv.w + 1e-5f)) + be.w, 0.f);
    ((float4*)(hc + (size_t)n * 128))[l] = o;
    float4 p = ((const float4*)pw)[l];
    float dot = o.x * p.x + o.y * p.y + o.z * p.z + o.w * p.w;
    float p2  = p.x * p.x + p.y * p.y + p.z * p.z + p.w * p.w;
#pragma unroll
    for (int off = 16; off; off >>= 1) {
        dot += __shfl_xor_sync(0xffffffffu, dot, off);
        p2  += __shfl_xor_sync(0xffffffffu, p2, off);
    }
    if (l == 0) score[n] = tanhf(dot * rsqrtf(p2));
}

// fused: bitonic full sort (1024 threads) + local inv + pooled h (bf16 split) + flats
__global__ __launch_bounds__(1024)
void topk_pool(const float* __restrict__ score, const float* __restrict__ hc,
               bf16* __restrict__ hhi, bf16* __restrict__ hlo,
               float* __restrict__ flats, int* __restrict__ inv, int n, int k, int accum)
{
    __shared__ float skey[1024];
    __shared__ int   sidx[1024];
    __shared__ float4 ssum[32][32];
    __shared__ float4 smax[32][32];
    int b = blockIdx.x;
    int tid = threadIdx.x;

    skey[tid] = (tid < n) ? score[b * n + tid] : -3.402823466e38f;
    sidx[tid] = tid;
    __syncthreads();

    for (int kk = 2; kk <= 1024; kk <<= 1) {
        for (int j = kk >> 1; j > 0; j >>= 1) {
            if (tid < 512) {
                int i = ((tid & ~(j - 1)) << 1) | (tid & (j - 1));
                int ixj = i | j;
                float ka = skey[i], kb = skey[ixj];
                int ia = sidx[i], ib = sidx[ixj];
                bool up = ((i & kk) == 0);
                bool sw = up ? ((ka < kb) || (ka == kb && ia > ib))
                             : ((ka > kb) || (ka == kb && ia < ib));
                if (sw) { skey[i] = kb; skey[ixj] = ka; sidx[i] = ib; sidx[ixj] = ia; }
            }
            __syncthreads();
        }
    }

    // local inv map: reset then write selected (old_local -> new_local)
    if (tid < n) inv[b * n + tid] = -1;
    __syncthreads();
    if (tid < k) inv[b * n + sidx[tid]] = tid;

    int w = tid >> 5, l = tid & 31;
    float4 sum = make_float4(0.f, 0.f, 0.f, 0.f);
    float4 mx  = make_float4(-3.402823466e38f, -3.402823466e38f, -3.402823466e38f, -3.402823466e38f);
    for (int j = w; j < k; j += 32) {
        int p = b * n + sidx[j];
        float v = skey[j];
        float4 hv = ((const float4*)(hc + (size_t)p * 128))[l];
        hv.x *= v; hv.y *= v; hv.z *= v; hv.w *= v;
        bf16 a0 = __float2bfloat16(hv.x), a1 = __float2bfloat16(hv.y);
        bf16 a2 = __float2bfloat16(hv.z), a3 = __float2bfloat16(hv.w);
        bf16 b0 = __float2bfloat16(hv.x - __bfloat162float(a0));
        bf16 b1 = __float2bfloat16(hv.y - __bfloat162float(a1));
        bf16 b2 = __float2bfloat16(hv.z - __bfloat162float(a2));
        bf16 b3 = __float2bfloat16(hv.w - __bfloat162float(a3));
        size_t rbase = (size_t)(b * k + j) * 128 + l * 4;
        *(ull*)(hhi + rbase) = pack4bf(a0, a1, a2, a3);
        *(ull*)(hlo + rbase) = pack4bf(b0, b1, b2, b3);
        sum.x += hv.x; sum.y += hv.y; sum.z += hv.z; sum.w += hv.w;
        mx.x = fmaxf(mx.x, hv.x); mx.y = fmaxf(mx.y, hv.y);
        mx.z = fmaxf(mx.z, hv.z); mx.w = fmaxf(mx.w, hv.w);
    }
    ssum[w][l] = sum; smax[w][l] = mx;
    __syncthreads();
    if (w == 0) {
#pragma unroll
        for (int q = 1; q < 32; q++) {
            float4 s2 = ssum[q][l], m2 = smax[q][l];
            sum.x += s2.x; sum.y += s2.y; sum.z += s2.z; sum.w += s2.w;
            mx.x = fmaxf(mx.x, m2.x); mx.y = fmaxf(mx.y, m2.y);
            mx.z = fmaxf(mx.z, m2.z); mx.w = fmaxf(mx.w, m2.w);
        }
        float kin = (float)k;
        float* f1 = flats + b * 256 + l * 4;
        float* f2 = flats + b * 256 + 128 + l * 4;
        if (accum) {
            f1[0] += sum.x / kin; f1[1] += sum.y / kin; f1[2] += sum.z / kin; f1[3] += sum.w / kin;
            f2[0] += mx.x; f2[1] += mx.y; f2[2] += mx.z; f2[3] += mx.w;
        } else {
            f1[0] = sum.x / kin; f1[1] = sum.y / kin; f1[2] = sum.z / kin; f1[3] = sum.w / kin;
            f2[0] = mx.x; f2[1] = mx.y; f2[2] = mx.z; f2[3] = mx.w;
        }
    }
}

__global__ __launch_bounds__(512)
void mlp_kernel(const float* __restrict__ flats, const float* __restrict__ d1w,
                const float* __restrict__ d1b, const float* __restrict__ d2w,
                const float* __restrict__ d2b, float* __restrict__ out)
{
    __shared__ float f[256];
    __shared__ float hd[512];
    int b = blockIdx.x, t = threadIdx.x;
    if (t < 256) f[t] = flats[b * 256 + t];
    __syncthreads();
    float acc = d1b[t];
#pragma unroll 8
    for (int i = 0; i < 256; i++) acc = fmaf(f[i], d1w[i * 512 + t], acc);
    hd[t] = fmaxf(acc, 0.f);
    __syncthreads();
    if (t < CC) {
        float o = d2b[t];
#pragma unroll 8
        for (int i = 0; i < 512; i++) o = fmaf(hd[i], d2w[i * CC + t], o);
        out[b * CC + t] = o;
    }
}

// ---------------- host launcher ----------------
extern "C" void kernel_launch(void* const* d_in, const int* in_sizes, int n_in,
                              void* d_out, int out_size)
{
    const float* x       = (const float*)d_in[0];
    const int*   ei      = (const int*)d_in[1];
    const float* ew      = (const float*)d_in[3];
    const float* conv1_w = (const float*)d_in[4];
    const float* conv_w  = (const float*)d_in[5];
    const float* conv_b  = (const float*)d_in[6];
    const float* bn_g    = (const float*)d_in[7];
    const float* bn_be   = (const float*)d_in[8];
    const float* bn_m    = (const float*)d_in[9];
    const float* bn_v    = (const float*)d_in[10];
    const float* pool_w  = (const float*)d_in[11];
    const float* d1w     = (const float*)d_in[12];
    const float* d1b     = (const float*)d_in[13];
    const float* d2w     = (const float*)d_in[14];
    const float* d2b     = (const float*)d_in[15];
    int E = in_sizes[3];

    float *xw, *hc, *score, *ecoef, *flats, *dinv;
    float *weE[2];
    int *rowptr, *rowend, *esrc, *inv, *gcnt;
    int *srcE[2], *dstE[2];
    bf16 *xhi, *xlo, *hhi, *hlo, *whi, *wlo;
    cudaGetSymbolAddress((void**)&xw,     g_xw);
    cudaGetSymbolAddress((void**)&hc,     g_hc);
    cudaGetSymbolAddress((void**)&score,  g_score);
    cudaGetSymbolAddress((void**)&rowptr, g_rowptr);
    cudaGetSymbolAddress((void**)&rowend, g_rowend);
    cudaGetSymbolAddress((void**)&esrc,   g_esrc);
    cudaGetSymbolAddress((void**)&ecoef,  g_ecoef);
    cudaGetSymbolAddress((void**)&flats,  g_flats);
    cudaGetSymbolAddress((void**)&dinv,   g_dinv);
    cudaGetSymbolAddress((void**)&inv,    g_inv);
    cudaGetSymbolAddress((void**)&gcnt,   g_gcnt);
    cudaGetSymbolAddress((void**)&xhi,    g_xhi);
    cudaGetSymbolAddress((void**)&xlo,    g_xlo);
    cudaGetSymbolAddress((void**)&hhi,    g_hhi);
    cudaGetSymbolAddress((void**)&hlo,    g_hlo);
    cudaGetSymbolAddress((void**)&whi,    g_whi);
    cudaGetSymbolAddress((void**)&wlo,    g_wlo);
    {
        float* p; int* q;
        cudaGetSymbolAddress((void**)&q, g_srcE);   srcE[0] = q; srcE[1] = q + EMAX;
        cudaGetSymbolAddress((void**)&q, g_dstE);   dstE[0] = q; dstE[1] = q + EMAX;
        cudaGetSymbolAddress((void**)&p, g_weE);    weE[0]  = p; weE[1]  = p + EMAX;
    }

    const int ns[6] = {1000, 800, 640, 512, 410, 328};
    const int ks[6] = {800, 640, 512, 410, 328, 263};
    const int SMEM_G64  = 4 * 128 * 64 * 2;    // 65536
    const int SMEM_G128 = 4 * 128 * 128 * 2;   // 131072

    cudaFuncSetAttribute(gemm_bf16<64>,  cudaFuncAttributeMaxDynamicSharedMemorySize, SMEM_G64);
    cudaFuncSetAttribute(gemm_bf16<128>, cudaFuncAttributeMaxDynamicSharedMemorySize, SMEM_G128);

    cudaStream_t s1;
    cudaStreamCreateWithFlags(&s1, cudaStreamNonBlocking);
    cudaStream_t s0 = (cudaStream_t)0;

    #define FORK_S1() do { cudaEvent_t e_; cudaEventCreateWithFlags(&e_, cudaEventDisableTiming); \
        cudaEventRecord(e_, s0); cudaStreamWaitEvent(s1, e_, 0); } while (0)
    #define JOIN_S0() do { cudaEvent_t e_; cudaEventCreateWithFlags(&e_, cudaEventDisableTiming); \
        cudaEventRecord(e_, s1); cudaStreamWaitEvent(s0, e_, 0); } while (0)

    // ---- prologue: edge build (layer0) on s0 ∥ prep + gemm0 on s1 ----
    FORK_S1();
    w_prep<<<(6 * 16384 + 255) / 256, 256, 0, s1>>>(conv1_w, conv_w, whi, wlo);
    x_prep<<<(NMAX * 64 + 255) / 256, 256, 0, s1>>>(x, xhi, xlo, NMAX * 64);
    gemm_bf16<64><<<BB * ns[0] / 128, 256, SMEM_G64, s1>>>(xhi, xlo, whi, wlo, xw);

    edge_build<<<BB, 1024, 0, s0>>>(ei, ei + E, ew, SEG, 0, 1000, 0, ns[0], (const int*)0,
                                    srcE[0], dstE[0], weE[0], esrc, ecoef,
                                    dinv, rowptr, rowend, gcnt);

    for (int i = 0; i < 6; i++) {
        int n = ns[i], k = ks[i], N = BB * n;
        int cur = i & 1, nxt = cur ^ 1;

        if (i > 0) {
            FORK_S1();
            gemm_bf16<128><<<N / 128, 256, SMEM_G128, s1>>>(hhi, hlo,
                whi + (size_t)i * 16384, wlo + (size_t)i * 16384, xw);

            // remap+compact+count+scan+CSR for layer i, reading layer i-1 edges
            edge_build<<<BB, 1024, 0, s0>>>(srcE[nxt], dstE[nxt], weE[nxt], 0, 1, 0,
                                            ns[i - 1], n, inv,
                                            srcE[cur], dstE[cur], weE[cur], esrc, ecoef,
                                            dinv, rowptr, rowend, gcnt);
        }

        JOIN_S0();   // wait for gemm(i)

        gcn_gather<<<N / 8, 256, 0, s0>>>(xw, rowptr, rowend, esrc, ecoef, dinv,
                                          conv_b + i * 128, bn_g + i * 128, bn_be + i * 128,
                                          bn_m + i * 128, bn_v + i * 128, pool_w + i * 128,
                                          hc, score, N);

        topk_pool<<<BB, 1024, 0, s0>>>(score, hc, hhi, hlo, flats, inv, n, k, i > 0);
    }

    mlp_kernel<<<BB, 512, 0, s0>>>(flats, d1w, d1b, d2w, d2b, (float*)d_out);

    #undef FORK_S1
    #undef JOIN_S0
}

// round 9
// speedup vs baseline: 1.8058x; 1.0049x over previous
#include <cuda_runtime.h>
#include <cuda_bf16.h>
#include <math.h>

#define BB 64
#define HD 128
#define CC 10
#define SEG 16000               // edge slots per graph
#define NMAX (BB*1000)          // 64000
#define EMAX (BB*SEG)           // 1024000

typedef unsigned long long ull;
typedef __nv_bfloat16 bf16;

// ---------------- scratch (device globals; no allocation) ----------------
__device__ float g_xw[NMAX*HD];
__device__ float g_hc[NMAX*HD];
__device__ __align__(16) bf16 g_hhi[NMAX*HD];
__device__ __align__(16) bf16 g_hlo[NMAX*HD];
__device__ __align__(16) bf16 g_xhi[NMAX*64];
__device__ __align__(16) bf16 g_xlo[NMAX*64];
__device__ __align__(16) bf16 g_whi[6*128*128];   // per layer: [n][k] K-major
__device__ __align__(16) bf16 g_wlo[6*128*128];
__device__ float g_dinv[NMAX];
__device__ int   g_inv[NMAX];           // per-graph local old->new map
__device__ float g_score[NMAX];
__device__ int   g_srcE[2][EMAX];       // graph-local ids, segmented by graph
__device__ int   g_dstE[2][EMAX];
__device__ float g_weE[2][EMAX];
__device__ int   g_rowptr[NMAX];        // absolute CSR start per node
__device__ int   g_rowend[NMAX];        // absolute CSR end per node
__device__ int   g_esrc[EMAX];          // global src ids
__device__ float g_ecoef[EMAX];
__device__ float g_flats[BB*2*HD];
__device__ int   g_gcnt[BB];            // per-graph live edge count

// ---------------- helpers ----------------
__device__ __forceinline__ unsigned smem_u32(const void* p) {
    return (unsigned)__cvta_generic_to_shared(p);
}
#define CPA16(dst, src) asm volatile("cp.async.ca.shared.global [%0], [%1], 16;" :: "r"(dst), "l"(src))

#define LDSM4(r, addr) \
    asm volatile("ldmatrix.sync.aligned.m8n8.x4.shared.b16 {%0,%1,%2,%3}, [%4];" \
        : "=r"((r)[0]), "=r"((r)[1]), "=r"((r)[2]), "=r"((r)[3]) : "r"(addr))

#define MMA16816(c, a, b0, b1) \
    asm volatile("mma.sync.aligned.m16n8k16.row.col.f32.bf16.bf16.f32 " \
        "{%0,%1,%2,%3},{%4,%5,%6,%7},{%8,%9},{%0,%1,%2,%3};" \
        : "+f"((c)[0]), "+f"((c)[1]), "+f"((c)[2]), "+f"((c)[3]) \
        : "r"((a)[0]), "r"((a)[1]), "r"((a)[2]), "r"((a)[3]), "r"(b0), "r"(b1))

__device__ __forceinline__ ull pack4bf(bf16 a0, bf16 a1, bf16 a2, bf16 a3) {
    return (ull)__bfloat16_as_ushort(a0) | ((ull)__bfloat16_as_ushort(a1) << 16)
         | ((ull)__bfloat16_as_ushort(a2) << 32) | ((ull)__bfloat16_as_ushort(a3) << 48);
}

// ---------------- prep kernels ----------------

__global__ void w_prep(const float* __restrict__ w1, const float* __restrict__ w5,
                       bf16* __restrict__ whi, bf16* __restrict__ wlo)
{
    int idx = blockIdx.x * 256 + threadIdx.x;
    if (idx >= 6 * 16384) return;
    int l = idx >> 14, r = idx & 16383;
    float v; int dst;
    if (l == 0) {
        if (r >= 128 * 64) return;
        int n = r >> 6, kk = r & 63;
        v = w1[kk * 128 + n];
        dst = n * 64 + kk;
    } else {
        int n = r >> 7, kk = r & 127;
        v = w5[(size_t)(l - 1) * 16384 + kk * 128 + n];
        dst = l * 16384 + n * 128 + kk;
    }
    bf16 hi = __float2bfloat16(v);
    whi[dst] = hi;
    wlo[dst] = __float2bfloat16(v - __bfloat162float(hi));
}

__global__ void x_prep(const float* __restrict__ x,
                       bf16* __restrict__ xhi, bf16* __restrict__ xlo, int n)
{
    int i = blockIdx.x * 256 + threadIdx.x;
    if (i >= n) return;
    float v = x[i];
    bf16 hi = __float2bfloat16(v);
    xhi[i] = hi;
    xlo[i] = __float2bfloat16(v - __bfloat162float(hi));
}

// ---------------- per-graph edge machinery (one block per graph) ----------------
__global__ __launch_bounds__(1024)
void edge_build(const int* __restrict__ pS, const int* __restrict__ pD,
                const float* __restrict__ pW,
                int fixedCnt, int useInv, int subMul, int nPrev, int nCur,
                const int* __restrict__ invG,
                int* __restrict__ srcN, int* __restrict__ dstN, float* __restrict__ weN,
                int* __restrict__ esrc, float* __restrict__ ecoef,
                float* __restrict__ dinvG, int* __restrict__ rowptrG, int* __restrict__ rowendG,
                int* __restrict__ gcnt)
{
    __shared__ int   s_inv[1024];
    __shared__ int   s_indeg[1024];
    __shared__ int   s_cur[1024];
    __shared__ float s_degw[1024];
    __shared__ float s_dinv[1024];
    __shared__ int   s_wsum[32];
    __shared__ int   s_woff[32];
    __shared__ int   s_count;

    int b = blockIdx.x;
    int tid = threadIdx.x;
    int lane = tid & 31;
    int seg = b * SEG;
    int sub = b * subMul;           // layer0: subtract graph base from global ids

    s_indeg[tid] = 0;
    s_degw[tid] = 0.f;
    if (tid == 0) s_count = 0;
    if (useInv && tid < nPrev) s_inv[tid] = invG[b * nPrev + tid];
    __syncthreads();

    int cnt = useInv ? gcnt[b] : fixedCnt;

    // Phase A: remap + compact + histogram (2-edge ILP batches)
    int iters = (cnt + 1023) >> 10;
    for (int it = 0; it < iters; it += 2) {
        int e0 = it * 1024 + tid;
        int e1 = e0 + 1024;
        bool in0 = (e0 < cnt), in1 = (it + 1 < iters) && (e1 < cnt);
        int s0 = 0, d0 = 0, s1 = 0, d1 = 0;
        float w0 = 0.f, w1 = 0.f;
        if (in0) { s0 = pS[seg + e0] - sub; d0 = pD[seg + e0] - sub; w0 = pW[seg + e0]; }
        if (in1) { s1 = pS[seg + e1] - sub; d1 = pD[seg + e1] - sub; w1 = pW[seg + e1]; }
        bool a0, a1;
        if (useInv) {
            if (in0) { s0 = s_inv[s0]; d0 = s_inv[d0]; }
            if (in1) { s1 = s_inv[s1]; d1 = s_inv[d1]; }
            a0 = in0 && (s0 >= 0) && (d0 >= 0) && (w0 > 0.f);
            a1 = in1 && (s1 >= 0) && (d1 >= 0) && (w1 > 0.f);
        } else {
            a0 = in0 && (w0 > 0.f);
            a1 = in1 && (w1 > 0.f);
        }
#pragma unroll
        for (int r = 0; r < 2; r++) {
            bool alive = r ? a1 : a0;
            int s = r ? s1 : s0, d = r ? d1 : d0;
            float w = r ? w1 : w0;
            unsigned m = __ballot_sync(0xffffffffu, alive);
            if (m) {
                int leader = __ffs(m) - 1;
                int base = 0;
                if (lane == leader) base = atomicAdd(&s_count, __popc(m));
                base = __shfl_sync(0xffffffffu, base, leader);
                if (alive) {
                    int pos = base + __popc(m & ((1u << lane) - 1));
                    srcN[seg + pos] = s;
                    dstN[seg + pos] = d;
                    weN[seg + pos] = w;
                    atomicAdd(&s_indeg[d], 1);
                    atomicAdd(&s_degw[d], w);
                }
            }
        }
    }
    __syncthreads();

    // Phase B: block scan of indeg -> CSR bases; dinv; per-node CSR bounds
    {
        int wid = tid >> 5;
        int v = s_indeg[tid];
        int incl = v;
#pragma unroll
        for (int o = 1; o < 32; o <<= 1) {
            int t = __shfl_up_sync(0xffffffffu, incl, o);
            if (lane >= o) incl += t;
        }
        if (lane == 31) s_wsum[wid] = incl;
        __syncthreads();
        if (wid == 0) {
            int sv = s_wsum[lane];
            int si = sv;
#pragma unroll
            for (int o = 1; o < 32; o <<= 1) {
                int t = __shfl_up_sync(0xffffffffu, si, o);
                if (lane >= o) si += t;
            }
            s_woff[lane] = si - sv;
        }
        __syncthreads();
        int base = s_woff[tid >> 5] + incl - v;
        s_cur[tid] = base;
        if (tid < nCur) {
            float dv = rsqrtf(1.0f + s_degw[tid]);
            s_dinv[tid] = dv;
            int gn = b * nCur + tid;
            dinvG[gn] = dv;
            rowptrG[gn] = seg + base;
            rowendG[gn] = seg + base + v;
        }
    }
    __syncthreads();

    // Phase C: scatter into CSR slots (smem cursors), 2-edge ILP batches
    int cntN = s_count;
    for (int e = tid; e < cntN; e += 2048) {
        int e2 = e + 1024;
        bool in2 = (e2 < cntN);
        int s0 = srcN[seg + e], d0 = dstN[seg + e];
        float w0 = weN[seg + e];
        int s1 = 0, d1 = 0; float w1 = 0.f;
        if (in2) { s1 = srcN[seg + e2]; d1 = dstN[seg + e2]; w1 = weN[seg + e2]; }
        int p0 = atomicAdd(&s_cur[d0], 1);
        esrc[seg + p0] = b * nCur + s0;
        ecoef[seg + p0] = s_dinv[s0] * s_dinv[d0] * w0;
        if (in2) {
            int p1 = atomicAdd(&s_cur[d1], 1);
            esrc[seg + p1] = b * nCur + s1;
            ecoef[seg + p1] = s_dinv[s1] * s_dinv[d1] * w1;
        }
    }
    if (tid == 0) gcnt[b] = cntN;
}

// ---------------- bf16 split-GEMM via mma.sync (HMMA) ----------------
template<int K>
__global__ __launch_bounds__(256)
void gemm_bf16(const bf16* __restrict__ Ahi, const bf16* __restrict__ Alo,
               const bf16* __restrict__ Whi, const bf16* __restrict__ Wlo,
               float* __restrict__ out)
{
    extern __shared__ __align__(128) char sm[];
    const unsigned smb = smem_u32(sm);
    constexpr int CH = K / 8;
    constexpr int TILEB = 128 * K * 2;
    constexpr unsigned OFF_A = 0;
    constexpr unsigned OFF_W = 2 * TILEB;

    int tid = threadIdx.x;
    int wid = tid >> 5, lane = tid & 31;
    int rowBase = blockIdx.x * 128;

    const bf16* gsrc[4] = { Ahi + (size_t)rowBase * K, Alo + (size_t)rowBase * K, Whi, Wlo };
    const unsigned soff[4] = { OFF_A, OFF_A + TILEB, OFF_W, OFF_W + TILEB };
#pragma unroll
    for (int m = 0; m < 4; m++) {
#pragma unroll
        for (int c = tid; c < 128 * CH; c += 256) {
            int r = c / CH, cc = c % CH;
            CPA16(smb + soff[m] + (unsigned)((r * CH + (cc ^ (r & 7))) * 16),
                  gsrc[m] + (size_t)r * K + cc * 8);
        }
    }
    asm volatile("cp.async.commit_group;");
    asm volatile("cp.async.wait_group 0;");
    __syncthreads();

    int mi = wid & 3, ni = wid >> 2;
    int mbase = mi * 32, nbase = ni * 64;

    float acc[2][8][4];
#pragma unroll
    for (int t = 0; t < 2; t++)
#pragma unroll
        for (int f = 0; f < 8; f++)
#pragma unroll
            for (int j = 0; j < 4; j++) acc[t][f][j] = 0.f;

    int rowA0 = mbase + (lane & 15);
    int rowW0 = nbase + (lane & 7) + ((lane >> 4) << 3);
    int kselA = (lane >> 4) & 1;
    int kselW = (lane >> 3) & 1;

#pragma unroll
    for (int s = 0; s < K / 16; s++) {
        unsigned aHi[2][4], aLo[2][4];
#pragma unroll
        for (int t = 0; t < 2; t++) {
            int row = rowA0 + t * 16;
            unsigned addr = smb + OFF_A + (unsigned)((row * CH + ((2 * s + kselA) ^ (row & 7))) * 16);
            LDSM4(aHi[t], addr);
            LDSM4(aLo[t], addr + TILEB);
        }
#pragma unroll
        for (int u = 0; u < 4; u++) {
            int row = rowW0 + u * 16;
            unsigned addr = smb + OFF_W + (unsigned)((row * CH + ((2 * s + kselW) ^ (row & 7))) * 16);
            unsigned bHi[4], bLo[4];
            LDSM4(bHi, addr);
            LDSM4(bLo, addr + TILEB);
#pragma unroll
            for (int t = 0; t < 2; t++) {
                MMA16816(acc[t][2 * u],     aHi[t], bHi[0], bHi[1]);
                MMA16816(acc[t][2 * u + 1], aHi[t], bHi[2], bHi[3]);
                MMA16816(acc[t][2 * u],     aHi[t], bLo[0], bLo[1]);
                MMA16816(acc[t][2 * u + 1], aHi[t], bLo[2], bLo[3]);
                MMA16816(acc[t][2 * u],     aLo[t], bHi[0], bHi[1]);
                MMA16816(acc[t][2 * u + 1], aLo[t], bHi[2], bHi[3]);
            }
        }
    }

    int g = lane >> 2, tg = lane & 3;
#pragma unroll
    for (int t = 0; t < 2; t++) {
        int row0 = rowBase + mbase + t * 16 + g;
#pragma unroll
        for (int f = 0; f < 8; f++) {
            int col = nbase + f * 8 + tg * 2;
            *(float2*)(out + (size_t)row0 * 128 + col) = make_float2(acc[t][f][0], acc[t][f][1]);
            *(float2*)(out + (size_t)(row0 + 8) * 128 + col) = make_float2(acc[t][f][2], acc[t][f][3]);
        }
    }
}

// ---------------- CSR gather + BN + ReLU + score: 2 blocks per graph for L1 locality ----
__global__ __launch_bounds__(1024)
void gcn_gather(const float* __restrict__ xw, const int* __restrict__ rowptr,
                const int* __restrict__ rowend,
                const int* __restrict__ esrc, const float* __restrict__ ecoef,
                const float* __restrict__ dinv,
                const float* __restrict__ bias, const float* __restrict__ bng,
                const float* __restrict__ bnb, const float* __restrict__ bnm,
                const float* __restrict__ bnv, const float* __restrict__ pw,
                float* __restrict__ hc, float* __restrict__ score, int n)
{
    int b = blockIdx.x >> 1;
    int half = blockIdx.x & 1;
    int warp = threadIdx.x >> 5;
    int l = threadIdx.x & 31;

    float4 bb = ((const float4*)bias)[l];
    float4 g  = ((const float4*)bng)[l];
    float4 be = ((const float4*)bnb)[l];
    float4 m  = ((const float4*)bnm)[l];
    float4 vv = ((const float4*)bnv)[l];
    float4 p  = ((const float4*)pw)[l];
    float4 bnscale = make_float4(g.x * rsqrtf(vv.x + 1e-5f), g.y * rsqrtf(vv.y + 1e-5f),
                                 g.z * rsqrtf(vv.z + 1e-5f), g.w * rsqrtf(vv.w + 1e-5f));

    for (int nn = half * 32 + warp; nn < n; nn += 64) {
        int node = b * n + nn;
        float di = dinv[node];
        float sc = di * di;
        float4 a = ((const float4*)(xw + (size_t)node * 128))[l];
        float4 ac0 = make_float4(a.x * sc, a.y * sc, a.z * sc, a.w * sc);
        float4 ac1 = make_float4(0.f, 0.f, 0.f, 0.f);
        float4 ac2 = make_float4(0.f, 0.f, 0.f, 0.f);
        float4 ac3 = make_float4(0.f, 0.f, 0.f, 0.f);
        int e0 = rowptr[node], e1 = rowend[node];
        int e = e0;
        for (; e + 4 <= e1; e += 4) {
            int s0 = esrc[e], s1 = esrc[e + 1], s2 = esrc[e + 2], s3 = esrc[e + 3];
            float c0 = ecoef[e], c1 = ecoef[e + 1], c2 = ecoef[e + 2], c3 = ecoef[e + 3];
            float4 v0 = ((const float4*)(xw + (size_t)s0 * 128))[l];
            float4 v1 = ((const float4*)(xw + (size_t)s1 * 128))[l];
            float4 v2 = ((const float4*)(xw + (size_t)s2 * 128))[l];
            float4 v3 = ((const float4*)(xw + (size_t)s3 * 128))[l];
            ac0.x = fmaf(c0, v0.x, ac0.x); ac0.y = fmaf(c0, v0.y, ac0.y);
            ac0.z = fmaf(c0, v0.z, ac0.z); ac0.w = fmaf(c0, v0.w, ac0.w);
            ac1.x = fmaf(c1, v1.x, ac1.x); ac1.y = fmaf(c1, v1.y, ac1.y);
            ac1.z = fmaf(c1, v1.z, ac1.z); ac1.w = fmaf(c1, v1.w, ac1.w);
            ac2.x = fmaf(c2, v2.x, ac2.x); ac2.y = fmaf(c2, v2.y, ac2.y);
            ac2.z = fmaf(c2, v2.z, ac2.z); ac2.w = fmaf(c2, v2.w, ac2.w);
            ac3.x = fmaf(c3, v3.x, ac3.x); ac3.y = fmaf(c3, v3.y, ac3.y);
            ac3.z = fmaf(c3, v3.z, ac3.z); ac3.w = fmaf(c3, v3.w, ac3.w);
        }
        for (; e < e1; e++) {
            int s = esrc[e];
            float c = ecoef[e];
            float4 v = ((const float4*)(xw + (size_t)s * 128))[l];
            ac0.x = fmaf(c, v.x, ac0.x); ac0.y = fmaf(c, v.y, ac0.y);
            ac0.z = fmaf(c, v.z, ac0.z); ac0.w = fmaf(c, v.w, ac0.w);
        }
        ac0.x += ac1.x + ac2.x + ac3.x;
        ac0.y += ac1.y + ac2.y + ac3.y;
        ac0.z += ac1.z + ac2.z + ac3.z;
        ac0.w += ac1.w + ac2.w + ac3.w;
        float4 o;
        o.x = fmaxf((ac0.x + bb.x - m.x) * bnscale.x + be.x, 0.f);
        o.y = fmaxf((ac0.y + bb.y - m.y) * bnscale.y + be.y, 0.f);
        o.z = fmaxf((ac0.z + bb.z - m.z) * bnscale.z + be.z, 0.f);
        o.w = fmaxf((ac0.w + bb.w - m.w) * bnscale.w + be.w, 0.f);
        ((float4*)(hc + (size_t)node * 128))[l] = o;
        float dot = o.x * p.x + o.y * p.y + o.z * p.z + o.w * p.w;
        float p2  = p.x * p.x + p.y * p.y + p.z * p.z + p.w * p.w;
#pragma unroll
        for (int off = 16; off; off >>= 1) {
            dot += __shfl_xor_sync(0xffffffffu, dot, off);
            p2  += __shfl_xor_sync(0xffffffffu, p2, off);
        }
        if (l == 0) score[node] = tanhf(dot * rsqrtf(p2));
    }
}

// fused: bitonic full sort (1024 threads) + local inv + pooled h (bf16 split) + flats
__global__ __launch_bounds__(1024)
void topk_pool(const float* __restrict__ score, const float* __restrict__ hc,
               bf16* __restrict__ hhi, bf16* __restrict__ hlo,
               float* __restrict__ flats, int* __restrict__ inv, int n, int k, int accum)
{
    __shared__ float skey[1024];
    __shared__ int   sidx[1024];
    __shared__ float4 ssum[32][32];
    __shared__ float4 smax[32][32];
    int b = blockIdx.x;
    int tid = threadIdx.x;

    skey[tid] = (tid < n) ? score[b * n + tid] : -3.402823466e38f;
    sidx[tid] = tid;
    __syncthreads();

    for (int kk = 2; kk <= 1024; kk <<= 1) {
        for (int j = kk >> 1; j > 0; j >>= 1) {
            if (tid < 512) {
                int i = ((tid & ~(j - 1)) << 1) | (tid & (j - 1));
                int ixj = i | j;
                float ka = skey[i], kb = skey[ixj];
                int ia = sidx[i], ib = sidx[ixj];
                bool up = ((i & kk) == 0);
                bool sw = up ? ((ka < kb) || (ka == kb && ia > ib))
                             : ((ka > kb) || (ka == kb && ia < ib));
                if (sw) { skey[i] = kb; skey[ixj] = ka; sidx[i] = ib; sidx[ixj] = ia; }
            }
            __syncthreads();
        }
    }

    if (tid < n) inv[b * n + tid] = -1;
    __syncthreads();
    if (tid < k) inv[b * n + sidx[tid]] = tid;

    int w = tid >> 5, l = tid & 31;
    float4 sum = make_float4(0.f, 0.f, 0.f, 0.f);
    float4 mx  = make_float4(-3.402823466e38f, -3.402823466e38f, -3.402823466e38f, -3.402823466e38f);
    for (int j = w; j < k; j += 32) {
        int p = b * n + sidx[j];
        float v = skey[j];
        float4 hv = ((const float4*)(hc + (size_t)p * 128))[l];
        hv.x *= v; hv.y *= v; hv.z *= v; hv.w *= v;
        bf16 a0 = __float2bfloat16(hv.x), a1 = __float2bfloat16(hv.y);
        bf16 a2 = __float2bfloat16(hv.z), a3 = __float2bfloat16(hv.w);
        bf16 b0 = __float2bfloat16(hv.x - __bfloat162float(a0));
        bf16 b1 = __float2bfloat16(hv.y - __bfloat162float(a1));
        bf16 b2 = __float2bfloat16(hv.z - __bfloat162float(a2));
        bf16 b3 = __float2bfloat16(hv.w - __bfloat162float(a3));
        size_t rbase = (size_t)(b * k + j) * 128 + l * 4;
        *(ull*)(hhi + rbase) = pack4bf(a0, a1, a2, a3);
        *(ull*)(hlo + rbase) = pack4bf(b0, b1, b2, b3);
        sum.x += hv.x; sum.y += hv.y; sum.z += hv.z; sum.w += hv.w;
        mx.x = fmaxf(mx.x, hv.x); mx.y = fmaxf(mx.y, hv.y);
        mx.z = fmaxf(mx.z, hv.z); mx.w = fmaxf(mx.w, hv.w);
    }
    ssum[w][l] = sum; smax[w][l] = mx;
    __syncthreads();
    if (w == 0) {
#pragma unroll
        for (int q = 1; q < 32; q++) {
            float4 s2 = ssum[q][l], m2 = smax[q][l];
            sum.x += s2.x; sum.y += s2.y; sum.z += s2.z; sum.w += s2.w;
            mx.x = fmaxf(mx.x, m2.x); mx.y = fmaxf(mx.y, m2.y);
            mx.z = fmaxf(mx.z, m2.z); mx.w = fmaxf(mx.w, m2.w);
        }
        float kin = (float)k;
        float* f1 = flats + b * 256 + l * 4;
        float* f2 = flats + b * 256 + 128 + l * 4;
        if (accum) {
            f1[0] += sum.x / kin; f1[1] += sum.y / kin; f1[2] += sum.z / kin; f1[3] += sum.w / kin;
            f2[0] += mx.x; f2[1] += mx.y; f2[2] += mx.z; f2[3] += mx.w;
        } else {
            f1[0] = sum.x / kin; f1[1] = sum.y / kin; f1[2] = sum.z / kin; f1[3] = sum.w / kin;
            f2[0] = mx.x; f2[1] = mx.y; f2[2] = mx.z; f2[3] = mx.w;
        }
    }
}

__global__ __launch_bounds__(512)
void mlp_kernel(const float* __restrict__ flats, const float* __restrict__ d1w,
                const float* __restrict__ d1b, const float* __restrict__ d2w,
                const float* __restrict__ d2b, float* __restrict__ out)
{
    __shared__ float f[256];
    __shared__ float hd[512];
    int b = blockIdx.x, t = threadIdx.x;
    if (t < 256) f[t] = flats[b * 256 + t];
    __syncthreads();
    float acc = d1b[t];
#pragma unroll 8
    for (int i = 0; i < 256; i++) acc = fmaf(f[i], d1w[i * 512 + t], acc);
    hd[t] = fmaxf(acc, 0.f);
    __syncthreads();
    if (t < CC) {
        float o = d2b[t];
#pragma unroll 8
        for (int i = 0; i < 512; i++) o = fmaf(hd[i], d2w[i * CC + t], o);
        out[b * CC + t] = o;
    }
}

// ---------------- host launcher ----------------
extern "C" void kernel_launch(void* const* d_in, const int* in_sizes, int n_in,
                              void* d_out, int out_size)
{
    const float* x       = (const float*)d_in[0];
    const int*   ei      = (const int*)d_in[1];
    const float* ew      = (const float*)d_in[3];
    const float* conv1_w = (const float*)d_in[4];
    const float* conv_w  = (const float*)d_in[5];
    const float* conv_b  = (const float*)d_in[6];
    const float* bn_g    = (const float*)d_in[7];
    const float* bn_be   = (const float*)d_in[8];
    const float* bn_m    = (const float*)d_in[9];
    const float* bn_v    = (const float*)d_in[10];
    const float* pool_w  = (const float*)d_in[11];
    const float* d1w     = (const float*)d_in[12];
    const float* d1b     = (const float*)d_in[13];
    const float* d2w     = (const float*)d_in[14];
    const float* d2b     = (const float*)d_in[15];
    int E = in_sizes[3];

    float *xw, *hc, *score, *ecoef, *flats, *dinv;
    float *weE[2];
    int *rowptr, *rowend, *esrc, *inv, *gcnt;
    int *srcE[2], *dstE[2];
    bf16 *xhi, *xlo, *hhi, *hlo, *whi, *wlo;
    cudaGetSymbolAddress((void**)&xw,     g_xw);
    cudaGetSymbolAddress((void**)&hc,     g_hc);
    cudaGetSymbolAddress((void**)&score,  g_score);
    cudaGetSymbolAddress((void**)&rowptr, g_rowptr);
    cudaGetSymbolAddress((void**)&rowend, g_rowend);
    cudaGetSymbolAddress((void**)&esrc,   g_esrc);
    cudaGetSymbolAddress((void**)&ecoef,  g_ecoef);
    cudaGetSymbolAddress((void**)&flats,  g_flats);
    cudaGetSymbolAddress((void**)&dinv,   g_dinv);
    cudaGetSymbolAddress((void**)&inv,    g_inv);
    cudaGetSymbolAddress((void**)&gcnt,   g_gcnt);
    cudaGetSymbolAddress((void**)&xhi,    g_xhi);
    cudaGetSymbolAddress((void**)&xlo,    g_xlo);
    cudaGetSymbolAddress((void**)&hhi,    g_hhi);
    cudaGetSymbolAddress((void**)&hlo,    g_hlo);
    cudaGetSymbolAddress((void**)&whi,    g_whi);
    cudaGetSymbolAddress((void**)&wlo,    g_wlo);
    {
        float* p; int* q;
        cudaGetSymbolAddress((void**)&q, g_srcE);   srcE[0] = q; srcE[1] = q + EMAX;
        cudaGetSymbolAddress((void**)&q, g_dstE);   dstE[0] = q; dstE[1] = q + EMAX;
        cudaGetSymbolAddress((void**)&p, g_weE);    weE[0]  = p; weE[1]  = p + EMAX;
    }

    const int ns[6] = {1000, 800, 640, 512, 410, 328};
    const int ks[6] = {800, 640, 512, 410, 328, 263};
    const int SMEM_G64  = 4 * 128 * 64 * 2;    // 65536
    const int SMEM_G128 = 4 * 128 * 128 * 2;   // 131072

    cudaFuncSetAttribute(gemm_bf16<64>,  cudaFuncAttributeMaxDynamicSharedMemorySize, SMEM_G64);
    cudaFuncSetAttribute(gemm_bf16<128>, cudaFuncAttributeMaxDynamicSharedMemorySize, SMEM_G128);

    cudaStream_t s1;
    cudaStreamCreateWithFlags(&s1, cudaStreamNonBlocking);
    cudaStream_t s0 = (cudaStream_t)0;

    #define FORK_S1() do { cudaEvent_t e_; cudaEventCreateWithFlags(&e_, cudaEventDisableTiming); \
        cudaEventRecord(e_, s0); cudaStreamWaitEvent(s1, e_, 0); } while (0)
    #define JOIN_S0() do { cudaEvent_t e_; cudaEventCreateWithFlags(&e_, cudaEventDisableTiming); \
        cudaEventRecord(e_, s1); cudaStreamWaitEvent(s0, e_, 0); } while (0)

    // ---- prologue: edge build (layer0) on s0 ∥ prep + gemm0 on s1 ----
    FORK_S1();
    w_prep<<<(6 * 16384 + 255) / 256, 256, 0, s1>>>(conv1_w, conv_w, whi, wlo);
    x_prep<<<(NMAX * 64 + 255) / 256, 256, 0, s1>>>(x, xhi, xlo, NMAX * 64);
    gemm_bf16<64><<<BB * ns[0] / 128, 256, SMEM_G64, s1>>>(xhi, xlo, whi, wlo, xw);

    edge_build<<<BB, 1024, 0, s0>>>(ei, ei + E, ew, SEG, 0, 1000, 0, ns[0], (const int*)0,
                                    srcE[0], dstE[0], weE[0], esrc, ecoef,
                                    dinv, rowptr, rowend, gcnt);

    for (int i = 0; i < 6; i++) {
        int n = ns[i], k = ks[i], N = BB * n;
        int cur = i & 1, nxt = cur ^ 1;

        if (i > 0) {
            FORK_S1();
            gemm_bf16<128><<<N / 128, 256, SMEM_G128, s1>>>(hhi, hlo,
                whi + (size_t)i * 16384, wlo + (size_t)i * 16384, xw);

            edge_build<<<BB, 1024, 0, s0>>>(srcE[nxt], dstE[nxt], weE[nxt], 0, 1, 0,
                                            ns[i - 1], n, inv,
                                            srcE[cur], dstE[cur], weE[cur], esrc, ecoef,
                                            dinv, rowptr, rowend, gcnt);
        }

        JOIN_S0();   // wait for gemm(i)

        gcn_gather<<<2 * BB, 1024, 0, s0>>>(xw, rowptr, rowend, esrc, ecoef, dinv,
                                            conv_b + i * 128, bn_g + i * 128, bn_be + i * 128,
                                            bn_m + i * 128, bn_v + i * 128, pool_w + i * 128,
                                            hc, score, n);

        topk_pool<<<BB, 1024, 0, s0>>>(score, hc, hhi, hlo, flats, inv, n, k, i > 0);
    }

    mlp_kernel<<<BB, 512, 0, s0>>>(flats, d1w, d1b, d2w, d2b, (float*)d_out);

    #undef FORK_S1
    #undef JOIN_S0
}